// round 8
// baseline (speedup 1.0000x reference)
#include <cuda_runtime.h>
#include <cstdint>

#define N_NODES 100000
#define N_EDGES 1600000
#define IN_DIM 128
#define HID_DIM 128
#define OUT_DIM 64

#define SCAN_TPB 512
#define SCAN_BLOCKS ((N_NODES + SCAN_TPB - 1) / SCAN_TPB)   // 196

// ---------------- device scratch ------------------------------------------------
__device__ int      g_deg[N_NODES];
__device__ int      g_rowptr[N_NODES + 1];
__device__ int      g_blocksum[SCAN_BLOCKS];
__device__ int      g_cursor[N_NODES];
__device__ int      g_csrc[N_EDGES];
__device__ float    g_dis[N_NODES];
__device__ float    g_h1[(size_t)N_NODES * HID_DIM];
__device__ float    g_agg1[(size_t)N_NODES * HID_DIM];
__device__ float    g_h2[(size_t)N_NODES * OUT_DIM];
__device__ uint32_t g_w1t_hi[HID_DIM * IN_DIM];   // W1^T split: [n][k]
__device__ uint32_t g_w1t_lo[HID_DIM * IN_DIM];
__device__ uint32_t g_w2t_hi[OUT_DIM * HID_DIM];  // W2^T split: [n][k]
__device__ uint32_t g_w2t_lo[OUT_DIM * HID_DIM];

// ---------------- helpers ----------------------------------------------------------
__device__ __forceinline__ uint32_t cvt_tf32(float x) {
    uint32_t r;
    asm("cvt.rna.tf32.f32 %0, %1;" : "=r"(r) : "f"(x));
    return r;
}

__device__ __forceinline__ void mma_tf32(float* d, const uint32_t* a, const uint32_t* b) {
    asm volatile(
        "mma.sync.aligned.m16n8k8.row.col.f32.tf32.tf32.f32 "
        "{%0,%1,%2,%3}, {%4,%5,%6,%7}, {%8,%9}, {%0,%1,%2,%3};"
        : "+f"(d[0]), "+f"(d[1]), "+f"(d[2]), "+f"(d[3])
        : "r"(a[0]), "r"(a[1]), "r"(a[2]), "r"(a[3]), "r"(b[0]), "r"(b[1]));
}

// ---------------- degree / norm ----------------------------------------------------
__global__ void deg_kernel(const int* __restrict__ dst, int* __restrict__ deg) {
    int i = blockIdx.x * blockDim.x + threadIdx.x;
    if (i < N_EDGES) atomicAdd(&deg[dst[i]], 1);
}
__global__ void dis_kernel(const int* __restrict__ deg, float* __restrict__ dis) {
    int i = blockIdx.x * blockDim.x + threadIdx.x;
    if (i < N_NODES) {
        float d = (float)deg[i];
        dis[i] = (d > 0.0f) ? rsqrtf(d) : 0.0f;
    }
}

// ---------------- 3-pass exclusive scan -> rowptr ----------------------------------
__global__ void scan_pass1(const int* __restrict__ deg, int* __restrict__ blocksum) {
    __shared__ int warpsum[SCAN_TPB / 32];
    int idx = blockIdx.x * SCAN_TPB + threadIdx.x;
    int v = (idx < N_NODES) ? deg[idx] : 0;
    for (int o = 16; o > 0; o >>= 1) v += __shfl_down_sync(0xffffffff, v, o);
    if ((threadIdx.x & 31) == 0) warpsum[threadIdx.x >> 5] = v;
    __syncthreads();
    if (threadIdx.x < SCAN_TPB / 32) {
        int s = warpsum[threadIdx.x];
        for (int o = 8; o > 0; o >>= 1) s += __shfl_down_sync(0xffff, s, o);
        if (threadIdx.x == 0) blocksum[blockIdx.x] = s;
    }
}
__global__ void scan_pass2(int* __restrict__ blocksum, int* __restrict__ rowptr) {
    __shared__ int ws[8];
    int lane = threadIdx.x & 31;
    int wid  = threadIdx.x >> 5;
    int v = (threadIdx.x < SCAN_BLOCKS) ? blocksum[threadIdx.x] : 0;
    int sc = v;
    for (int o = 1; o < 32; o <<= 1) {
        int t = __shfl_up_sync(0xffffffff, sc, o);
        if (lane >= o) sc += t;
    }
    if (lane == 31) ws[wid] = sc;
    __syncthreads();
    if (wid == 0 && lane < 8) {
        int s = ws[lane], ss = s;
        for (int o = 1; o < 8; o <<= 1) {
            int t = __shfl_up_sync(0xff, ss, o);
            if (lane >= o) ss += t;
        }
        ws[lane] = ss - s;
    }
    __syncthreads();
    if (threadIdx.x < SCAN_BLOCKS) blocksum[threadIdx.x] = ws[wid] + sc - v;
    if (threadIdx.x == 0) rowptr[N_NODES] = N_EDGES;
}
__global__ void scan_pass3(const int* __restrict__ deg, const int* __restrict__ blocksum,
                           int* __restrict__ rowptr) {
    __shared__ int warpsum[SCAN_TPB / 32];
    int idx = blockIdx.x * SCAN_TPB + threadIdx.x;
    int lane = threadIdx.x & 31;
    int wid  = threadIdx.x >> 5;
    int v = (idx < N_NODES) ? deg[idx] : 0;
    int sc = v;
    for (int o = 1; o < 32; o <<= 1) {
        int t = __shfl_up_sync(0xffffffff, sc, o);
        if (lane >= o) sc += t;
    }
    if (lane == 31) warpsum[wid] = sc;
    __syncthreads();
    if (wid == 0 && lane < SCAN_TPB / 32) {
        int s = warpsum[lane];
        int ss = s;
        for (int o = 1; o < SCAN_TPB / 32; o <<= 1) {
            int t = __shfl_up_sync(0xffff, ss, o);
            if (lane >= o) ss += t;
        }
        warpsum[lane] = ss - s;
    }
    __syncthreads();
    if (idx < N_NODES)
        rowptr[idx] = blocksum[blockIdx.x] + warpsum[wid] + (sc - v);
}

// ---------------- CSR fill ----------------------------------------------------------
__global__ void fill_kernel(const int* __restrict__ src, const int* __restrict__ dst,
                            const int* __restrict__ rowptr, int* __restrict__ cursor,
                            int* __restrict__ csrc) {
    int e = blockIdx.x * blockDim.x + threadIdx.x;
    if (e < N_EDGES) {
        int d = dst[e];
        int pos = rowptr[d] + atomicAdd(&cursor[d], 1);
        csrc[pos] = src[e];
    }
}

// ---------------- W transpose + tf32 split ------------------------------------------
template<int N>
__global__ void splitW_kernel(const float* __restrict__ W,
                              uint32_t* __restrict__ WT_hi, uint32_t* __restrict__ WT_lo) {
    int idx = blockIdx.x * blockDim.x + threadIdx.x;
    if (idx < 128 * N) {
        int k = idx / N, n = idx % N;
        float w = W[idx];
        uint32_t hi = cvt_tf32(w);
        float lo = w - __uint_as_float(hi);
        WT_hi[n * 128 + k] = hi;
        WT_lo[n * 128 + k] = cvt_tf32(lo);
    }
}

// ---------------- tf32 mma.sync GEMM: C[M,N] = A[M,128] @ W[128,N] -------------------
// 256 threads = 8 warps in 2 (row-groups of 64) x 4 (col-groups of N/4).
// K tiled in 2 chunks of 64. 3-term split: Ah*Bh + Ah*Bl + Al*Bh (fp32 accumulate).
template<int N>
__global__ void __launch_bounds__(256) gemm_mma_kernel(const float* __restrict__ A,
                                                       const uint32_t* __restrict__ BTh,
                                                       const uint32_t* __restrict__ BTl,
                                                       float* __restrict__ C, int M) {
    constexpr int BK  = 64;
    constexpr int STR = BK + 4;     // padded row stride (floats)
    constexpr int NW  = N / 4;      // cols per warp
    constexpr int NF  = NW / 8;     // n-frags per warp (4 or 2)

    extern __shared__ char smem[];
    float*    As  = (float*)smem;                               // [128][STR]
    uint32_t* Bhs = (uint32_t*)(smem + 128 * STR * 4);          // [N][STR]
    uint32_t* Bls = Bhs + N * STR;                              // [N][STR]

    const int tid  = threadIdx.x;
    const int w    = tid >> 5;
    const int lane = tid & 31;
    const int g    = lane >> 2;     // groupID (0..7)
    const int t    = lane & 3;      // threadID in group
    const int wr   = w >> 2;        // row group (0..1): rows wr*64..wr*64+63
    const int wc   = w & 3;         // col group (0..3): cols wc*NW..
    const int m0   = blockIdx.x * 128;

    float acc[4][NF][4];
#pragma unroll
    for (int mf = 0; mf < 4; mf++)
#pragma unroll
        for (int nf = 0; nf < NF; nf++)
#pragma unroll
            for (int j = 0; j < 4; j++) acc[mf][nf][j] = 0.0f;

#pragma unroll 1
    for (int chunk = 0; chunk < 2; chunk++) {
        const int kt = chunk * BK;
        // ---- stage A chunk: 128 rows x 64 cols, coalesced float4
#pragma unroll
        for (int i = 0; i < 8; i++) {
            int idx = tid + i * 256;        // 0..2047
            int r   = idx >> 4;             // 0..127
            int c   = idx & 15;             // float4 index (0..15)
            int gm  = m0 + r;
            float4 v = make_float4(0.f, 0.f, 0.f, 0.f);
            if (gm < M) v = *(const float4*)(A + (size_t)gm * 128 + kt + c * 4);
            *(float4*)(As + r * STR + c * 4) = v;
        }
        // ---- stage B chunk: N rows x 64 cols, hi and lo
#pragma unroll
        for (int i = 0; i < N / 16; i++) {
            int idx = tid + i * 256;
            int r   = idx >> 4;
            int c   = idx & 15;
            *(uint4*)(Bhs + r * STR + c * 4) = *(const uint4*)(BTh + (size_t)r * 128 + kt + c * 4);
            *(uint4*)(Bls + r * STR + c * 4) = *(const uint4*)(BTl + (size_t)r * 128 + kt + c * 4);
        }
        __syncthreads();

        // ---- compute: 8 k-steps of k8
#pragma unroll 1
        for (int ks = 0; ks < 8; ks++) {
            const int kc = ks * 8;
            uint32_t ah[4][4], al[4][4];
#pragma unroll
            for (int mf = 0; mf < 4; mf++) {
                const int r = wr * 64 + mf * 16;
                float a0 = As[(r + g)     * STR + kc + t];
                float a1 = As[(r + g + 8) * STR + kc + t];
                float a2 = As[(r + g)     * STR + kc + t + 4];
                float a3 = As[(r + g + 8) * STR + kc + t + 4];
                ah[mf][0] = cvt_tf32(a0); al[mf][0] = cvt_tf32(a0 - __uint_as_float(ah[mf][0]));
                ah[mf][1] = cvt_tf32(a1); al[mf][1] = cvt_tf32(a1 - __uint_as_float(ah[mf][1]));
                ah[mf][2] = cvt_tf32(a2); al[mf][2] = cvt_tf32(a2 - __uint_as_float(ah[mf][2]));
                ah[mf][3] = cvt_tf32(a3); al[mf][3] = cvt_tf32(a3 - __uint_as_float(ah[mf][3]));
            }
#pragma unroll
            for (int nf = 0; nf < NF; nf++) {
                const int nrow = wc * NW + nf * 8 + g;
                uint32_t bh[2], bl[2];
                bh[0] = Bhs[nrow * STR + kc + t];
                bh[1] = Bhs[nrow * STR + kc + t + 4];
                bl[0] = Bls[nrow * STR + kc + t];
                bl[1] = Bls[nrow * STR + kc + t + 4];
#pragma unroll
                for (int mf = 0; mf < 4; mf++) {
                    mma_tf32(acc[mf][nf], ah[mf], bh);
                    mma_tf32(acc[mf][nf], ah[mf], bl);
                    mma_tf32(acc[mf][nf], al[mf], bh);
                }
            }
        }
        __syncthreads();
    }

    // ---- epilogue: c0,c1 -> (row, 2t), (row, 2t+1); c2,c3 -> row+8
#pragma unroll
    for (int mf = 0; mf < 4; mf++) {
        const int gr = m0 + wr * 64 + mf * 16 + g;
#pragma unroll
        for (int nf = 0; nf < NF; nf++) {
            int cc = wc * NW + nf * 8 + 2 * t;
            if (gr < M)
                *(float2*)(C + (size_t)gr * N + cc) = make_float2(acc[mf][nf][0], acc[mf][nf][1]);
            if (gr + 8 < M)
                *(float2*)(C + (size_t)(gr + 8) * N + cc) = make_float2(acc[mf][nf][2], acc[mf][nf][3]);
        }
    }
}

// ---------------- CSR gather: one warp per node --------------------------------------
template<bool RELU>
__global__ void gather128_kernel(const int* __restrict__ rowptr,
                                 const int* __restrict__ csrc,
                                 const float* __restrict__ dis,
                                 const float* __restrict__ h,
                                 const float* __restrict__ bias,
                                 float* __restrict__ out) {
    const int lane = threadIdx.x & 31;
    const int node = blockIdx.x * (blockDim.x >> 5) + (threadIdx.x >> 5);
    if (node >= N_NODES) return;

    const int start = rowptr[node];
    const int end   = rowptr[node + 1];
    float4 acc = make_float4(0.f, 0.f, 0.f, 0.f);

    int j = start;
    for (; j + 2 <= end; j += 2) {
        int s0 = csrc[j], s1 = csrc[j + 1];
        float w0 = dis[s0], w1 = dis[s1];
        float4 v0 = ((const float4*)(h + (size_t)s0 * 128))[lane];
        float4 v1 = ((const float4*)(h + (size_t)s1 * 128))[lane];
        acc.x += w0 * v0.x + w1 * v1.x;
        acc.y += w0 * v0.y + w1 * v1.y;
        acc.z += w0 * v0.z + w1 * v1.z;
        acc.w += w0 * v0.w + w1 * v1.w;
    }
    if (j < end) {
        int s0 = csrc[j];
        float w0 = dis[s0];
        float4 v0 = ((const float4*)(h + (size_t)s0 * 128))[lane];
        acc.x += w0 * v0.x; acc.y += w0 * v0.y; acc.z += w0 * v0.z; acc.w += w0 * v0.w;
    }

    float dn = dis[node];
    float4 bv = ((const float4*)bias)[lane];
    float4 r;
    r.x = dn * acc.x + bv.x;
    r.y = dn * acc.y + bv.y;
    r.z = dn * acc.z + bv.z;
    r.w = dn * acc.w + bv.w;
    if (RELU) {
        r.x = fmaxf(r.x, 0.f); r.y = fmaxf(r.y, 0.f);
        r.z = fmaxf(r.z, 0.f); r.w = fmaxf(r.w, 0.f);
    }
    ((float4*)(out + (size_t)node * 128))[lane] = r;
}

__global__ void gather64_kernel(const int* __restrict__ rowptr,
                                const int* __restrict__ csrc,
                                const float* __restrict__ dis,
                                const float* __restrict__ h,
                                const float* __restrict__ bias,
                                float* __restrict__ out) {
    const int lane = threadIdx.x & 31;
    const int node = blockIdx.x * (blockDim.x >> 5) + (threadIdx.x >> 5);
    if (node >= N_NODES) return;

    const int start = rowptr[node];
    const int end   = rowptr[node + 1];
    float2 acc = make_float2(0.f, 0.f);

    int j = start;
    for (; j + 2 <= end; j += 2) {
        int s0 = csrc[j], s1 = csrc[j + 1];
        float w0 = dis[s0], w1 = dis[s1];
        float2 v0 = ((const float2*)(h + (size_t)s0 * 64))[lane];
        float2 v1 = ((const float2*)(h + (size_t)s1 * 64))[lane];
        acc.x += w0 * v0.x + w1 * v1.x;
        acc.y += w0 * v0.y + w1 * v1.y;
    }
    if (j < end) {
        int s0 = csrc[j];
        float w0 = dis[s0];
        float2 v0 = ((const float2*)(h + (size_t)s0 * 64))[lane];
        acc.x += w0 * v0.x; acc.y += w0 * v0.y;
    }

    float dn = dis[node];
    float2 bv = ((const float2*)bias)[lane];
    float2 r;
    r.x = dn * acc.x + bv.x;
    r.y = dn * acc.y + bv.y;
    ((float2*)(out + (size_t)node * 64))[lane] = r;
}

// ---------------- launch ----------------------------------------------------------
extern "C" void kernel_launch(void* const* d_in, const int* in_sizes, int n_in,
                              void* d_out, int out_size) {
    const float* x   = (const float*)d_in[0];
    const int*   ei  = (const int*)d_in[1];   // [2, E] int32
    const float* W1  = (const float*)d_in[2];
    const float* b1  = (const float*)d_in[3];
    const float* W2  = (const float*)d_in[4];
    const float* b2  = (const float*)d_in[5];
    float*       out = (float*)d_out;

    const int* src = ei;
    const int* dst = ei + N_EDGES;

    int*      deg;      cudaGetSymbolAddress((void**)&deg,      g_deg);
    int*      rowptr;   cudaGetSymbolAddress((void**)&rowptr,   g_rowptr);
    int*      blocksum; cudaGetSymbolAddress((void**)&blocksum, g_blocksum);
    int*      cursor;   cudaGetSymbolAddress((void**)&cursor,   g_cursor);
    int*      csrc;     cudaGetSymbolAddress((void**)&csrc,     g_csrc);
    float*    dis;      cudaGetSymbolAddress((void**)&dis,      g_dis);
    float*    h1;       cudaGetSymbolAddress((void**)&h1,       g_h1);
    float*    agg1;     cudaGetSymbolAddress((void**)&agg1,     g_agg1);
    float*    h2;       cudaGetSymbolAddress((void**)&h2,       g_h2);
    uint32_t* w1h;      cudaGetSymbolAddress((void**)&w1h,      g_w1t_hi);
    uint32_t* w1l;      cudaGetSymbolAddress((void**)&w1l,      g_w1t_lo);
    uint32_t* w2h;      cudaGetSymbolAddress((void**)&w2h,      g_w2t_hi);
    uint32_t* w2l;      cudaGetSymbolAddress((void**)&w2l,      g_w2t_lo);

    // dynamic smem: As[128][68] + Bh[N][68] + Bl[N][68], 4B each
    constexpr int SMEM_G1 = (128 * 68 + 2 * 128 * 68) * 4;   // 104448
    constexpr int SMEM_G2 = (128 * 68 + 2 * 64 * 68) * 4;    //  69632
    cudaFuncSetAttribute(gemm_mma_kernel<128>, cudaFuncAttributeMaxDynamicSharedMemorySize, SMEM_G1);
    cudaFuncSetAttribute(gemm_mma_kernel<64>,  cudaFuncAttributeMaxDynamicSharedMemorySize, SMEM_G2);

    // --- CSR build ---
    cudaMemsetAsync(deg, 0, N_NODES * sizeof(int));
    cudaMemsetAsync(cursor, 0, N_NODES * sizeof(int));
    deg_kernel<<<(N_EDGES + 255) / 256, 256>>>(dst, deg);
    dis_kernel<<<(N_NODES + 255) / 256, 256>>>(deg, dis);
    scan_pass1<<<SCAN_BLOCKS, SCAN_TPB>>>(deg, blocksum);
    scan_pass2<<<1, 256>>>(blocksum, rowptr);
    scan_pass3<<<SCAN_BLOCKS, SCAN_TPB>>>(deg, blocksum, rowptr);
    fill_kernel<<<(N_EDGES + 255) / 256, 256>>>(src, dst, rowptr, cursor, csrc);

    // --- weight prep: transpose + tf32 split ---
    splitW_kernel<128><<<(128 * 128 + 255) / 256, 256>>>(W1, w1h, w1l);
    splitW_kernel<64><<<(128 * 64 + 255) / 256, 256>>>(W2, w2h, w2l);

    const int gemm_grid = (N_NODES + 127) / 128;  // 782

    // --- layer 1 ---
    gemm_mma_kernel<128><<<gemm_grid, 256, SMEM_G1>>>(x, w1h, w1l, h1, N_NODES);
    gather128_kernel<true><<<(N_NODES + 7) / 8, 256>>>(rowptr, csrc, dis, h1, b1, agg1);

    // --- layer 2 ---
    gemm_mma_kernel<64><<<gemm_grid, 256, SMEM_G2>>>(agg1, w2h, w2l, h2, N_NODES);
    gather64_kernel<<<(N_NODES + 7) / 8, 256>>>(rowptr, csrc, dis, h2, b2, out);
}

// round 9
// speedup vs baseline: 1.0576x; 1.0576x over previous
#include <cuda_runtime.h>
#include <cstdint>

#define N_NODES 100000
#define N_EDGES 1600000
#define IN_DIM 128
#define HID_DIM 128
#define OUT_DIM 64

#define SCAN_TPB 512
#define SCAN_BLOCKS ((N_NODES + SCAN_TPB - 1) / SCAN_TPB)   // 196

// ---------------- device scratch ------------------------------------------------
__device__ int      g_deg[N_NODES];
__device__ int      g_rowptr[N_NODES + 1];
__device__ int      g_blocksum[SCAN_BLOCKS];
__device__ int      g_cursor[N_NODES];
__device__ int      g_csrc[N_EDGES];
__device__ float    g_dis[N_NODES];
__device__ float    g_h1[(size_t)N_NODES * HID_DIM];
__device__ float    g_agg1[(size_t)N_NODES * HID_DIM];
__device__ float    g_h2[(size_t)N_NODES * OUT_DIM];
__device__ uint32_t g_w1t_hi[HID_DIM * IN_DIM];   // W1^T split: [n][k]
__device__ uint32_t g_w1t_lo[HID_DIM * IN_DIM];
__device__ uint32_t g_w2t_hi[OUT_DIM * HID_DIM];  // W2^T split: [n][k]
__device__ uint32_t g_w2t_lo[OUT_DIM * HID_DIM];

// ---------------- helpers ----------------------------------------------------------
__device__ __forceinline__ uint32_t smem_u32(const void* p) {
    uint32_t a;
    asm("{ .reg .u64 t; cvta.to.shared.u64 t, %1; cvt.u32.u64 %0, t; }" : "=r"(a) : "l"(p));
    return a;
}
__device__ __forceinline__ uint32_t cvt_tf32(float x) {
    uint32_t r;
    asm("cvt.rna.tf32.f32 %0, %1;" : "=r"(r) : "f"(x));
    return r;
}
__device__ __forceinline__ void mma_tf32(float* d, const uint32_t* a, const uint32_t* b) {
    asm volatile(
        "mma.sync.aligned.m16n8k8.row.col.f32.tf32.tf32.f32 "
        "{%0,%1,%2,%3}, {%4,%5,%6,%7}, {%8,%9}, {%0,%1,%2,%3};"
        : "+f"(d[0]), "+f"(d[1]), "+f"(d[2]), "+f"(d[3])
        : "r"(a[0]), "r"(a[1]), "r"(a[2]), "r"(a[3]), "r"(b[0]), "r"(b[1]));
}
__device__ __forceinline__ void ldsm_x4(uint32_t& r0, uint32_t& r1, uint32_t& r2, uint32_t& r3,
                                        uint32_t addr) {
    asm volatile("ldmatrix.sync.aligned.m8n8.x4.shared.b16 {%0,%1,%2,%3}, [%4];"
                 : "=r"(r0), "=r"(r1), "=r"(r2), "=r"(r3) : "r"(addr));
}

// ---------------- zero + degree -----------------------------------------------------
__global__ void zero_kernel(int* __restrict__ deg, int* __restrict__ cursor) {
    int i = blockIdx.x * blockDim.x + threadIdx.x;
    if (i < N_NODES) { deg[i] = 0; cursor[i] = 0; }
}
__global__ void deg_kernel(const int* __restrict__ dst, int* __restrict__ deg) {
    int i = blockIdx.x * blockDim.x + threadIdx.x;
    if (i < N_EDGES) atomicAdd(&deg[dst[i]], 1);
}

// ---------------- 3-pass exclusive scan -> rowptr (+dis in pass3) -------------------
__global__ void scan_pass1(const int* __restrict__ deg, int* __restrict__ blocksum) {
    __shared__ int warpsum[SCAN_TPB / 32];
    int idx = blockIdx.x * SCAN_TPB + threadIdx.x;
    int v = (idx < N_NODES) ? deg[idx] : 0;
    for (int o = 16; o > 0; o >>= 1) v += __shfl_down_sync(0xffffffff, v, o);
    if ((threadIdx.x & 31) == 0) warpsum[threadIdx.x >> 5] = v;
    __syncthreads();
    if (threadIdx.x < SCAN_TPB / 32) {
        int s = warpsum[threadIdx.x];
        for (int o = 8; o > 0; o >>= 1) s += __shfl_down_sync(0xffff, s, o);
        if (threadIdx.x == 0) blocksum[blockIdx.x] = s;
    }
}
__global__ void scan_pass2(int* __restrict__ blocksum, int* __restrict__ rowptr) {
    __shared__ int ws[8];
    int lane = threadIdx.x & 31;
    int wid  = threadIdx.x >> 5;
    int v = (threadIdx.x < SCAN_BLOCKS) ? blocksum[threadIdx.x] : 0;
    int sc = v;
    for (int o = 1; o < 32; o <<= 1) {
        int t = __shfl_up_sync(0xffffffff, sc, o);
        if (lane >= o) sc += t;
    }
    if (lane == 31) ws[wid] = sc;
    __syncthreads();
    if (wid == 0 && lane < 8) {
        int s = ws[lane], ss = s;
        for (int o = 1; o < 8; o <<= 1) {
            int t = __shfl_up_sync(0xff, ss, o);
            if (lane >= o) ss += t;
        }
        ws[lane] = ss - s;
    }
    __syncthreads();
    if (threadIdx.x < SCAN_BLOCKS) blocksum[threadIdx.x] = ws[wid] + sc - v;
    if (threadIdx.x == 0) rowptr[N_NODES] = N_EDGES;
}
__global__ void scan_pass3(const int* __restrict__ deg, const int* __restrict__ blocksum,
                           int* __restrict__ rowptr, float* __restrict__ dis) {
    __shared__ int warpsum[SCAN_TPB / 32];
    int idx = blockIdx.x * SCAN_TPB + threadIdx.x;
    int lane = threadIdx.x & 31;
    int wid  = threadIdx.x >> 5;
    int v = (idx < N_NODES) ? deg[idx] : 0;
    int sc = v;
    for (int o = 1; o < 32; o <<= 1) {
        int t = __shfl_up_sync(0xffffffff, sc, o);
        if (lane >= o) sc += t;
    }
    if (lane == 31) warpsum[wid] = sc;
    __syncthreads();
    if (wid == 0 && lane < SCAN_TPB / 32) {
        int s = warpsum[lane];
        int ss = s;
        for (int o = 1; o < SCAN_TPB / 32; o <<= 1) {
            int t = __shfl_up_sync(0xffff, ss, o);
            if (lane >= o) ss += t;
        }
        warpsum[lane] = ss - s;
    }
    __syncthreads();
    if (idx < N_NODES) {
        rowptr[idx] = blocksum[blockIdx.x] + warpsum[wid] + (sc - v);
        float d = (float)v;
        dis[idx] = (d > 0.0f) ? rsqrtf(d) : 0.0f;
    }
}

// ---------------- CSR fill ----------------------------------------------------------
__global__ void fill_kernel(const int* __restrict__ src, const int* __restrict__ dst,
                            const int* __restrict__ rowptr, int* __restrict__ cursor,
                            int* __restrict__ csrc) {
    int e = blockIdx.x * blockDim.x + threadIdx.x;
    if (e < N_EDGES) {
        int d = dst[e];
        int pos = rowptr[d] + atomicAdd(&cursor[d], 1);
        csrc[pos] = src[e];
    }
}

// ---------------- W transpose + tf32 split ------------------------------------------
template<int N>
__global__ void splitW_kernel(const float* __restrict__ W,
                              uint32_t* __restrict__ WT_hi, uint32_t* __restrict__ WT_lo) {
    int idx = blockIdx.x * blockDim.x + threadIdx.x;
    if (idx < 128 * N) {
        int k = idx / N, n = idx % N;
        float w = W[idx];
        uint32_t hi = cvt_tf32(w);
        float lo = w - __uint_as_float(hi);
        WT_hi[n * 128 + k] = hi;
        WT_lo[n * 128 + k] = cvt_tf32(lo);
    }
}

// ---------------- tf32 mma.sync GEMM: C[M,N] = A[M,128] @ W[128,N] -------------------
// 256 threads = 8 warps, warp w owns rows [w*16, w*16+16) x full N (R7 tiling).
// Frags via ldmatrix.x4. K in 2 chunks of 64. 3-term split: AhBh + AhBl + AlBh.
template<int N>
__global__ void __launch_bounds__(256) gemm_mma_kernel(const float* __restrict__ A,
                                                       const uint32_t* __restrict__ BTh,
                                                       const uint32_t* __restrict__ BTl,
                                                       float* __restrict__ C, int M) {
    constexpr int BK  = 64;
    constexpr int STR = BK + 4;     // 68-word row stride: LDSM phases conflict-free
    constexpr int NT  = N / 8;      // n-frags per warp

    extern __shared__ char smem[];
    float*    As  = (float*)smem;                               // [128][STR]
    uint32_t* Bhs = (uint32_t*)(smem + 128 * STR * 4);          // [N][STR]
    uint32_t* Bls = Bhs + N * STR;                              // [N][STR]

    const int tid  = threadIdx.x;
    const int w    = tid >> 5;
    const int lane = tid & 31;
    const int g    = lane >> 2;     // groupID (0..7)
    const int t    = lane & 3;      // threadID in group
    const int m0   = blockIdx.x * 128;
    const int r0   = w * 16;

    // ldmatrix lane roles
    const int rowi = lane & 7;
    const int sel  = lane >> 3;     // which of the 4 matrices this lane addresses

    const uint32_t as_u32  = smem_u32(As);
    const uint32_t bhs_u32 = smem_u32(Bhs);
    const uint32_t bls_u32 = smem_u32(Bls);

    // A quad: {rows@kc, rows+8@kc, rows@kc+4, rows+8@kc+4}
    const uint32_t a_lane_base =
        as_u32 + (uint32_t)(((r0 + (sel & 1) * 8 + rowi) * STR + (sel >> 1) * 4) * 4);
    // B quad: {Bh@kc, Bh@kc+4, Bl@kc, Bl@kc+4}
    const uint32_t b_lane_base =
        ((sel < 2) ? bhs_u32 : bls_u32) + (uint32_t)((rowi * STR + (sel & 1) * 4) * 4);

    float acc[NT][4];
#pragma unroll
    for (int nt = 0; nt < NT; nt++)
#pragma unroll
        for (int j = 0; j < 4; j++) acc[nt][j] = 0.0f;

#pragma unroll 1
    for (int chunk = 0; chunk < 2; chunk++) {
        const int kt = chunk * BK;
        // ---- stage A chunk: 128 rows x 64 cols, coalesced float4
#pragma unroll
        for (int i = 0; i < 8; i++) {
            int idx = tid + i * 256;
            int r   = idx >> 4;
            int c   = idx & 15;
            int gm  = m0 + r;
            float4 v = make_float4(0.f, 0.f, 0.f, 0.f);
            if (gm < M) v = *(const float4*)(A + (size_t)gm * 128 + kt + c * 4);
            *(float4*)(As + r * STR + c * 4) = v;
        }
        // ---- stage B chunk: N rows x 64 cols, hi and lo
#pragma unroll
        for (int i = 0; i < N / 16; i++) {
            int idx = tid + i * 256;
            int r   = idx >> 4;
            int c   = idx & 15;
            *(uint4*)(Bhs + r * STR + c * 4) = *(const uint4*)(BTh + (size_t)r * 128 + kt + c * 4);
            *(uint4*)(Bls + r * STR + c * 4) = *(const uint4*)(BTl + (size_t)r * 128 + kt + c * 4);
        }
        __syncthreads();

        // ---- compute: 8 k-steps of k8
#pragma unroll 1
        for (int ks = 0; ks < 8; ks++) {
            const int kc = ks * 8;
            // A frag: one ldmatrix.x4, then split hi/lo
            uint32_t ar[4], ah[4], al[4];
            ldsm_x4(ar[0], ar[1], ar[2], ar[3], a_lane_base + kc * 4);
#pragma unroll
            for (int i = 0; i < 4; i++) {
                float af = __uint_as_float(ar[i]);
                ah[i] = cvt_tf32(af);
                al[i] = cvt_tf32(af - __uint_as_float(ah[i]));
            }
#pragma unroll
            for (int nt = 0; nt < NT; nt++) {
                uint32_t bh[2], bl[2];
                ldsm_x4(bh[0], bh[1], bl[0], bl[1],
                        b_lane_base + (uint32_t)((nt * 8 * STR + kc) * 4));
                mma_tf32(acc[nt], ah, bh);
                mma_tf32(acc[nt], ah, bl);
                mma_tf32(acc[nt], al, bh);
            }
        }
        __syncthreads();
    }

    // ---- epilogue
    const int gr0 = m0 + r0 + g;
#pragma unroll
    for (int nt = 0; nt < NT; nt++) {
        int cc = nt * 8 + 2 * t;
        if (gr0 < M)
            *(float2*)(C + (size_t)gr0 * N + cc) = make_float2(acc[nt][0], acc[nt][1]);
        if (gr0 + 8 < M)
            *(float2*)(C + (size_t)(gr0 + 8) * N + cc) = make_float2(acc[nt][2], acc[nt][3]);
    }
}

// ---------------- CSR gather: one warp per node --------------------------------------
template<bool RELU>
__global__ void gather128_kernel(const int* __restrict__ rowptr,
                                 const int* __restrict__ csrc,
                                 const float* __restrict__ dis,
                                 const float* __restrict__ h,
                                 const float* __restrict__ bias,
                                 float* __restrict__ out) {
    const int lane = threadIdx.x & 31;
    const int node = blockIdx.x * (blockDim.x >> 5) + (threadIdx.x >> 5);
    if (node >= N_NODES) return;

    const int start = rowptr[node];
    const int end   = rowptr[node + 1];
    float4 acc = make_float4(0.f, 0.f, 0.f, 0.f);

    int j = start;
    for (; j + 2 <= end; j += 2) {
        int s0 = csrc[j], s1 = csrc[j + 1];
        float w0 = dis[s0], w1 = dis[s1];
        float4 v0 = ((const float4*)(h + (size_t)s0 * 128))[lane];
        float4 v1 = ((const float4*)(h + (size_t)s1 * 128))[lane];
        acc.x += w0 * v0.x + w1 * v1.x;
        acc.y += w0 * v0.y + w1 * v1.y;
        acc.z += w0 * v0.z + w1 * v1.z;
        acc.w += w0 * v0.w + w1 * v1.w;
    }
    if (j < end) {
        int s0 = csrc[j];
        float w0 = dis[s0];
        float4 v0 = ((const float4*)(h + (size_t)s0 * 128))[lane];
        acc.x += w0 * v0.x; acc.y += w0 * v0.y; acc.z += w0 * v0.z; acc.w += w0 * v0.w;
    }

    float dn = dis[node];
    float4 bv = ((const float4*)bias)[lane];
    float4 r;
    r.x = dn * acc.x + bv.x;
    r.y = dn * acc.y + bv.y;
    r.z = dn * acc.z + bv.z;
    r.w = dn * acc.w + bv.w;
    if (RELU) {
        r.x = fmaxf(r.x, 0.f); r.y = fmaxf(r.y, 0.f);
        r.z = fmaxf(r.z, 0.f); r.w = fmaxf(r.w, 0.f);
    }
    ((float4*)(out + (size_t)node * 128))[lane] = r;
}

__global__ void gather64_kernel(const int* __restrict__ rowptr,
                                const int* __restrict__ csrc,
                                const float* __restrict__ dis,
                                const float* __restrict__ h,
                                const float* __restrict__ bias,
                                float* __restrict__ out) {
    const int lane = threadIdx.x & 31;
    const int node = blockIdx.x * (blockDim.x >> 5) + (threadIdx.x >> 5);
    if (node >= N_NODES) return;

    const int start = rowptr[node];
    const int end   = rowptr[node + 1];
    float2 acc = make_float2(0.f, 0.f);

    int j = start;
    for (; j + 2 <= end; j += 2) {
        int s0 = csrc[j], s1 = csrc[j + 1];
        float w0 = dis[s0], w1 = dis[s1];
        float2 v0 = ((const float2*)(h + (size_t)s0 * 64))[lane];
        float2 v1 = ((const float2*)(h + (size_t)s1 * 64))[lane];
        acc.x += w0 * v0.x + w1 * v1.x;
        acc.y += w0 * v0.y + w1 * v1.y;
    }
    if (j < end) {
        int s0 = csrc[j];
        float w0 = dis[s0];
        float2 v0 = ((const float2*)(h + (size_t)s0 * 64))[lane];
        acc.x += w0 * v0.x; acc.y += w0 * v0.y;
    }

    float dn = dis[node];
    float2 bv = ((const float2*)bias)[lane];
    float2 r;
    r.x = dn * acc.x + bv.x;
    r.y = dn * acc.y + bv.y;
    ((float2*)(out + (size_t)node * 64))[lane] = r;
}

// ---------------- launch ----------------------------------------------------------
extern "C" void kernel_launch(void* const* d_in, const int* in_sizes, int n_in,
                              void* d_out, int out_size) {
    const float* x   = (const float*)d_in[0];
    const int*   ei  = (const int*)d_in[1];   // [2, E] int32
    const float* W1  = (const float*)d_in[2];
    const float* b1  = (const float*)d_in[3];
    const float* W2  = (const float*)d_in[4];
    const float* b2  = (const float*)d_in[5];
    float*       out = (float*)d_out;

    const int* src = ei;
    const int* dst = ei + N_EDGES;

    int*      deg;      cudaGetSymbolAddress((void**)&deg,      g_deg);
    int*      rowptr;   cudaGetSymbolAddress((void**)&rowptr,   g_rowptr);
    int*      blocksum; cudaGetSymbolAddress((void**)&blocksum, g_blocksum);
    int*      cursor;   cudaGetSymbolAddress((void**)&cursor,   g_cursor);
    int*      csrc;     cudaGetSymbolAddress((void**)&csrc,     g_csrc);
    float*    dis;      cudaGetSymbolAddress((void**)&dis,      g_dis);
    float*    h1;       cudaGetSymbolAddress((void**)&h1,       g_h1);
    float*    agg1;     cudaGetSymbolAddress((void**)&agg1,     g_agg1);
    float*    h2;       cudaGetSymbolAddress((void**)&h2,       g_h2);
    uint32_t* w1h;      cudaGetSymbolAddress((void**)&w1h,      g_w1t_hi);
    uint32_t* w1l;      cudaGetSymbolAddress((void**)&w1l,      g_w1t_lo);
    uint32_t* w2h;      cudaGetSymbolAddress((void**)&w2h,      g_w2t_hi);
    uint32_t* w2l;      cudaGetSymbolAddress((void**)&w2l,      g_w2t_lo);

    constexpr int SMEM_G1 = (128 * 68 + 2 * 128 * 68) * 4;   // 104448
    constexpr int SMEM_G2 = (128 * 68 + 2 * 64 * 68) * 4;    //  69632
    cudaFuncSetAttribute(gemm_mma_kernel<128>, cudaFuncAttributeMaxDynamicSharedMemorySize, SMEM_G1);
    cudaFuncSetAttribute(gemm_mma_kernel<64>,  cudaFuncAttributeMaxDynamicSharedMemorySize, SMEM_G2);

    const int gemm_grid = (N_NODES + 127) / 128;  // 782

    // Launch order puts gemm1 at slot 6 so ncu (-s 5 -c 1) profiles it.
    zero_kernel<<<(N_NODES + 255) / 256, 256>>>(deg, cursor);                    // 1
    splitW_kernel<128><<<(128 * 128 + 255) / 256, 256>>>(W1, w1h, w1l);          // 2
    splitW_kernel<64><<<(128 * 64 + 255) / 256, 256>>>(W2, w2h, w2l);            // 3
    deg_kernel<<<(N_EDGES + 255) / 256, 256>>>(dst, deg);                        // 4
    scan_pass1<<<SCAN_BLOCKS, SCAN_TPB>>>(deg, blocksum);                        // 5
    gemm_mma_kernel<128><<<gemm_grid, 256, SMEM_G1>>>(x, w1h, w1l, h1, N_NODES); // 6 <- profiled
    scan_pass2<<<1, 256>>>(blocksum, rowptr);                                    // 7
    scan_pass3<<<SCAN_BLOCKS, SCAN_TPB>>>(deg, blocksum, rowptr, dis);           // 8
    fill_kernel<<<(N_EDGES + 255) / 256, 256>>>(src, dst, rowptr, cursor, csrc); // 9
    gather128_kernel<true><<<(N_NODES + 7) / 8, 256>>>(rowptr, csrc, dis, h1, b1, agg1); // 10
    gemm_mma_kernel<64><<<gemm_grid, 256, SMEM_G2>>>(agg1, w2h, w2l, h2, N_NODES);       // 11
    gather64_kernel<<<(N_NODES + 7) / 8, 256>>>(rowptr, csrc, dis, h2, b2, out);         // 12
}

// round 10
// speedup vs baseline: 1.1246x; 1.0633x over previous
#include <cuda_runtime.h>
#include <cuda_fp16.h>
#include <cstdint>

#define N_NODES 100000
#define N_EDGES 1600000
#define IN_DIM 128
#define HID_DIM 128
#define OUT_DIM 64

#define SCAN_TPB 512
#define SCAN_BLOCKS ((N_NODES + SCAN_TPB - 1) / SCAN_TPB)   // 196

// ---------------- device scratch ------------------------------------------------
__device__ int      g_deg[N_NODES];
__device__ int      g_rowptr[N_NODES + 1];
__device__ int      g_blocksum[SCAN_BLOCKS];
__device__ int      g_cursor[N_NODES];
__device__ int      g_csrc[N_EDGES];
__device__ float    g_dis[N_NODES];
__device__ __half2  g_h1h[(size_t)N_NODES * HID_DIM / 2];   // x @ W1, fp16
__device__ float    g_agg1[(size_t)N_NODES * HID_DIM];      // relu(A_hat h1 + b1), fp32
__device__ __half2  g_h2h[(size_t)N_NODES * OUT_DIM / 2];   // agg1 @ W2, fp16
__device__ uint32_t g_w1t_hi[HID_DIM * IN_DIM];   // W1^T split: [n][k]
__device__ uint32_t g_w1t_lo[HID_DIM * IN_DIM];
__device__ uint32_t g_w2t_hi[OUT_DIM * HID_DIM];  // W2^T split: [n][k]
__device__ uint32_t g_w2t_lo[OUT_DIM * HID_DIM];

// ---------------- helpers ----------------------------------------------------------
__device__ __forceinline__ uint32_t smem_u32(const void* p) {
    uint32_t a;
    asm("{ .reg .u64 t; cvta.to.shared.u64 t, %1; cvt.u32.u64 %0, t; }" : "=r"(a) : "l"(p));
    return a;
}
__device__ __forceinline__ uint32_t cvt_tf32(float x) {
    uint32_t r;
    asm("cvt.rna.tf32.f32 %0, %1;" : "=r"(r) : "f"(x));
    return r;
}
__device__ __forceinline__ void mma_tf32(float* d, const uint32_t* a, const uint32_t* b) {
    asm volatile(
        "mma.sync.aligned.m16n8k8.row.col.f32.tf32.tf32.f32 "
        "{%0,%1,%2,%3}, {%4,%5,%6,%7}, {%8,%9}, {%0,%1,%2,%3};"
        : "+f"(d[0]), "+f"(d[1]), "+f"(d[2]), "+f"(d[3])
        : "r"(a[0]), "r"(a[1]), "r"(a[2]), "r"(a[3]), "r"(b[0]), "r"(b[1]));
}
__device__ __forceinline__ void ldsm_x4(uint32_t& r0, uint32_t& r1, uint32_t& r2, uint32_t& r3,
                                        uint32_t addr) {
    asm volatile("ldmatrix.sync.aligned.m8n8.x4.shared.b16 {%0,%1,%2,%3}, [%4];"
                 : "=r"(r0), "=r"(r1), "=r"(r2), "=r"(r3) : "r"(addr));
}

// ---------------- zero + degree -----------------------------------------------------
__global__ void zero_kernel(int* __restrict__ deg, int* __restrict__ cursor) {
    int i = blockIdx.x * blockDim.x + threadIdx.x;
    if (i < N_NODES) { deg[i] = 0; cursor[i] = 0; }
}
__global__ void deg_kernel(const int* __restrict__ dst, int* __restrict__ deg) {
    int i = blockIdx.x * blockDim.x + threadIdx.x;
    if (i < N_EDGES) atomicAdd(&deg[dst[i]], 1);
}

// ---------------- 3-pass exclusive scan -> rowptr (+dis in pass3) -------------------
__global__ void scan_pass1(const int* __restrict__ deg, int* __restrict__ blocksum) {
    __shared__ int warpsum[SCAN_TPB / 32];
    int idx = blockIdx.x * SCAN_TPB + threadIdx.x;
    int v = (idx < N_NODES) ? deg[idx] : 0;
    for (int o = 16; o > 0; o >>= 1) v += __shfl_down_sync(0xffffffff, v, o);
    if ((threadIdx.x & 31) == 0) warpsum[threadIdx.x >> 5] = v;
    __syncthreads();
    if (threadIdx.x < SCAN_TPB / 32) {
        int s = warpsum[threadIdx.x];
        for (int o = 8; o > 0; o >>= 1) s += __shfl_down_sync(0xffff, s, o);
        if (threadIdx.x == 0) blocksum[blockIdx.x] = s;
    }
}
__global__ void scan_pass2(int* __restrict__ blocksum, int* __restrict__ rowptr) {
    __shared__ int ws[8];
    int lane = threadIdx.x & 31;
    int wid  = threadIdx.x >> 5;
    int v = (threadIdx.x < SCAN_BLOCKS) ? blocksum[threadIdx.x] : 0;
    int sc = v;
    for (int o = 1; o < 32; o <<= 1) {
        int t = __shfl_up_sync(0xffffffff, sc, o);
        if (lane >= o) sc += t;
    }
    if (lane == 31) ws[wid] = sc;
    __syncthreads();
    if (wid == 0 && lane < 8) {
        int s = ws[lane], ss = s;
        for (int o = 1; o < 8; o <<= 1) {
            int t = __shfl_up_sync(0xff, ss, o);
            if (lane >= o) ss += t;
        }
        ws[lane] = ss - s;
    }
    __syncthreads();
    if (threadIdx.x < SCAN_BLOCKS) blocksum[threadIdx.x] = ws[wid] + sc - v;
    if (threadIdx.x == 0) rowptr[N_NODES] = N_EDGES;
}
__global__ void scan_pass3(const int* __restrict__ deg, const int* __restrict__ blocksum,
                           int* __restrict__ rowptr, float* __restrict__ dis) {
    __shared__ int warpsum[SCAN_TPB / 32];
    int idx = blockIdx.x * SCAN_TPB + threadIdx.x;
    int lane = threadIdx.x & 31;
    int wid  = threadIdx.x >> 5;
    int v = (idx < N_NODES) ? deg[idx] : 0;
    int sc = v;
    for (int o = 1; o < 32; o <<= 1) {
        int t = __shfl_up_sync(0xffffffff, sc, o);
        if (lane >= o) sc += t;
    }
    if (lane == 31) warpsum[wid] = sc;
    __syncthreads();
    if (wid == 0 && lane < SCAN_TPB / 32) {
        int s = warpsum[lane];
        int ss = s;
        for (int o = 1; o < SCAN_TPB / 32; o <<= 1) {
            int t = __shfl_up_sync(0xffff, ss, o);
            if (lane >= o) ss += t;
        }
        warpsum[lane] = ss - s;
    }
    __syncthreads();
    if (idx < N_NODES) {
        rowptr[idx] = blocksum[blockIdx.x] + warpsum[wid] + (sc - v);
        float d = (float)v;
        dis[idx] = (d > 0.0f) ? rsqrtf(d) : 0.0f;
    }
}

// ---------------- CSR fill ----------------------------------------------------------
__global__ void fill_kernel(const int* __restrict__ src, const int* __restrict__ dst,
                            const int* __restrict__ rowptr, int* __restrict__ cursor,
                            int* __restrict__ csrc) {
    int e = blockIdx.x * blockDim.x + threadIdx.x;
    if (e < N_EDGES) {
        int d = dst[e];
        int pos = rowptr[d] + atomicAdd(&cursor[d], 1);
        csrc[pos] = src[e];
    }
}

// ---------------- W transpose + tf32 split ------------------------------------------
template<int N>
__global__ void splitW_kernel(const float* __restrict__ W,
                              uint32_t* __restrict__ WT_hi, uint32_t* __restrict__ WT_lo) {
    int idx = blockIdx.x * blockDim.x + threadIdx.x;
    if (idx < 128 * N) {
        int k = idx / N, n = idx % N;
        float w = W[idx];
        uint32_t hi = cvt_tf32(w);
        float lo = w - __uint_as_float(hi);
        WT_hi[n * 128 + k] = hi;
        WT_lo[n * 128 + k] = cvt_tf32(lo);
    }
}

// ---------------- tf32 mma.sync GEMM: Ch[M,N](fp16) = A[M,128] @ W[128,N] ------------
// 256 threads = 8 warps, warp w owns rows [w*16, w*16+16) x full N.
// Frags via ldmatrix.x4. K in 2 chunks of 64. 3-term split: AhBh + AhBl + AlBh.
template<int N>
__global__ void __launch_bounds__(256) gemm_mma_kernel(const float* __restrict__ A,
                                                       const uint32_t* __restrict__ BTh,
                                                       const uint32_t* __restrict__ BTl,
                                                       __half2* __restrict__ Ch, int M) {
    constexpr int BK  = 64;
    constexpr int STR = BK + 4;     // 68-word row stride: LDSM phases conflict-free
    constexpr int NT  = N / 8;      // n-frags per warp

    extern __shared__ char smem[];
    float*    As  = (float*)smem;                               // [128][STR]
    uint32_t* Bhs = (uint32_t*)(smem + 128 * STR * 4);          // [N][STR]
    uint32_t* Bls = Bhs + N * STR;                              // [N][STR]

    const int tid  = threadIdx.x;
    const int w    = tid >> 5;
    const int lane = tid & 31;
    const int g    = lane >> 2;     // groupID (0..7)
    const int t    = lane & 3;      // threadID in group
    const int m0   = blockIdx.x * 128;
    const int r0   = w * 16;

    const int rowi = lane & 7;
    const int sel  = lane >> 3;

    const uint32_t as_u32  = smem_u32(As);
    const uint32_t bhs_u32 = smem_u32(Bhs);
    const uint32_t bls_u32 = smem_u32(Bls);

    const uint32_t a_lane_base =
        as_u32 + (uint32_t)(((r0 + (sel & 1) * 8 + rowi) * STR + (sel >> 1) * 4) * 4);
    const uint32_t b_lane_base =
        ((sel < 2) ? bhs_u32 : bls_u32) + (uint32_t)((rowi * STR + (sel & 1) * 4) * 4);

    float acc[NT][4];
#pragma unroll
    for (int nt = 0; nt < NT; nt++)
#pragma unroll
        for (int j = 0; j < 4; j++) acc[nt][j] = 0.0f;

#pragma unroll 1
    for (int chunk = 0; chunk < 2; chunk++) {
        const int kt = chunk * BK;
#pragma unroll
        for (int i = 0; i < 8; i++) {
            int idx = tid + i * 256;
            int r   = idx >> 4;
            int c   = idx & 15;
            int gm  = m0 + r;
            float4 v = make_float4(0.f, 0.f, 0.f, 0.f);
            if (gm < M) v = *(const float4*)(A + (size_t)gm * 128 + kt + c * 4);
            *(float4*)(As + r * STR + c * 4) = v;
        }
#pragma unroll
        for (int i = 0; i < N / 16; i++) {
            int idx = tid + i * 256;
            int r   = idx >> 4;
            int c   = idx & 15;
            *(uint4*)(Bhs + r * STR + c * 4) = *(const uint4*)(BTh + (size_t)r * 128 + kt + c * 4);
            *(uint4*)(Bls + r * STR + c * 4) = *(const uint4*)(BTl + (size_t)r * 128 + kt + c * 4);
        }
        __syncthreads();

#pragma unroll 1
        for (int ks = 0; ks < 8; ks++) {
            const int kc = ks * 8;
            uint32_t ar[4], ah[4], al[4];
            ldsm_x4(ar[0], ar[1], ar[2], ar[3], a_lane_base + kc * 4);
#pragma unroll
            for (int i = 0; i < 4; i++) {
                float af = __uint_as_float(ar[i]);
                ah[i] = cvt_tf32(af);
                al[i] = cvt_tf32(af - __uint_as_float(ah[i]));
            }
#pragma unroll
            for (int nt = 0; nt < NT; nt++) {
                uint32_t bh[2], bl[2];
                ldsm_x4(bh[0], bh[1], bl[0], bl[1],
                        b_lane_base + (uint32_t)((nt * 8 * STR + kc) * 4));
                mma_tf32(acc[nt], ah, bh);
                mma_tf32(acc[nt], ah, bl);
                mma_tf32(acc[nt], al, bh);
            }
        }
        __syncthreads();
    }

    // ---- epilogue: fp16 store. cols (cc, cc+1) -> one __half2
    const int gr0 = m0 + r0 + g;
#pragma unroll
    for (int nt = 0; nt < NT; nt++) {
        int cc = nt * 8 + 2 * t;
        if (gr0 < M)
            Ch[(size_t)gr0 * (N / 2) + cc / 2] = __floats2half2_rn(acc[nt][0], acc[nt][1]);
        if (gr0 + 8 < M)
            Ch[(size_t)(gr0 + 8) * (N / 2) + cc / 2] = __floats2half2_rn(acc[nt][2], acc[nt][3]);
    }
}

// ---------------- CSR gather (fp16 input): one warp per node -------------------------
// F=128: lane owns 4 cols (2 half2 = one uint2 load, 8B).
template<bool RELU>
__global__ void gather128_kernel(const int* __restrict__ rowptr,
                                 const int* __restrict__ csrc,
                                 const float* __restrict__ dis,
                                 const __half2* __restrict__ h,
                                 const float* __restrict__ bias,
                                 float* __restrict__ out) {
    const int lane = threadIdx.x & 31;
    const int node = blockIdx.x * (blockDim.x >> 5) + (threadIdx.x >> 5);
    if (node >= N_NODES) return;

    const int start = rowptr[node];
    const int end   = rowptr[node + 1];
    float4 acc = make_float4(0.f, 0.f, 0.f, 0.f);

    for (int j = start; j < end; j++) {
        int s = csrc[j];
        float ws = dis[s];
        // row = 64 half2; lane covers half2 indices 2*lane, 2*lane+1
        uint2 raw = ((const uint2*)(h + (size_t)s * 64))[lane];
        float2 p0 = __half22float2(*(const __half2*)&raw.x);
        float2 p1 = __half22float2(*(const __half2*)&raw.y);
        acc.x += ws * p0.x;
        acc.y += ws * p0.y;
        acc.z += ws * p1.x;
        acc.w += ws * p1.y;
    }

    float dn = dis[node];
    float4 bv = ((const float4*)bias)[lane];
    float4 r;
    r.x = dn * acc.x + bv.x;
    r.y = dn * acc.y + bv.y;
    r.z = dn * acc.z + bv.z;
    r.w = dn * acc.w + bv.w;
    if (RELU) {
        r.x = fmaxf(r.x, 0.f); r.y = fmaxf(r.y, 0.f);
        r.z = fmaxf(r.z, 0.f); r.w = fmaxf(r.w, 0.f);
    }
    ((float4*)(out + (size_t)node * 128))[lane] = r;
}

// F=64: lane owns 2 cols (one half2, 4B) -> full row = 128B = one L2 line.
__global__ void gather64_kernel(const int* __restrict__ rowptr,
                                const int* __restrict__ csrc,
                                const float* __restrict__ dis,
                                const __half2* __restrict__ h,
                                const float* __restrict__ bias,
                                float* __restrict__ out) {
    const int lane = threadIdx.x & 31;
    const int node = blockIdx.x * (blockDim.x >> 5) + (threadIdx.x >> 5);
    if (node >= N_NODES) return;

    const int start = rowptr[node];
    const int end   = rowptr[node + 1];
    float2 acc = make_float2(0.f, 0.f);

    for (int j = start; j < end; j++) {
        int s = csrc[j];
        float ws = dis[s];
        float2 p = __half22float2(h[(size_t)s * 32 + lane]);
        acc.x += ws * p.x;
        acc.y += ws * p.y;
    }

    float dn = dis[node];
    float2 bv = ((const float2*)bias)[lane];
    float2 r;
    r.x = dn * acc.x + bv.x;
    r.y = dn * acc.y + bv.y;
    ((float2*)(out + (size_t)node * 64))[lane] = r;
}

// ---------------- launch ----------------------------------------------------------
extern "C" void kernel_launch(void* const* d_in, const int* in_sizes, int n_in,
                              void* d_out, int out_size) {
    const float* x   = (const float*)d_in[0];
    const int*   ei  = (const int*)d_in[1];   // [2, E] int32
    const float* W1  = (const float*)d_in[2];
    const float* b1  = (const float*)d_in[3];
    const float* W2  = (const float*)d_in[4];
    const float* b2  = (const float*)d_in[5];
    float*       out = (float*)d_out;

    const int* src = ei;
    const int* dst = ei + N_EDGES;

    int*      deg;      cudaGetSymbolAddress((void**)&deg,      g_deg);
    int*      rowptr;   cudaGetSymbolAddress((void**)&rowptr,   g_rowptr);
    int*      blocksum; cudaGetSymbolAddress((void**)&blocksum, g_blocksum);
    int*      cursor;   cudaGetSymbolAddress((void**)&cursor,   g_cursor);
    int*      csrc;     cudaGetSymbolAddress((void**)&csrc,     g_csrc);
    float*    dis;      cudaGetSymbolAddress((void**)&dis,      g_dis);
    __half2*  h1h;      cudaGetSymbolAddress((void**)&h1h,      g_h1h);
    float*    agg1;     cudaGetSymbolAddress((void**)&agg1,     g_agg1);
    __half2*  h2h;      cudaGetSymbolAddress((void**)&h2h,      g_h2h);
    uint32_t* w1h;      cudaGetSymbolAddress((void**)&w1h,      g_w1t_hi);
    uint32_t* w1l;      cudaGetSymbolAddress((void**)&w1l,      g_w1t_lo);
    uint32_t* w2h;      cudaGetSymbolAddress((void**)&w2h,      g_w2t_hi);
    uint32_t* w2l;      cudaGetSymbolAddress((void**)&w2l,      g_w2t_lo);

    constexpr int SMEM_G1 = (128 * 68 + 2 * 128 * 68) * 4;   // 104448
    constexpr int SMEM_G2 = (128 * 68 + 2 * 64 * 68) * 4;    //  69632
    cudaFuncSetAttribute(gemm_mma_kernel<128>, cudaFuncAttributeMaxDynamicSharedMemorySize, SMEM_G1);
    cudaFuncSetAttribute(gemm_mma_kernel<64>,  cudaFuncAttributeMaxDynamicSharedMemorySize, SMEM_G2);

    const int gemm_grid = (N_NODES + 127) / 128;  // 782

    // ncu profiles the 4th kernel launch -> place gemm1 there.
    zero_kernel<<<(N_NODES + 255) / 256, 256>>>(deg, cursor);                      // 1
    splitW_kernel<128><<<(128 * 128 + 255) / 256, 256>>>(W1, w1h, w1l);            // 2
    deg_kernel<<<(N_EDGES + 255) / 256, 256>>>(dst, deg);                          // 3
    gemm_mma_kernel<128><<<gemm_grid, 256, SMEM_G1>>>(x, w1h, w1l, h1h, N_NODES);  // 4 <- profiled
    splitW_kernel<64><<<(128 * 64 + 255) / 256, 256>>>(W2, w2h, w2l);              // 5
    scan_pass1<<<SCAN_BLOCKS, SCAN_TPB>>>(deg, blocksum);                          // 6
    scan_pass2<<<1, 256>>>(blocksum, rowptr);                                      // 7
    scan_pass3<<<SCAN_BLOCKS, SCAN_TPB>>>(deg, blocksum, rowptr, dis);             // 8
    fill_kernel<<<(N_EDGES + 255) / 256, 256>>>(src, dst, rowptr, cursor, csrc);   // 9
    gather128_kernel<true><<<(N_NODES + 7) / 8, 256>>>(rowptr, csrc, dis, h1h, b1, agg1); // 10
    gemm_mma_kernel<64><<<gemm_grid, 256, SMEM_G2>>>(agg1, w2h, w2l, h2h, N_NODES);       // 11
    gather64_kernel<<<(N_NODES + 7) / 8, 256>>>(rowptr, csrc, dis, h2h, b2, out);         // 12
}

// round 11
// speedup vs baseline: 1.1265x; 1.0017x over previous
#include <cuda_runtime.h>
#include <cuda_fp16.h>
#include <cstdint>

#define N_NODES 100000
#define N_EDGES 1600000
#define IN_DIM 128
#define HID_DIM 128
#define OUT_DIM 64

#define SCAN_TPB 512
#define SCAN_BLOCKS ((N_NODES + SCAN_TPB - 1) / SCAN_TPB)   // 196
#define GEMM_GRID 152
#define NTILES ((N_NODES + 127) / 128)                      // 782

// ---------------- device scratch ------------------------------------------------
__device__ int      g_deg[N_NODES];
__device__ int      g_rowptr[N_NODES + 1];
__device__ int      g_blocksum[SCAN_BLOCKS];
__device__ int      g_cursor[N_NODES];
__device__ int      g_csrc[N_EDGES];
__device__ float    g_dis[N_NODES];
__device__ __half2  g_h1h[(size_t)N_NODES * HID_DIM / 2];   // x @ W1, fp16
__device__ float    g_agg1[(size_t)N_NODES * HID_DIM];      // relu(A_hat h1 + b1), fp32
__device__ __half2  g_h2h[(size_t)N_NODES * OUT_DIM / 2];   // agg1 @ W2, fp16
__device__ uint32_t g_w1t_hi[HID_DIM * IN_DIM];   // W1^T split: [n][k]
__device__ uint32_t g_w1t_lo[HID_DIM * IN_DIM];
__device__ uint32_t g_w2t_hi[OUT_DIM * HID_DIM];  // W2^T split: [n][k]
__device__ uint32_t g_w2t_lo[OUT_DIM * HID_DIM];

// ---------------- helpers ----------------------------------------------------------
__device__ __forceinline__ uint32_t smem_u32(const void* p) {
    uint32_t a;
    asm("{ .reg .u64 t; cvta.to.shared.u64 t, %1; cvt.u32.u64 %0, t; }" : "=r"(a) : "l"(p));
    return a;
}
__device__ __forceinline__ uint32_t cvt_tf32(float x) {
    uint32_t r;
    asm("cvt.rna.tf32.f32 %0, %1;" : "=r"(r) : "f"(x));
    return r;
}
__device__ __forceinline__ void mma_tf32(float* d, const uint32_t* a, const uint32_t* b) {
    asm volatile(
        "mma.sync.aligned.m16n8k8.row.col.f32.tf32.tf32.f32 "
        "{%0,%1,%2,%3}, {%4,%5,%6,%7}, {%8,%9}, {%0,%1,%2,%3};"
        : "+f"(d[0]), "+f"(d[1]), "+f"(d[2]), "+f"(d[3])
        : "r"(a[0]), "r"(a[1]), "r"(a[2]), "r"(a[3]), "r"(b[0]), "r"(b[1]));
}
__device__ __forceinline__ void ldsm_x4(uint32_t& r0, uint32_t& r1, uint32_t& r2, uint32_t& r3,
                                        uint32_t addr) {
    asm volatile("ldmatrix.sync.aligned.m8n8.x4.shared.b16 {%0,%1,%2,%3}, [%4];"
                 : "=r"(r0), "=r"(r1), "=r"(r2), "=r"(r3) : "r"(addr));
}
__device__ __forceinline__ void cp_async16(uint32_t dst, const void* src, int src_bytes) {
    asm volatile("cp.async.cg.shared.global [%0], [%1], 16, %2;"
                 :: "r"(dst), "l"(src), "r"(src_bytes) : "memory");
}
__device__ __forceinline__ void cp_commit() {
    asm volatile("cp.async.commit_group;" ::: "memory");
}
template<int NMAX>
__device__ __forceinline__ void cp_wait() {
    asm volatile("cp.async.wait_group %0;" :: "n"(NMAX) : "memory");
}

// ---------------- zero + degree -----------------------------------------------------
__global__ void zero_kernel(int* __restrict__ deg, int* __restrict__ cursor) {
    int i = blockIdx.x * blockDim.x + threadIdx.x;
    if (i < N_NODES) { deg[i] = 0; cursor[i] = 0; }
}
__global__ void deg_kernel(const int* __restrict__ dst, int* __restrict__ deg) {
    int i = blockIdx.x * blockDim.x + threadIdx.x;
    if (i < N_EDGES) atomicAdd(&deg[dst[i]], 1);
}

// ---------------- 3-pass exclusive scan -> rowptr (+dis in pass3) -------------------
__global__ void scan_pass1(const int* __restrict__ deg, int* __restrict__ blocksum) {
    __shared__ int warpsum[SCAN_TPB / 32];
    int idx = blockIdx.x * SCAN_TPB + threadIdx.x;
    int v = (idx < N_NODES) ? deg[idx] : 0;
    for (int o = 16; o > 0; o >>= 1) v += __shfl_down_sync(0xffffffff, v, o);
    if ((threadIdx.x & 31) == 0) warpsum[threadIdx.x >> 5] = v;
    __syncthreads();
    if (threadIdx.x < SCAN_TPB / 32) {
        int s = warpsum[threadIdx.x];
        for (int o = 8; o > 0; o >>= 1) s += __shfl_down_sync(0xffff, s, o);
        if (threadIdx.x == 0) blocksum[blockIdx.x] = s;
    }
}
__global__ void scan_pass2(int* __restrict__ blocksum, int* __restrict__ rowptr) {
    __shared__ int ws[8];
    int lane = threadIdx.x & 31;
    int wid  = threadIdx.x >> 5;
    int v = (threadIdx.x < SCAN_BLOCKS) ? blocksum[threadIdx.x] : 0;
    int sc = v;
    for (int o = 1; o < 32; o <<= 1) {
        int t = __shfl_up_sync(0xffffffff, sc, o);
        if (lane >= o) sc += t;
    }
    if (lane == 31) ws[wid] = sc;
    __syncthreads();
    if (wid == 0 && lane < 8) {
        int s = ws[lane], ss = s;
        for (int o = 1; o < 8; o <<= 1) {
            int t = __shfl_up_sync(0xff, ss, o);
            if (lane >= o) ss += t;
        }
        ws[lane] = ss - s;
    }
    __syncthreads();
    if (threadIdx.x < SCAN_BLOCKS) blocksum[threadIdx.x] = ws[wid] + sc - v;
    if (threadIdx.x == 0) rowptr[N_NODES] = N_EDGES;
}
__global__ void scan_pass3(const int* __restrict__ deg, const int* __restrict__ blocksum,
                           int* __restrict__ rowptr, float* __restrict__ dis) {
    __shared__ int warpsum[SCAN_TPB / 32];
    int idx = blockIdx.x * SCAN_TPB + threadIdx.x;
    int lane = threadIdx.x & 31;
    int wid  = threadIdx.x >> 5;
    int v = (idx < N_NODES) ? deg[idx] : 0;
    int sc = v;
    for (int o = 1; o < 32; o <<= 1) {
        int t = __shfl_up_sync(0xffffffff, sc, o);
        if (lane >= o) sc += t;
    }
    if (lane == 31) warpsum[wid] = sc;
    __syncthreads();
    if (wid == 0 && lane < SCAN_TPB / 32) {
        int s = warpsum[lane];
        int ss = s;
        for (int o = 1; o < SCAN_TPB / 32; o <<= 1) {
            int t = __shfl_up_sync(0xffff, ss, o);
            if (lane >= o) ss += t;
        }
        warpsum[lane] = ss - s;
    }
    __syncthreads();
    if (idx < N_NODES) {
        rowptr[idx] = blocksum[blockIdx.x] + warpsum[wid] + (sc - v);
        float d = (float)v;
        dis[idx] = (d > 0.0f) ? rsqrtf(d) : 0.0f;
    }
}

// ---------------- CSR fill ----------------------------------------------------------
__global__ void fill_kernel(const int* __restrict__ src, const int* __restrict__ dst,
                            const int* __restrict__ rowptr, int* __restrict__ cursor,
                            int* __restrict__ csrc) {
    int e = blockIdx.x * blockDim.x + threadIdx.x;
    if (e < N_EDGES) {
        int d = dst[e];
        int pos = rowptr[d] + atomicAdd(&cursor[d], 1);
        csrc[pos] = src[e];
    }
}

// ---------------- W transpose + tf32 split ------------------------------------------
template<int N>
__global__ void splitW_kernel(const float* __restrict__ W,
                              uint32_t* __restrict__ WT_hi, uint32_t* __restrict__ WT_lo) {
    int idx = blockIdx.x * blockDim.x + threadIdx.x;
    if (idx < 128 * N) {
        int k = idx / N, n = idx % N;
        float w = W[idx];
        uint32_t hi = cvt_tf32(w);
        float lo = w - __uint_as_float(hi);
        WT_hi[n * 128 + k] = hi;
        WT_lo[n * 128 + k] = cvt_tf32(lo);
    }
}

// ---------------- persistent tf32 GEMM: Ch(fp16) = A[M,128] @ W[128,N] ---------------
// grid=GEMM_GRID, 1 CTA/SM. B (full-K, hi+lo) resident in smem for the whole kernel;
// A streamed per 128-row tile in two K=64 chunks, double-buffered via cp.async.
// 8 warps; warp w owns rows [w*16, w*16+16) x full N. 3-term split AhBh+AhBl+AlBh.
template<int N>
__global__ void __launch_bounds__(256) gemm_mma_kernel(const float* __restrict__ A,
                                                       const uint32_t* __restrict__ BTh,
                                                       const uint32_t* __restrict__ BTl,
                                                       __half2* __restrict__ Ch, int M) {
    constexpr int STRB = 132;       // B row stride (words), full K=128 + pad
    constexpr int STRA = 68;        // A chunk row stride (words), K=64 + pad
    constexpr int NT   = N / 8;

    extern __shared__ char smem[];
    const uint32_t sb   = smem_u32(smem);
    const uint32_t bh_b = sb;
    const uint32_t bl_b = bh_b + (uint32_t)(N * STRB * 4);
    const uint32_t a_b0 = bl_b + (uint32_t)(N * STRB * 4);
    const uint32_t a_b1 = a_b0 + (uint32_t)(128 * STRA * 4);

    const int tid  = threadIdx.x;
    const int w    = tid >> 5;
    const int lane = tid & 31;
    const int g    = lane >> 2;
    const int t    = lane & 3;
    const int r0   = w * 16;
    const int rowi = lane & 7;
    const int sel  = lane >> 3;

    // ---- prologue: B (hi+lo) via cp.async, then first A chunk; one group
#pragma unroll
    for (int i = 0; i < N * 32 / 256; i++) {
        int idx = tid + i * 256;
        int r = idx >> 5, c = idx & 31;             // c indexes 16B (4-word) pieces
        cp_async16(bh_b + (uint32_t)((r * STRB + c * 4) * 4), BTh + (size_t)r * 128 + c * 4, 16);
    }
#pragma unroll
    for (int i = 0; i < N * 32 / 256; i++) {
        int idx = tid + i * 256;
        int r = idx >> 5, c = idx & 31;
        cp_async16(bl_b + (uint32_t)((r * STRB + c * 4) * 4), BTl + (size_t)r * 128 + c * 4, 16);
    }

#define STAGE_A(bufu32, m0_, chunk_)                                                        \
    _Pragma("unroll")                                                                       \
    for (int i = 0; i < 8; i++) {                                                           \
        int idx = tid + i * 256;                                                            \
        int r = idx >> 4, c = idx & 15;                                                     \
        int gm = (m0_) + r;                                                                 \
        const float* srcp = A + (size_t)(gm < M ? gm : M - 1) * 128 + (chunk_) * 64 + c * 4;\
        cp_async16((bufu32) + (uint32_t)((r * STRA + c * 4) * 4), srcp, (gm < M) ? 16 : 0); \
    }

    int tile = blockIdx.x;
    STAGE_A(a_b0, tile * 128, 0);
    cp_commit();

    // fragment lane offsets
    const uint32_t a_off =
        (uint32_t)((((sel & 1) * 8 + rowi + r0) * STRA + (sel >> 1) * 4) * 4);
    const uint32_t b_base0 =
        ((sel < 2) ? bh_b : bl_b) + (uint32_t)((rowi * STRB + (sel & 1) * 4) * 4);

    float acc[NT][4];
#pragma unroll
    for (int nt = 0; nt < NT; nt++)
#pragma unroll
        for (int j = 0; j < 4; j++) acc[nt][j] = 0.0f;

    int cur = 0;
    for (; tile < NTILES; tile += GEMM_GRID) {
#pragma unroll
        for (int chunk = 0; chunk < 2; chunk++) {
            const int   nTile  = (chunk == 0) ? tile : tile + GEMM_GRID;
            const int   nChunk = chunk ^ 1;
            const bool  have   = (nTile < NTILES);
            const uint32_t abuf_next = cur ? a_b0 : a_b1;
            if (have) { STAGE_A(abuf_next, nTile * 128, nChunk); cp_commit(); }
            if (have) cp_wait<1>(); else cp_wait<0>();
            __syncthreads();

            const uint32_t abuf = cur ? a_b1 : a_b0;
            const int kcb = chunk * 64;
#pragma unroll 1
            for (int ks = 0; ks < 8; ks++) {
                uint32_t ar[4], ah[4], al[4];
                ldsm_x4(ar[0], ar[1], ar[2], ar[3], abuf + a_off + (uint32_t)(ks * 32));
#pragma unroll
                for (int i = 0; i < 4; i++) {
                    float af = __uint_as_float(ar[i]);
                    ah[i] = cvt_tf32(af);
                    al[i] = cvt_tf32(af - __uint_as_float(ah[i]));
                }
                const uint32_t kc4 = (uint32_t)((kcb + ks * 8) * 4);
#pragma unroll
                for (int nt = 0; nt < NT; nt++) {
                    uint32_t bh[2], bl[2];
                    ldsm_x4(bh[0], bh[1], bl[0], bl[1],
                            b_base0 + (uint32_t)(nt * 8 * STRB * 4) + kc4);
                    mma_tf32(acc[nt], ah, bh);
                    mma_tf32(acc[nt], ah, bl);
                    mma_tf32(acc[nt], al, bh);
                }
            }
            __syncthreads();
            cur ^= 1;
        }
        // ---- epilogue for this tile: fp16 store, reset acc
        const int gr0 = tile * 128 + r0 + g;
#pragma unroll
        for (int nt = 0; nt < NT; nt++) {
            int cc = nt * 8 + 2 * t;
            if (gr0 < M)
                Ch[(size_t)gr0 * (N / 2) + cc / 2] = __floats2half2_rn(acc[nt][0], acc[nt][1]);
            if (gr0 + 8 < M)
                Ch[(size_t)(gr0 + 8) * (N / 2) + cc / 2] = __floats2half2_rn(acc[nt][2], acc[nt][3]);
#pragma unroll
            for (int j = 0; j < 4; j++) acc[nt][j] = 0.0f;
        }
    }
#undef STAGE_A
}

// ---------------- CSR gather (fp16 input): one warp per node -------------------------
template<bool RELU>
__global__ void gather128_kernel(const int* __restrict__ rowptr,
                                 const int* __restrict__ csrc,
                                 const float* __restrict__ dis,
                                 const __half2* __restrict__ h,
                                 const float* __restrict__ bias,
                                 float* __restrict__ out) {
    const int lane = threadIdx.x & 31;
    const int node = blockIdx.x * (blockDim.x >> 5) + (threadIdx.x >> 5);
    if (node >= N_NODES) return;

    const int start = rowptr[node];
    const int end   = rowptr[node + 1];
    float4 acc = make_float4(0.f, 0.f, 0.f, 0.f);

    for (int j = start; j < end; j++) {
        int s = csrc[j];
        float ws = dis[s];
        uint2 raw = ((const uint2*)(h + (size_t)s * 64))[lane];
        float2 p0 = __half22float2(*(const __half2*)&raw.x);
        float2 p1 = __half22float2(*(const __half2*)&raw.y);
        acc.x += ws * p0.x;
        acc.y += ws * p0.y;
        acc.z += ws * p1.x;
        acc.w += ws * p1.y;
    }

    float dn = dis[node];
    float4 bv = ((const float4*)bias)[lane];
    float4 r;
    r.x = dn * acc.x + bv.x;
    r.y = dn * acc.y + bv.y;
    r.z = dn * acc.z + bv.z;
    r.w = dn * acc.w + bv.w;
    if (RELU) {
        r.x = fmaxf(r.x, 0.f); r.y = fmaxf(r.y, 0.f);
        r.z = fmaxf(r.z, 0.f); r.w = fmaxf(r.w, 0.f);
    }
    ((float4*)(out + (size_t)node * 128))[lane] = r;
}

__global__ void gather64_kernel(const int* __restrict__ rowptr,
                                const int* __restrict__ csrc,
                                const float* __restrict__ dis,
                                const __half2* __restrict__ h,
                                const float* __restrict__ bias,
                                float* __restrict__ out) {
    const int lane = threadIdx.x & 31;
    const int node = blockIdx.x * (blockDim.x >> 5) + (threadIdx.x >> 5);
    if (node >= N_NODES) return;

    const int start = rowptr[node];
    const int end   = rowptr[node + 1];
    float2 acc = make_float2(0.f, 0.f);

    for (int j = start; j < end; j++) {
        int s = csrc[j];
        float ws = dis[s];
        float2 p = __half22float2(h[(size_t)s * 32 + lane]);
        acc.x += ws * p.x;
        acc.y += ws * p.y;
    }

    float dn = dis[node];
    float2 bv = ((const float2*)bias)[lane];
    float2 r;
    r.x = dn * acc.x + bv.x;
    r.y = dn * acc.y + bv.y;
    ((float2*)(out + (size_t)node * 64))[lane] = r;
}

// ---------------- launch ----------------------------------------------------------
extern "C" void kernel_launch(void* const* d_in, const int* in_sizes, int n_in,
                              void* d_out, int out_size) {
    const float* x   = (const float*)d_in[0];
    const int*   ei  = (const int*)d_in[1];   // [2, E] int32
    const float* W1  = (const float*)d_in[2];
    const float* b1  = (const float*)d_in[3];
    const float* W2  = (const float*)d_in[4];
    const float* b2  = (const float*)d_in[5];
    float*       out = (float*)d_out;

    const int* src = ei;
    const int* dst = ei + N_EDGES;

    int*      deg;      cudaGetSymbolAddress((void**)&deg,      g_deg);
    int*      rowptr;   cudaGetSymbolAddress((void**)&rowptr,   g_rowptr);
    int*      blocksum; cudaGetSymbolAddress((void**)&blocksum, g_blocksum);
    int*      cursor;   cudaGetSymbolAddress((void**)&cursor,   g_cursor);
    int*      csrc;     cudaGetSymbolAddress((void**)&csrc,     g_csrc);
    float*    dis;      cudaGetSymbolAddress((void**)&dis,      g_dis);
    __half2*  h1h;      cudaGetSymbolAddress((void**)&h1h,      g_h1h);
    float*    agg1;     cudaGetSymbolAddress((void**)&agg1,     g_agg1);
    __half2*  h2h;      cudaGetSymbolAddress((void**)&h2h,      g_h2h);
    uint32_t* w1h;      cudaGetSymbolAddress((void**)&w1h,      g_w1t_hi);
    uint32_t* w1l;      cudaGetSymbolAddress((void**)&w1l,      g_w1t_lo);
    uint32_t* w2h;      cudaGetSymbolAddress((void**)&w2h,      g_w2t_hi);
    uint32_t* w2l;      cudaGetSymbolAddress((void**)&w2l,      g_w2t_lo);

    // smem: B full-K (hi+lo, stride 132) + 2 A chunk buffers (stride 68)
    constexpr int SMEM_G1 = (2 * 128 * 132 + 2 * 128 * 68) * 4;   // 204800
    constexpr int SMEM_G2 = (2 * 64 * 132 + 2 * 128 * 68) * 4;    // 137216
    cudaFuncSetAttribute(gemm_mma_kernel<128>, cudaFuncAttributeMaxDynamicSharedMemorySize, SMEM_G1);
    cudaFuncSetAttribute(gemm_mma_kernel<64>,  cudaFuncAttributeMaxDynamicSharedMemorySize, SMEM_G2);

    // ncu profiles the 4th kernel launch -> keep gemm1 there.
    zero_kernel<<<(N_NODES + 255) / 256, 256>>>(deg, cursor);                      // 1
    splitW_kernel<128><<<(128 * 128 + 255) / 256, 256>>>(W1, w1h, w1l);            // 2
    deg_kernel<<<(N_EDGES + 255) / 256, 256>>>(dst, deg);                          // 3
    gemm_mma_kernel<128><<<GEMM_GRID, 256, SMEM_G1>>>(x, w1h, w1l, h1h, N_NODES);  // 4 <- profiled
    splitW_kernel<64><<<(128 * 64 + 255) / 256, 256>>>(W2, w2h, w2l);              // 5
    scan_pass1<<<SCAN_BLOCKS, SCAN_TPB>>>(deg, blocksum);                          // 6
    scan_pass2<<<1, 256>>>(blocksum, rowptr);                                      // 7
    scan_pass3<<<SCAN_BLOCKS, SCAN_TPB>>>(deg, blocksum, rowptr, dis);             // 8
    fill_kernel<<<(N_EDGES + 255) / 256, 256>>>(src, dst, rowptr, cursor, csrc);   // 9
    gather128_kernel<true><<<(N_NODES + 7) / 8, 256>>>(rowptr, csrc, dis, h1h, b1, agg1); // 10
    gemm_mma_kernel<64><<<GEMM_GRID, 256, SMEM_G2>>>(agg1, w2h, w2l, h2h, N_NODES);       // 11
    gather64_kernel<<<(N_NODES + 7) / 8, 256>>>(rowptr, csrc, dis, h2h, b2, out);         // 12
}

// round 12
// speedup vs baseline: 1.3537x; 1.2017x over previous
#include <cuda_runtime.h>
#include <cuda_fp16.h>
#include <cstdint>

#define N_NODES 100000
#define N_EDGES 1600000
#define IN_DIM 128
#define HID_DIM 128
#define OUT_DIM 64

#define SCAN_TPB 512
#define SCAN_BLOCKS ((N_NODES + SCAN_TPB - 1) / SCAN_TPB)   // 196
#define GEMM_GRID 152
#define NTILES ((N_NODES + 127) / 128)                      // 782

// ---------------- device scratch ------------------------------------------------
__device__ int      g_deg[N_NODES];
__device__ int      g_rowptr[N_NODES + 1];
__device__ int      g_blocksum[SCAN_BLOCKS];
__device__ int      g_cursor[N_NODES];
__device__ int      g_csrc[N_EDGES];
__device__ float    g_dis[N_NODES];
__device__ __half2  g_h1h[(size_t)N_NODES * HID_DIM / 2];   // x @ W1, fp16
__device__ float    g_agg1[(size_t)N_NODES * HID_DIM];      // relu(A_hat h1 + b1), fp32
__device__ __half2  g_h2h[(size_t)N_NODES * OUT_DIM / 2];   // agg1 @ W2, fp16
// W^T split into fp16 hi/lo, interleaved-pair layout (see splitW): [n][64 half2 words]
__device__ __half2  g_w1t_hi[HID_DIM * 64];
__device__ __half2  g_w1t_lo[HID_DIM * 64];
__device__ __half2  g_w2t_hi[OUT_DIM * 64];
__device__ __half2  g_w2t_lo[OUT_DIM * 64];

// ---------------- helpers ----------------------------------------------------------
__device__ __forceinline__ uint32_t smem_u32(const void* p) {
    uint32_t a;
    asm("{ .reg .u64 t; cvta.to.shared.u64 t, %1; cvt.u32.u64 %0, t; }" : "=r"(a) : "l"(p));
    return a;
}
__device__ __forceinline__ void mma_f16(float* d, const uint32_t* a, const uint32_t* b) {
    asm volatile(
        "mma.sync.aligned.m16n8k16.row.col.f32.f16.f16.f32 "
        "{%0,%1,%2,%3}, {%4,%5,%6,%7}, {%8,%9}, {%0,%1,%2,%3};"
        : "+f"(d[0]), "+f"(d[1]), "+f"(d[2]), "+f"(d[3])
        : "r"(a[0]), "r"(a[1]), "r"(a[2]), "r"(a[3]), "r"(b[0]), "r"(b[1]));
}
__device__ __forceinline__ void ldsm_x4(uint32_t& r0, uint32_t& r1, uint32_t& r2, uint32_t& r3,
                                        uint32_t addr) {
    asm volatile("ldmatrix.sync.aligned.m8n8.x4.shared.b16 {%0,%1,%2,%3}, [%4];"
                 : "=r"(r0), "=r"(r1), "=r"(r2), "=r"(r3) : "r"(addr));
}
__device__ __forceinline__ void cp_async16(uint32_t dst, const void* src, int src_bytes) {
    asm volatile("cp.async.cg.shared.global [%0], [%1], 16, %2;"
                 :: "r"(dst), "l"(src), "r"(src_bytes) : "memory");
}
__device__ __forceinline__ void cp_commit() {
    asm volatile("cp.async.commit_group;" ::: "memory");
}
template<int NMAX>
__device__ __forceinline__ void cp_wait() {
    asm volatile("cp.async.wait_group %0;" :: "n"(NMAX) : "memory");
}
// split two fp32 (as u32 bits) into packed fp16 hi + fp16 lo halves
__device__ __forceinline__ void split_pack(uint32_t w0, uint32_t w1,
                                           uint32_t& hi, uint32_t& lo) {
    float f0 = __uint_as_float(w0), f1 = __uint_as_float(w1);
    __half2 h = __floats2half2_rn(f0, f1);
    float2 hf = __half22float2(h);
    __half2 l = __floats2half2_rn(f0 - hf.x, f1 - hf.y);
    hi = *(uint32_t*)&h;
    lo = *(uint32_t*)&l;
}

// ---------------- zero + degree -----------------------------------------------------
__global__ void zero_kernel(int* __restrict__ deg, int* __restrict__ cursor) {
    int i = blockIdx.x * blockDim.x + threadIdx.x;
    if (i < N_NODES) { deg[i] = 0; cursor[i] = 0; }
}
__global__ void deg_kernel(const int* __restrict__ dst, int* __restrict__ deg) {
    int i = blockIdx.x * blockDim.x + threadIdx.x;
    if (i < N_EDGES) atomicAdd(&deg[dst[i]], 1);
}

// ---------------- 3-pass exclusive scan -> rowptr (+dis in pass3) -------------------
__global__ void scan_pass1(const int* __restrict__ deg, int* __restrict__ blocksum) {
    __shared__ int warpsum[SCAN_TPB / 32];
    int idx = blockIdx.x * SCAN_TPB + threadIdx.x;
    int v = (idx < N_NODES) ? deg[idx] : 0;
    for (int o = 16; o > 0; o >>= 1) v += __shfl_down_sync(0xffffffff, v, o);
    if ((threadIdx.x & 31) == 0) warpsum[threadIdx.x >> 5] = v;
    __syncthreads();
    if (threadIdx.x < SCAN_TPB / 32) {
        int s = warpsum[threadIdx.x];
        for (int o = 8; o > 0; o >>= 1) s += __shfl_down_sync(0xffff, s, o);
        if (threadIdx.x == 0) blocksum[blockIdx.x] = s;
    }
}
__global__ void scan_pass2(int* __restrict__ blocksum, int* __restrict__ rowptr) {
    __shared__ int ws[8];
    int lane = threadIdx.x & 31;
    int wid  = threadIdx.x >> 5;
    int v = (threadIdx.x < SCAN_BLOCKS) ? blocksum[threadIdx.x] : 0;
    int sc = v;
    for (int o = 1; o < 32; o <<= 1) {
        int t = __shfl_up_sync(0xffffffff, sc, o);
        if (lane >= o) sc += t;
    }
    if (lane == 31) ws[wid] = sc;
    __syncthreads();
    if (wid == 0 && lane < 8) {
        int s = ws[lane], ss = s;
        for (int o = 1; o < 8; o <<= 1) {
            int t = __shfl_up_sync(0xff, ss, o);
            if (lane >= o) ss += t;
        }
        ws[lane] = ss - s;
    }
    __syncthreads();
    if (threadIdx.x < SCAN_BLOCKS) blocksum[threadIdx.x] = ws[wid] + sc - v;
    if (threadIdx.x == 0) rowptr[N_NODES] = N_EDGES;
}
__global__ void scan_pass3(const int* __restrict__ deg, const int* __restrict__ blocksum,
                           int* __restrict__ rowptr, float* __restrict__ dis) {
    __shared__ int warpsum[SCAN_TPB / 32];
    int idx = blockIdx.x * SCAN_TPB + threadIdx.x;
    int lane = threadIdx.x & 31;
    int wid  = threadIdx.x >> 5;
    int v = (idx < N_NODES) ? deg[idx] : 0;
    int sc = v;
    for (int o = 1; o < 32; o <<= 1) {
        int t = __shfl_up_sync(0xffffffff, sc, o);
        if (lane >= o) sc += t;
    }
    if (lane == 31) warpsum[wid] = sc;
    __syncthreads();
    if (wid == 0 && lane < SCAN_TPB / 32) {
        int s = warpsum[lane];
        int ss = s;
        for (int o = 1; o < SCAN_TPB / 32; o <<= 1) {
            int t = __shfl_up_sync(0xffff, ss, o);
            if (lane >= o) ss += t;
        }
        warpsum[lane] = ss - s;
    }
    __syncthreads();
    if (idx < N_NODES) {
        rowptr[idx] = blocksum[blockIdx.x] + warpsum[wid] + (sc - v);
        float d = (float)v;
        dis[idx] = (d > 0.0f) ? rsqrtf(d) : 0.0f;
    }
}

// ---------------- CSR fill ----------------------------------------------------------
__global__ void fill_kernel(const int* __restrict__ src, const int* __restrict__ dst,
                            const int* __restrict__ rowptr, int* __restrict__ cursor,
                            int* __restrict__ csrc) {
    int e = blockIdx.x * blockDim.x + threadIdx.x;
    if (e < N_EDGES) {
        int d = dst[e];
        int pos = rowptr[d] + atomicAdd(&cursor[d], 1);
        csrc[pos] = src[e];
    }
}

// ---------------- W transpose + fp16 split, interleaved-pair layout ------------------
// W: [K=128, N] row-major -> WT_hi/lo: [n][64 half2 words].
// Per k16 block b (b=0..7), word w (0..7), t=w&3:
//   w<4: word = {W[16b+t][n],   W[16b+t+4][n]}     (MMA slot b0)
//   w>=4: word = {W[16b+8+t][n], W[16b+12+t][n]}   (MMA slot b1)
template<int N>
__global__ void splitW_kernel(const float* __restrict__ W,
                              __half2* __restrict__ WTh, __half2* __restrict__ WTl) {
    int idx = blockIdx.x * blockDim.x + threadIdx.x;
    if (idx < N * 64) {
        int n = idx >> 6, word = idx & 63;
        int b = word >> 3, w = word & 7;
        int t = w & 3;
        int k0 = b * 16 + ((w >> 2) << 3) + t;
        int k1 = k0 + 4;
        float v0 = W[k0 * N + n], v1 = W[k1 * N + n];
        __half2 h = __floats2half2_rn(v0, v1);
        float2 hf = __half22float2(h);
        __half2 l = __floats2half2_rn(v0 - hf.x, v1 - hf.y);
        WTh[n * 64 + word] = h;
        WTl[n * 64 + word] = l;
    }
}

// ---------------- persistent fp16-split GEMM: Ch(fp16) = A[M,128] @ W[128,N] ---------
// grid=GEMM_GRID, 1 CTA/SM. B (fp16 hi+lo, full K, interleaved pairs) smem-resident;
// A (fp32) streamed per 128-row tile in two K=64 chunks, double-buffered cp.async.
// 8 warps; warp w owns rows [w*16, w*16+16) x full N.
// mma m16n8k16: 3-term split AhBh + AhBl + AlBh (fp32 accumulate).
template<int N>
__global__ void __launch_bounds__(256) gemm_mma_kernel(const float* __restrict__ A,
                                                       const __half2* __restrict__ BTh,
                                                       const __half2* __restrict__ BTl,
                                                       __half2* __restrict__ Ch, int M) {
    constexpr int STRB = 68;        // B row stride (half2 words = 4B each), 64 + pad
    constexpr int STRA = 68;        // A chunk row stride (fp32 words), 64 + pad
    constexpr int NT   = N / 8;

    extern __shared__ char smem[];
    const uint32_t sb   = smem_u32(smem);
    const uint32_t bh_b = sb;
    const uint32_t bl_b = bh_b + (uint32_t)(N * STRB * 4);
    const uint32_t a_b0 = bl_b + (uint32_t)(N * STRB * 4);
    const uint32_t a_b1 = a_b0 + (uint32_t)(128 * STRA * 4);

    const int tid  = threadIdx.x;
    const int w    = tid >> 5;
    const int lane = tid & 31;
    const int g    = lane >> 2;
    const int t    = lane & 3;
    const int r0   = w * 16;
    const int rowi = lane & 7;
    const int sel  = lane >> 3;

    // ---- prologue: B (hi+lo) via cp.async (16B pieces = 4 half2 words)
#pragma unroll
    for (int i = 0; i < N * 16 / 256; i++) {
        int idx = tid + i * 256;
        int r = idx >> 4, c = idx & 15;
        cp_async16(bh_b + (uint32_t)((r * STRB + c * 4) * 4), BTh + (size_t)r * 64 + c * 4, 16);
    }
#pragma unroll
    for (int i = 0; i < N * 16 / 256; i++) {
        int idx = tid + i * 256;
        int r = idx >> 4, c = idx & 15;
        cp_async16(bl_b + (uint32_t)((r * STRB + c * 4) * 4), BTl + (size_t)r * 64 + c * 4, 16);
    }

#define STAGE_A(bufu32, m0_, chunk_)                                                        \
    _Pragma("unroll")                                                                       \
    for (int i = 0; i < 8; i++) {                                                           \
        int idx = tid + i * 256;                                                            \
        int r = idx >> 4, c = idx & 15;                                                     \
        int gm = (m0_) + r;                                                                 \
        const float* srcp = A + (size_t)(gm < M ? gm : M - 1) * 128 + (chunk_) * 64 + c * 4;\
        cp_async16((bufu32) + (uint32_t)((r * STRA + c * 4) * 4), srcp, (gm < M) ? 16 : 0); \
    }

    int tile = blockIdx.x;
    STAGE_A(a_b0, tile * 128, 0);
    cp_commit();

    // ldsm lane bases
    const uint32_t a_off =
        (uint32_t)((((sel & 1) * 8 + rowi + r0) * STRA + (sel >> 1) * 4) * 4);
    // B quad: {Bh b0, Bh b1, Bl b0, Bl b1}
    const uint32_t b_base0 =
        ((sel < 2) ? bh_b : bl_b) + (uint32_t)((rowi * STRB + (sel & 1) * 4) * 4);

    float acc[NT][4];
#pragma unroll
    for (int nt = 0; nt < NT; nt++)
#pragma unroll
        for (int j = 0; j < 4; j++) acc[nt][j] = 0.0f;

    int cur = 0;
    for (; tile < NTILES; tile += GEMM_GRID) {
#pragma unroll
        for (int chunk = 0; chunk < 2; chunk++) {
            const int   nTile  = (chunk == 0) ? tile : tile + GEMM_GRID;
            const int   nChunk = chunk ^ 1;
            const bool  have   = (nTile < NTILES);
            const uint32_t abuf_next = cur ? a_b0 : a_b1;
            if (have) { STAGE_A(abuf_next, nTile * 128, nChunk); cp_commit(); }
            if (have) cp_wait<1>(); else cp_wait<0>();
            __syncthreads();

            const uint32_t abuf = cur ? a_b1 : a_b0;
#pragma unroll 1
            for (int ks = 0; ks < 4; ks++) {        // 4 k16-steps per K=64 chunk
                // A: two b16-ldsm quads give fp32 words at k = kc+{t,t+4,t+8,t+12}
                uint32_t ar[8];
                ldsm_x4(ar[0], ar[1], ar[2], ar[3], abuf + a_off + (uint32_t)(ks * 64));
                ldsm_x4(ar[4], ar[5], ar[6], ar[7], abuf + a_off + (uint32_t)(ks * 64 + 32));
                uint32_t ah[4], al[4];
                split_pack(ar[0], ar[2], ah[0], al[0]);   // row g,   k {t, t+4}
                split_pack(ar[1], ar[3], ah[1], al[1]);   // row g+8, k {t, t+4}
                split_pack(ar[4], ar[6], ah[2], al[2]);   // row g,   k {t+8, t+12}
                split_pack(ar[5], ar[7], ah[3], al[3]);   // row g+8, k {t+8, t+12}

                const uint32_t koff = (uint32_t)(chunk * 128 + ks * 32);
#pragma unroll
                for (int nt = 0; nt < NT; nt++) {
                    uint32_t bh[2], bl[2];
                    ldsm_x4(bh[0], bh[1], bl[0], bl[1],
                            b_base0 + (uint32_t)(nt * 8 * STRB * 4) + koff);
                    mma_f16(acc[nt], ah, bh);
                    mma_f16(acc[nt], ah, bl);
                    mma_f16(acc[nt], al, bh);
                }
            }
            __syncthreads();
            cur ^= 1;
        }
        // ---- epilogue for this tile: fp16 store, reset acc
        const int gr0 = tile * 128 + r0 + g;
#pragma unroll
        for (int nt = 0; nt < NT; nt++) {
            int cc = nt * 8 + 2 * t;
            if (gr0 < M)
                Ch[(size_t)gr0 * (N / 2) + cc / 2] = __floats2half2_rn(acc[nt][0], acc[nt][1]);
            if (gr0 + 8 < M)
                Ch[(size_t)(gr0 + 8) * (N / 2) + cc / 2] = __floats2half2_rn(acc[nt][2], acc[nt][3]);
#pragma unroll
            for (int j = 0; j < 4; j++) acc[nt][j] = 0.0f;
        }
    }
#undef STAGE_A
}

// ---------------- CSR gather (fp16 input): one warp per node -------------------------
template<bool RELU>
__global__ void gather128_kernel(const int* __restrict__ rowptr,
                                 const int* __restrict__ csrc,
                                 const float* __restrict__ dis,
                                 const __half2* __restrict__ h,
                                 const float* __restrict__ bias,
                                 float* __restrict__ out) {
    const int lane = threadIdx.x & 31;
    const int node = blockIdx.x * (blockDim.x >> 5) + (threadIdx.x >> 5);
    if (node >= N_NODES) return;

    const int start = rowptr[node];
    const int end   = rowptr[node + 1];
    float4 acc = make_float4(0.f, 0.f, 0.f, 0.f);

    for (int j = start; j < end; j++) {
        int s = csrc[j];
        float ws = dis[s];
        uint2 raw = ((const uint2*)(h + (size_t)s * 64))[lane];
        float2 p0 = __half22float2(*(const __half2*)&raw.x);
        float2 p1 = __half22float2(*(const __half2*)&raw.y);
        acc.x += ws * p0.x;
        acc.y += ws * p0.y;
        acc.z += ws * p1.x;
        acc.w += ws * p1.y;
    }

    float dn = dis[node];
    float4 bv = ((const float4*)bias)[lane];
    float4 r;
    r.x = dn * acc.x + bv.x;
    r.y = dn * acc.y + bv.y;
    r.z = dn * acc.z + bv.z;
    r.w = dn * acc.w + bv.w;
    if (RELU) {
        r.x = fmaxf(r.x, 0.f); r.y = fmaxf(r.y, 0.f);
        r.z = fmaxf(r.z, 0.f); r.w = fmaxf(r.w, 0.f);
    }
    ((float4*)(out + (size_t)node * 128))[lane] = r;
}

__global__ void gather64_kernel(const int* __restrict__ rowptr,
                                const int* __restrict__ csrc,
                                const float* __restrict__ dis,
                                const __half2* __restrict__ h,
                                const float* __restrict__ bias,
                                float* __restrict__ out) {
    const int lane = threadIdx.x & 31;
    const int node = blockIdx.x * (blockDim.x >> 5) + (threadIdx.x >> 5);
    if (node >= N_NODES) return;

    const int start = rowptr[node];
    const int end   = rowptr[node + 1];
    float2 acc = make_float2(0.f, 0.f);

    for (int j = start; j < end; j++) {
        int s = csrc[j];
        float ws = dis[s];
        float2 p = __half22float2(h[(size_t)s * 32 + lane]);
        acc.x += ws * p.x;
        acc.y += ws * p.y;
    }

    float dn = dis[node];
    float2 bv = ((const float2*)bias)[lane];
    float2 r;
    r.x = dn * acc.x + bv.x;
    r.y = dn * acc.y + bv.y;
    ((float2*)(out + (size_t)node * 64))[lane] = r;
}

// ---------------- launch ----------------------------------------------------------
extern "C" void kernel_launch(void* const* d_in, const int* in_sizes, int n_in,
                              void* d_out, int out_size) {
    const float* x   = (const float*)d_in[0];
    const int*   ei  = (const int*)d_in[1];   // [2, E] int32
    const float* W1  = (const float*)d_in[2];
    const float* b1  = (const float*)d_in[3];
    const float* W2  = (const float*)d_in[4];
    const float* b2  = (const float*)d_in[5];
    float*       out = (float*)d_out;

    const int* src = ei;
    const int* dst = ei + N_EDGES;

    int*      deg;      cudaGetSymbolAddress((void**)&deg,      g_deg);
    int*      rowptr;   cudaGetSymbolAddress((void**)&rowptr,   g_rowptr);
    int*      blocksum; cudaGetSymbolAddress((void**)&blocksum, g_blocksum);
    int*      cursor;   cudaGetSymbolAddress((void**)&cursor,   g_cursor);
    int*      csrc;     cudaGetSymbolAddress((void**)&csrc,     g_csrc);
    float*    dis;      cudaGetSymbolAddress((void**)&dis,      g_dis);
    __half2*  h1h;      cudaGetSymbolAddress((void**)&h1h,      g_h1h);
    float*    agg1;     cudaGetSymbolAddress((void**)&agg1,     g_agg1);
    __half2*  h2h;      cudaGetSymbolAddress((void**)&h2h,      g_h2h);
    __half2*  w1h;      cudaGetSymbolAddress((void**)&w1h,      g_w1t_hi);
    __half2*  w1l;      cudaGetSymbolAddress((void**)&w1l,      g_w1t_lo);
    __half2*  w2h;      cudaGetSymbolAddress((void**)&w2h,      g_w2t_hi);
    __half2*  w2l;      cudaGetSymbolAddress((void**)&w2l,      g_w2t_lo);

    // smem: B fp16 hi+lo (stride 68 half2-words) + 2 A fp32 chunk buffers (stride 68)
    constexpr int SMEM_G1 = (2 * 128 * 68 + 2 * 128 * 68) * 4;   // 139264
    constexpr int SMEM_G2 = (2 * 64 * 68 + 2 * 128 * 68) * 4;    // 104448
    cudaFuncSetAttribute(gemm_mma_kernel<128>, cudaFuncAttributeMaxDynamicSharedMemorySize, SMEM_G1);
    cudaFuncSetAttribute(gemm_mma_kernel<64>,  cudaFuncAttributeMaxDynamicSharedMemorySize, SMEM_G2);

    // ncu profiles the 4th kernel launch -> keep gemm1 there.
    zero_kernel<<<(N_NODES + 255) / 256, 256>>>(deg, cursor);                      // 1
    splitW_kernel<128><<<(128 * 64 + 255) / 256, 256>>>(W1, w1h, w1l);             // 2
    deg_kernel<<<(N_EDGES + 255) / 256, 256>>>(dst, deg);                          // 3
    gemm_mma_kernel<128><<<GEMM_GRID, 256, SMEM_G1>>>(x, w1h, w1l, h1h, N_NODES);  // 4 <- profiled
    splitW_kernel<64><<<(64 * 64 + 255) / 256, 256>>>(W2, w2h, w2l);               // 5
    scan_pass1<<<SCAN_BLOCKS, SCAN_TPB>>>(deg, blocksum);                          // 6
    scan_pass2<<<1, 256>>>(blocksum, rowptr);                                      // 7
    scan_pass3<<<SCAN_BLOCKS, SCAN_TPB>>>(deg, blocksum, rowptr, dis);             // 8
    fill_kernel<<<(N_EDGES + 255) / 256, 256>>>(src, dst, rowptr, cursor, csrc);   // 9
    gather128_kernel<true><<<(N_NODES + 7) / 8, 256>>>(rowptr, csrc, dis, h1h, b1, agg1); // 10
    gemm_mma_kernel<64><<<GEMM_GRID, 256, SMEM_G2>>>(agg1, w2h, w2l, h2h, N_NODES);       // 11
    gather64_kernel<<<(N_NODES + 7) / 8, 256>>>(rowptr, csrc, dis, h2h, b2, out);         // 12
}

// round 13
// speedup vs baseline: 1.3670x; 1.0098x over previous
#include <cuda_runtime.h>
#include <cuda_fp16.h>
#include <cstdint>

#define N_NODES 100000
#define N_EDGES 1600000
#define IN_DIM 128
#define HID_DIM 128
#define OUT_DIM 64

#define SCAN_TPB 512
#define SCAN_BLOCKS ((N_NODES + SCAN_TPB - 1) / SCAN_TPB)   // 196
#define GEMM_SMS 152
#define NTILES ((N_NODES + 127) / 128)                      // 782

// ---------------- device scratch ------------------------------------------------
__device__ int      g_deg[N_NODES];
__device__ int      g_rowptr[N_NODES + 1];
__device__ int      g_blocksum[SCAN_BLOCKS];
__device__ int      g_epos[N_EDGES];
__device__ int      g_csrc[N_EDGES];
__device__ float    g_dis[N_NODES];
__device__ __half2  g_h1h[(size_t)N_NODES * HID_DIM / 2];   // x @ W1, fp16
__device__ float    g_agg1[(size_t)N_NODES * HID_DIM];      // relu(A_hat h1 + b1), fp32
__device__ __half2  g_h2h[(size_t)N_NODES * OUT_DIM / 2];   // agg1 @ W2, fp16
// W^T split into fp16 hi/lo, interleaved-pair layout (see splitW): [n][64 half2 words]
__device__ __half2  g_w1t_hi[HID_DIM * 64];
__device__ __half2  g_w1t_lo[HID_DIM * 64];
__device__ __half2  g_w2t_hi[OUT_DIM * 64];
__device__ __half2  g_w2t_lo[OUT_DIM * 64];

// ---------------- helpers ----------------------------------------------------------
__device__ __forceinline__ uint32_t smem_u32(const void* p) {
    uint32_t a;
    asm("{ .reg .u64 t; cvta.to.shared.u64 t, %1; cvt.u32.u64 %0, t; }" : "=r"(a) : "l"(p));
    return a;
}
__device__ __forceinline__ void mma_f16(float* d, const uint32_t* a, const uint32_t* b) {
    asm volatile(
        "mma.sync.aligned.m16n8k16.row.col.f32.f16.f16.f32 "
        "{%0,%1,%2,%3}, {%4,%5,%6,%7}, {%8,%9}, {%0,%1,%2,%3};"
        : "+f"(d[0]), "+f"(d[1]), "+f"(d[2]), "+f"(d[3])
        : "r"(a[0]), "r"(a[1]), "r"(a[2]), "r"(a[3]), "r"(b[0]), "r"(b[1]));
}
__device__ __forceinline__ void ldsm_x4(uint32_t& r0, uint32_t& r1, uint32_t& r2, uint32_t& r3,
                                        uint32_t addr) {
    asm volatile("ldmatrix.sync.aligned.m8n8.x4.shared.b16 {%0,%1,%2,%3}, [%4];"
                 : "=r"(r0), "=r"(r1), "=r"(r2), "=r"(r3) : "r"(addr));
}
__device__ __forceinline__ void cp_async16(uint32_t dst, const void* src, int src_bytes) {
    asm volatile("cp.async.cg.shared.global [%0], [%1], 16, %2;"
                 :: "r"(dst), "l"(src), "r"(src_bytes) : "memory");
}
__device__ __forceinline__ void cp_commit() {
    asm volatile("cp.async.commit_group;" ::: "memory");
}
template<int NMAX>
__device__ __forceinline__ void cp_wait() {
    asm volatile("cp.async.wait_group %0;" :: "n"(NMAX) : "memory");
}
// split two fp32 (as u32 bits) into packed fp16 hi + fp16 lo halves
__device__ __forceinline__ void split_pack(uint32_t w0, uint32_t w1,
                                           uint32_t& hi, uint32_t& lo) {
    float f0 = __uint_as_float(w0), f1 = __uint_as_float(w1);
    __half2 h = __floats2half2_rn(f0, f1);
    float2 hf = __half22float2(h);
    __half2 l = __floats2half2_rn(f0 - hf.x, f1 - hf.y);
    hi = *(uint32_t*)&h;
    lo = *(uint32_t*)&l;
}

// ---------------- zero + degree (+edge position) -------------------------------------
__global__ void zero_kernel(int* __restrict__ deg) {
    int i = blockIdx.x * blockDim.x + threadIdx.x;
    if (i < N_NODES) deg[i] = 0;
}
// Counts in-degree AND records each edge's slot within its destination bucket.
__global__ void deg_kernel(const int* __restrict__ dst, int* __restrict__ deg,
                           int* __restrict__ epos) {
    int i = blockIdx.x * blockDim.x + threadIdx.x;
    if (i < N_EDGES) epos[i] = atomicAdd(&deg[dst[i]], 1);
}

// ---------------- 3-pass exclusive scan -> rowptr (+dis in pass3) -------------------
__global__ void scan_pass1(const int* __restrict__ deg, int* __restrict__ blocksum) {
    __shared__ int warpsum[SCAN_TPB / 32];
    int idx = blockIdx.x * SCAN_TPB + threadIdx.x;
    int v = (idx < N_NODES) ? deg[idx] : 0;
    for (int o = 16; o > 0; o >>= 1) v += __shfl_down_sync(0xffffffff, v, o);
    if ((threadIdx.x & 31) == 0) warpsum[threadIdx.x >> 5] = v;
    __syncthreads();
    if (threadIdx.x < SCAN_TPB / 32) {
        int s = warpsum[threadIdx.x];
        for (int o = 8; o > 0; o >>= 1) s += __shfl_down_sync(0xffff, s, o);
        if (threadIdx.x == 0) blocksum[blockIdx.x] = s;
    }
}
__global__ void scan_pass2(int* __restrict__ blocksum, int* __restrict__ rowptr) {
    __shared__ int ws[8];
    int lane = threadIdx.x & 31;
    int wid  = threadIdx.x >> 5;
    int v = (threadIdx.x < SCAN_BLOCKS) ? blocksum[threadIdx.x] : 0;
    int sc = v;
    for (int o = 1; o < 32; o <<= 1) {
        int t = __shfl_up_sync(0xffffffff, sc, o);
        if (lane >= o) sc += t;
    }
    if (lane == 31) ws[wid] = sc;
    __syncthreads();
    if (wid == 0 && lane < 8) {
        int s = ws[lane], ss = s;
        for (int o = 1; o < 8; o <<= 1) {
            int t = __shfl_up_sync(0xff, ss, o);
            if (lane >= o) ss += t;
        }
        ws[lane] = ss - s;
    }
    __syncthreads();
    if (threadIdx.x < SCAN_BLOCKS) blocksum[threadIdx.x] = ws[wid] + sc - v;
    if (threadIdx.x == 0) rowptr[N_NODES] = N_EDGES;
}
__global__ void scan_pass3(const int* __restrict__ deg, const int* __restrict__ blocksum,
                           int* __restrict__ rowptr, float* __restrict__ dis) {
    __shared__ int warpsum[SCAN_TPB / 32];
    int idx = blockIdx.x * SCAN_TPB + threadIdx.x;
    int lane = threadIdx.x & 31;
    int wid  = threadIdx.x >> 5;
    int v = (idx < N_NODES) ? deg[idx] : 0;
    int sc = v;
    for (int o = 1; o < 32; o <<= 1) {
        int t = __shfl_up_sync(0xffffffff, sc, o);
        if (lane >= o) sc += t;
    }
    if (lane == 31) warpsum[wid] = sc;
    __syncthreads();
    if (wid == 0 && lane < SCAN_TPB / 32) {
        int s = warpsum[lane];
        int ss = s;
        for (int o = 1; o < SCAN_TPB / 32; o <<= 1) {
            int t = __shfl_up_sync(0xffff, ss, o);
            if (lane >= o) ss += t;
        }
        warpsum[lane] = ss - s;
    }
    __syncthreads();
    if (idx < N_NODES) {
        rowptr[idx] = blocksum[blockIdx.x] + warpsum[wid] + (sc - v);
        float d = (float)v;
        dis[idx] = (d > 0.0f) ? rsqrtf(d) : 0.0f;
    }
}

// ---------------- CSR fill (atomic-free: uses precomputed epos) ----------------------
__global__ void fill_kernel(const int* __restrict__ src, const int* __restrict__ dst,
                            const int* __restrict__ rowptr, const int* __restrict__ epos,
                            int* __restrict__ csrc) {
    int e = blockIdx.x * blockDim.x + threadIdx.x;
    if (e < N_EDGES) {
        csrc[rowptr[dst[e]] + epos[e]] = src[e];
    }
}

// ---------------- W transpose + fp16 split, interleaved-pair layout ------------------
template<int N>
__global__ void splitW_kernel(const float* __restrict__ W,
                              __half2* __restrict__ WTh, __half2* __restrict__ WTl) {
    int idx = blockIdx.x * blockDim.x + threadIdx.x;
    if (idx < N * 64) {
        int n = idx >> 6, word = idx & 63;
        int b = word >> 3, w = word & 7;
        int t = w & 3;
        int k0 = b * 16 + ((w >> 2) << 3) + t;
        int k1 = k0 + 4;
        float v0 = W[k0 * N + n], v1 = W[k1 * N + n];
        __half2 h = __floats2half2_rn(v0, v1);
        float2 hf = __half22float2(h);
        __half2 l = __floats2half2_rn(v0 - hf.x, v1 - hf.y);
        WTh[n * 64 + word] = h;
        WTl[n * 64 + word] = l;
    }
}

// ---------------- persistent fp16-split GEMM, N-split across 2 CTAs/SM ----------------
// grid = 2*GEMM_SMS. CTA (bx&1) computes output cols [colhalf*N_CTA, colhalf*N_CTA+N_CTA).
// B (fp16 hi+lo for this half) smem-resident; A (fp32) streamed per 128-row tile,
// double-buffered cp.async. 8 warps; warp w owns rows [w*16,w*16+16) x N_CTA.
// mma m16n8k16: 3-term split AhBh + AhBl + AlBh (fp32 accumulate).
template<int N_CTA, int N_FULL>
__global__ void __launch_bounds__(256, 2) gemm_mma_kernel(const float* __restrict__ A,
                                                          const __half2* __restrict__ BTh,
                                                          const __half2* __restrict__ BTl,
                                                          __half2* __restrict__ Ch, int M) {
    constexpr int STRB = 68;
    constexpr int STRA = 68;
    constexpr int NT   = N_CTA / 8;

    extern __shared__ char smem[];
    const uint32_t sb   = smem_u32(smem);
    const uint32_t bh_b = sb;
    const uint32_t bl_b = bh_b + (uint32_t)(N_CTA * STRB * 4);
    const uint32_t a_b0 = bl_b + (uint32_t)(N_CTA * STRB * 4);
    const uint32_t a_b1 = a_b0 + (uint32_t)(128 * STRA * 4);

    const int tid  = threadIdx.x;
    const int w    = tid >> 5;
    const int lane = tid & 31;
    const int g    = lane >> 2;
    const int t    = lane & 3;
    const int r0   = w * 16;
    const int rowi = lane & 7;
    const int sel  = lane >> 3;
    const int colhalf = blockIdx.x & 1;

    const __half2* BThc = BTh + (size_t)colhalf * N_CTA * 64;
    const __half2* BTlc = BTl + (size_t)colhalf * N_CTA * 64;

    // ---- prologue: B (hi+lo) via cp.async (16B pieces = 4 half2 words)
#pragma unroll
    for (int i = 0; i < N_CTA * 16 / 256; i++) {
        int idx = tid + i * 256;
        int r = idx >> 4, c = idx & 15;
        cp_async16(bh_b + (uint32_t)((r * STRB + c * 4) * 4), BThc + (size_t)r * 64 + c * 4, 16);
    }
#pragma unroll
    for (int i = 0; i < N_CTA * 16 / 256; i++) {
        int idx = tid + i * 256;
        int r = idx >> 4, c = idx & 15;
        cp_async16(bl_b + (uint32_t)((r * STRB + c * 4) * 4), BTlc + (size_t)r * 64 + c * 4, 16);
    }

#define STAGE_A(bufu32, m0_, chunk_)                                                        \
    _Pragma("unroll")                                                                       \
    for (int i = 0; i < 8; i++) {                                                           \
        int idx = tid + i * 256;                                                            \
        int r = idx >> 4, c = idx & 15;                                                     \
        int gm = (m0_) + r;                                                                 \
        const float* srcp = A + (size_t)(gm < M ? gm : M - 1) * 128 + (chunk_) * 64 + c * 4;\
        cp_async16((bufu32) + (uint32_t)((r * STRA + c * 4) * 4), srcp, (gm < M) ? 16 : 0); \
    }

    int tile = blockIdx.x >> 1;
    STAGE_A(a_b0, tile * 128, 0);
    cp_commit();

    const uint32_t a_off =
        (uint32_t)((((sel & 1) * 8 + rowi + r0) * STRA + (sel >> 1) * 4) * 4);
    const uint32_t b_base0 =
        ((sel < 2) ? bh_b : bl_b) + (uint32_t)((rowi * STRB + (sel & 1) * 4) * 4);

    float acc[NT][4];
#pragma unroll
    for (int nt = 0; nt < NT; nt++)
#pragma unroll
        for (int j = 0; j < 4; j++) acc[nt][j] = 0.0f;

    int cur = 0;
    for (; tile < NTILES; tile += GEMM_SMS) {
#pragma unroll
        for (int chunk = 0; chunk < 2; chunk++) {
            const int   nTile  = (chunk == 0) ? tile : tile + GEMM_SMS;
            const int   nChunk = chunk ^ 1;
            const bool  have   = (nTile < NTILES);
            const uint32_t abuf_next = cur ? a_b0 : a_b1;
            if (have) { STAGE_A(abuf_next, nTile * 128, nChunk); cp_commit(); }
            if (have) cp_wait<1>(); else cp_wait<0>();
            __syncthreads();

            const uint32_t abuf = cur ? a_b1 : a_b0;
#pragma unroll 1
            for (int ks = 0; ks < 4; ks++) {        // 4 k16-steps per K=64 chunk
                uint32_t ar[8];
                ldsm_x4(ar[0], ar[1], ar[2], ar[3], abuf + a_off + (uint32_t)(ks * 64));
                ldsm_x4(ar[4], ar[5], ar[6], ar[7], abuf + a_off + (uint32_t)(ks * 64 + 32));
                uint32_t ah[4], al[4];
                split_pack(ar[0], ar[2], ah[0], al[0]);
                split_pack(ar[1], ar[3], ah[1], al[1]);
                split_pack(ar[4], ar[6], ah[2], al[2]);
                split_pack(ar[5], ar[7], ah[3], al[3]);

                const uint32_t koff = (uint32_t)(chunk * 128 + ks * 32);
#pragma unroll
                for (int nt = 0; nt < NT; nt++) {
                    uint32_t bh[2], bl[2];
                    ldsm_x4(bh[0], bh[1], bl[0], bl[1],
                            b_base0 + (uint32_t)(nt * 8 * STRB * 4) + koff);
                    mma_f16(acc[nt], ah, bh);
                    mma_f16(acc[nt], ah, bl);
                    mma_f16(acc[nt], al, bh);
                }
            }
            __syncthreads();
            cur ^= 1;
        }
        // ---- epilogue for this tile: fp16 store, reset acc
        const int gr0 = tile * 128 + r0 + g;
#pragma unroll
        for (int nt = 0; nt < NT; nt++) {
            int cc = colhalf * N_CTA + nt * 8 + 2 * t;
            if (gr0 < M)
                Ch[(size_t)gr0 * (N_FULL / 2) + cc / 2] =
                    __floats2half2_rn(acc[nt][0], acc[nt][1]);
            if (gr0 + 8 < M)
                Ch[(size_t)(gr0 + 8) * (N_FULL / 2) + cc / 2] =
                    __floats2half2_rn(acc[nt][2], acc[nt][3]);
#pragma unroll
            for (int j = 0; j < 4; j++) acc[nt][j] = 0.0f;
        }
    }
#undef STAGE_A
}

// ---------------- CSR gather (fp16 input): one warp per node -------------------------
template<bool RELU>
__global__ void gather128_kernel(const int* __restrict__ rowptr,
                                 const int* __restrict__ csrc,
                                 const float* __restrict__ dis,
                                 const __half2* __restrict__ h,
                                 const float* __restrict__ bias,
                                 float* __restrict__ out) {
    const int lane = threadIdx.x & 31;
    const int node = blockIdx.x * (blockDim.x >> 5) + (threadIdx.x >> 5);
    if (node >= N_NODES) return;

    const int start = rowptr[node];
    const int end   = rowptr[node + 1];
    float4 acc = make_float4(0.f, 0.f, 0.f, 0.f);

    for (int j = start; j < end; j++) {
        int s = csrc[j];
        float ws = dis[s];
        uint2 raw = ((const uint2*)(h + (size_t)s * 64))[lane];
        float2 p0 = __half22float2(*(const __half2*)&raw.x);
        float2 p1 = __half22float2(*(const __half2*)&raw.y);
        acc.x += ws * p0.x;
        acc.y += ws * p0.y;
        acc.z += ws * p1.x;
        acc.w += ws * p1.y;
    }

    float dn = dis[node];
    float4 bv = ((const float4*)bias)[lane];
    float4 r;
    r.x = dn * acc.x + bv.x;
    r.y = dn * acc.y + bv.y;
    r.z = dn * acc.z + bv.z;
    r.w = dn * acc.w + bv.w;
    if (RELU) {
        r.x = fmaxf(r.x, 0.f); r.y = fmaxf(r.y, 0.f);
        r.z = fmaxf(r.z, 0.f); r.w = fmaxf(r.w, 0.f);
    }
    ((float4*)(out + (size_t)node * 128))[lane] = r;
}

__global__ void gather64_kernel(const int* __restrict__ rowptr,
                                const int* __restrict__ csrc,
                                const float* __restrict__ dis,
                                const __half2* __restrict__ h,
                                const float* __restrict__ bias,
                                float* __restrict__ out) {
    const int lane = threadIdx.x & 31;
    const int node = blockIdx.x * (blockDim.x >> 5) + (threadIdx.x >> 5);
    if (node >= N_NODES) return;

    const int start = rowptr[node];
    const int end   = rowptr[node + 1];
    float2 acc = make_float2(0.f, 0.f);

    for (int j = start; j < end; j++) {
        int s = csrc[j];
        float ws = dis[s];
        float2 p = __half22float2(h[(size_t)s * 32 + lane]);
        acc.x += ws * p.x;
        acc.y += ws * p.y;
    }

    float dn = dis[node];
    float2 bv = ((const float2*)bias)[lane];
    float2 r;
    r.x = dn * acc.x + bv.x;
    r.y = dn * acc.y + bv.y;
    ((float2*)(out + (size_t)node * 64))[lane] = r;
}

// ---------------- launch ----------------------------------------------------------
extern "C" void kernel_launch(void* const* d_in, const int* in_sizes, int n_in,
                              void* d_out, int out_size) {
    const float* x   = (const float*)d_in[0];
    const int*   ei  = (const int*)d_in[1];   // [2, E] int32
    const float* W1  = (const float*)d_in[2];
    const float* b1  = (const float*)d_in[3];
    const float* W2  = (const float*)d_in[4];
    const float* b2  = (const float*)d_in[5];
    float*       out = (float*)d_out;

    const int* src = ei;
    const int* dst = ei + N_EDGES;

    int*      deg;      cudaGetSymbolAddress((void**)&deg,      g_deg);
    int*      rowptr;   cudaGetSymbolAddress((void**)&rowptr,   g_rowptr);
    int*      blocksum; cudaGetSymbolAddress((void**)&blocksum, g_blocksum);
    int*      epos;     cudaGetSymbolAddress((void**)&epos,     g_epos);
    int*      csrc;     cudaGetSymbolAddress((void**)&csrc,     g_csrc);
    float*    dis;      cudaGetSymbolAddress((void**)&dis,      g_dis);
    __half2*  h1h;      cudaGetSymbolAddress((void**)&h1h,      g_h1h);
    float*    agg1;     cudaGetSymbolAddress((void**)&agg1,     g_agg1);
    __half2*  h2h;      cudaGetSymbolAddress((void**)&h2h,      g_h2h);
    __half2*  w1h;      cudaGetSymbolAddress((void**)&w1h,      g_w1t_hi);
    __half2*  w1l;      cudaGetSymbolAddress((void**)&w1l,      g_w1t_lo);
    __half2*  w2h;      cudaGetSymbolAddress((void**)&w2h,      g_w2t_hi);
    __half2*  w2l;      cudaGetSymbolAddress((void**)&w2l,      g_w2t_lo);

    // per-CTA smem: B fp16 hi+lo (N_CTA rows) + 2 A fp32 chunk buffers -> 2 CTAs/SM
    constexpr int SMEM_G1 = (2 * 64 * 68 + 2 * 128 * 68) * 4;   // 104448
    constexpr int SMEM_G2 = (2 * 32 * 68 + 2 * 128 * 68) * 4;   //  87040
    cudaFuncSetAttribute(gemm_mma_kernel<64, 128>,
                         cudaFuncAttributeMaxDynamicSharedMemorySize, SMEM_G1);
    cudaFuncSetAttribute(gemm_mma_kernel<32, 64>,
                         cudaFuncAttributeMaxDynamicSharedMemorySize, SMEM_G2);

    // ncu profiles the 4th kernel launch -> keep gemm1 there.
    zero_kernel<<<(N_NODES + 255) / 256, 256>>>(deg);                               // 1
    splitW_kernel<128><<<(128 * 64 + 255) / 256, 256>>>(W1, w1h, w1l);              // 2
    deg_kernel<<<(N_EDGES + 255) / 256, 256>>>(dst, deg, epos);                     // 3
    gemm_mma_kernel<64, 128><<<2 * GEMM_SMS, 256, SMEM_G1>>>(x, w1h, w1l, h1h, N_NODES); // 4
    splitW_kernel<64><<<(64 * 64 + 255) / 256, 256>>>(W2, w2h, w2l);                // 5
    scan_pass1<<<SCAN_BLOCKS, SCAN_TPB>>>(deg, blocksum);                           // 6
    scan_pass2<<<1, 256>>>(blocksum, rowptr);                                       // 7
    scan_pass3<<<SCAN_BLOCKS, SCAN_TPB>>>(deg, blocksum, rowptr, dis);              // 8
    fill_kernel<<<(N_EDGES + 255) / 256, 256>>>(src, dst, rowptr, epos, csrc);      // 9
    gather128_kernel<true><<<(N_NODES + 7) / 8, 256>>>(rowptr, csrc, dis, h1h, b1, agg1); // 10
    gemm_mma_kernel<32, 64><<<2 * GEMM_SMS, 256, SMEM_G2>>>(agg1, w2h, w2l, h2h, N_NODES); // 11
    gather64_kernel<<<(N_NODES + 7) / 8, 256>>>(rowptr, csrc, dis, h2h, b2, out);          // 12
}

// round 15
// speedup vs baseline: 1.5929x; 1.1652x over previous
#include <cuda_runtime.h>
#include <cuda_fp16.h>
#include <cstdint>

#define N_NODES 100000
#define N_EDGES 1600000
#define IN_DIM 128
#define HID_DIM 128
#define OUT_DIM 64

#define SCAN_TPB 512
#define SCAN_BLOCKS ((N_NODES + SCAN_TPB - 1) / SCAN_TPB)   // 196
#define GEMM_GRID 304
#define NTILES ((N_NODES + 127) / 128)                      // 782

// ---------------- device scratch ------------------------------------------------
__device__ int      g_deg[N_NODES];
__device__ int      g_rowptr[N_NODES + 1];
__device__ int      g_blocksum[SCAN_BLOCKS];
__device__ int      g_epos[N_EDGES];
__device__ int      g_csrc[N_EDGES];
__device__ float    g_dis[N_NODES];
__device__ __half2  g_h1h[(size_t)N_NODES * HID_DIM / 2];   // x @ W1, fp16
__device__ __half2  g_agg1h[(size_t)N_NODES * HID_DIM / 2]; // relu(A_hat h1 + b1), fp16
__device__ __half2  g_h2h[(size_t)N_NODES * OUT_DIM / 2];   // agg1 @ W2, fp16
// W1^T fp16, interleaved-pair layout (matches fp32-ldsm A slots): [n][64 half2 words]
__device__ __half2  g_w1t[HID_DIM * 64];
// W2^T fp16, natural layout: [n][128 fp16] (contiguous k)
__device__ __half2  g_w2t[OUT_DIM * 64];

// ---------------- helpers ----------------------------------------------------------
__device__ __forceinline__ uint32_t smem_u32(const void* p) {
    uint32_t a;
    asm("{ .reg .u64 t; cvta.to.shared.u64 t, %1; cvt.u32.u64 %0, t; }" : "=r"(a) : "l"(p));
    return a;
}
__device__ __forceinline__ void mma_f16(float* d, const uint32_t* a,
                                        uint32_t b0, uint32_t b1) {
    asm volatile(
        "mma.sync.aligned.m16n8k16.row.col.f32.f16.f16.f32 "
        "{%0,%1,%2,%3}, {%4,%5,%6,%7}, {%8,%9}, {%0,%1,%2,%3};"
        : "+f"(d[0]), "+f"(d[1]), "+f"(d[2]), "+f"(d[3])
        : "r"(a[0]), "r"(a[1]), "r"(a[2]), "r"(a[3]), "r"(b0), "r"(b1));
}
__device__ __forceinline__ void ldsm_x4(uint32_t& r0, uint32_t& r1, uint32_t& r2, uint32_t& r3,
                                        uint32_t addr) {
    asm volatile("ldmatrix.sync.aligned.m8n8.x4.shared.b16 {%0,%1,%2,%3}, [%4];"
                 : "=r"(r0), "=r"(r1), "=r"(r2), "=r"(r3) : "r"(addr));
}
__device__ __forceinline__ void cp_async16(uint32_t dst, const void* src, int src_bytes) {
    asm volatile("cp.async.cg.shared.global [%0], [%1], 16, %2;"
                 :: "r"(dst), "l"(src), "r"(src_bytes) : "memory");
}
__device__ __forceinline__ void cp_commit() {
    asm volatile("cp.async.commit_group;" ::: "memory");
}
template<int NMAX>
__device__ __forceinline__ void cp_wait() {
    asm volatile("cp.async.wait_group %0;" :: "n"(NMAX) : "memory");
}
__device__ __forceinline__ uint32_t pack_h2(uint32_t w0, uint32_t w1) {
    __half2 h = __floats2half2_rn(__uint_as_float(w0), __uint_as_float(w1));
    return *(uint32_t*)&h;
}

// ---------------- zero + degree (+edge position) -------------------------------------
__global__ void zero_kernel(int* __restrict__ deg) {
    int i = blockIdx.x * blockDim.x + threadIdx.x;
    if (i < N_NODES) deg[i] = 0;
}
__global__ void deg_kernel(const int* __restrict__ dst, int* __restrict__ deg,
                           int* __restrict__ epos) {
    int i = blockIdx.x * blockDim.x + threadIdx.x;
    if (i < N_EDGES) epos[i] = atomicAdd(&deg[dst[i]], 1);
}

// ---------------- 3-pass exclusive scan -> rowptr (+dis in pass3) -------------------
__global__ void scan_pass1(const int* __restrict__ deg, int* __restrict__ blocksum) {
    __shared__ int warpsum[SCAN_TPB / 32];
    int idx = blockIdx.x * SCAN_TPB + threadIdx.x;
    int v = (idx < N_NODES) ? deg[idx] : 0;
    for (int o = 16; o > 0; o >>= 1) v += __shfl_down_sync(0xffffffff, v, o);
    if ((threadIdx.x & 31) == 0) warpsum[threadIdx.x >> 5] = v;
    __syncthreads();
    if (threadIdx.x < SCAN_TPB / 32) {
        int s = warpsum[threadIdx.x];
        for (int o = 8; o > 0; o >>= 1) s += __shfl_down_sync(0xffff, s, o);
        if (threadIdx.x == 0) blocksum[blockIdx.x] = s;
    }
}
__global__ void scan_pass2(int* __restrict__ blocksum, int* __restrict__ rowptr) {
    __shared__ int ws[8];
    int lane = threadIdx.x & 31;
    int wid  = threadIdx.x >> 5;
    int v = (threadIdx.x < SCAN_BLOCKS) ? blocksum[threadIdx.x] : 0;
    int sc = v;
    for (int o = 1; o < 32; o <<= 1) {
        int t = __shfl_up_sync(0xffffffff, sc, o);
        if (lane >= o) sc += t;
    }
    if (lane == 31) ws[wid] = sc;
    __syncthreads();
    if (wid == 0 && lane < 8) {
        int s = ws[lane], ss = s;
        for (int o = 1; o < 8; o <<= 1) {
            int t = __shfl_up_sync(0xff, ss, o);
            if (lane >= o) ss += t;
        }
        ws[lane] = ss - s;
    }
    __syncthreads();
    if (threadIdx.x < SCAN_BLOCKS) blocksum[threadIdx.x] = ws[wid] + sc - v;
    if (threadIdx.x == 0) rowptr[N_NODES] = N_EDGES;
}
__global__ void scan_pass3(const int* __restrict__ deg, const int* __restrict__ blocksum,
                           int* __restrict__ rowptr, float* __restrict__ dis) {
    __shared__ int warpsum[SCAN_TPB / 32];
    int idx = blockIdx.x * SCAN_TPB + threadIdx.x;
    int lane = threadIdx.x & 31;
    int wid  = threadIdx.x >> 5;
    int v = (idx < N_NODES) ? deg[idx] : 0;
    int sc = v;
    for (int o = 1; o < 32; o <<= 1) {
        int t = __shfl_up_sync(0xffffffff, sc, o);
        if (lane >= o) sc += t;
    }
    if (lane == 31) warpsum[wid] = sc;
    __syncthreads();
    if (wid == 0 && lane < SCAN_TPB / 32) {
        int s = warpsum[lane];
        int ss = s;
        for (int o = 1; o < SCAN_TPB / 32; o <<= 1) {
            int t = __shfl_up_sync(0xffff, ss, o);
            if (lane >= o) ss += t;
        }
        warpsum[lane] = ss - s;
    }
    __syncthreads();
    if (idx < N_NODES) {
        rowptr[idx] = blocksum[blockIdx.x] + warpsum[wid] + (sc - v);
        float d = (float)v;
        dis[idx] = (d > 0.0f) ? rsqrtf(d) : 0.0f;
    }
}

// ---------------- CSR fill (atomic-free) ----------------------------------------------
__global__ void fill_kernel(const int* __restrict__ src, const int* __restrict__ dst,
                            const int* __restrict__ rowptr, const int* __restrict__ epos,
                            int* __restrict__ csrc) {
    int e = blockIdx.x * blockDim.x + threadIdx.x;
    if (e < N_EDGES) {
        csrc[rowptr[dst[e]] + epos[e]] = src[e];
    }
}

// ---------------- W1^T fp16 interleaved-pair; W2^T fp16 natural -----------------------
// W1 [128,128] -> [n][64 half2]: block b, word w, t=w&3:
//   k0 = 16b + ((w>>2)<<3) + t, k1 = k0+4
__global__ void splitW1_kernel(const float* __restrict__ W, __half2* __restrict__ WT) {
    int idx = blockIdx.x * blockDim.x + threadIdx.x;
    if (idx < 128 * 64) {
        int n = idx >> 6, word = idx & 63;
        int b = word >> 3, w = word & 7;
        int t = w & 3;
        int k0 = b * 16 + ((w >> 2) << 3) + t;
        WT[n * 64 + word] = __floats2half2_rn(W[k0 * 128 + n], W[(k0 + 4) * 128 + n]);
    }
}
// W2 [128,64] -> [n][64 half2] natural: word w = {W[2w][n], W[2w+1][n]}
__global__ void transW2_kernel(const float* __restrict__ W, __half2* __restrict__ WT) {
    int idx = blockIdx.x * blockDim.x + threadIdx.x;
    if (idx < 64 * 64) {
        int n = idx >> 6, word = idx & 63;
        WT[n * 64 + word] = __floats2half2_rn(W[(2 * word) * 64 + n],
                                              W[(2 * word + 1) * 64 + n]);
    }
}

// ---------------- GEMM1 (pure fp16): h1(fp16) = fp16(x) @ W1 -------------------------
// Persistent, grid=GEMM_GRID. B (fp16, full K, interleaved pairs) smem-resident;
// A (fp32) streamed per 128-row tile in two K=64 chunks, double-buffered cp.async,
// converted to fp16 in registers. 8 warps; warp w owns rows [w*16,w*16+16) x N=128.
__global__ void __launch_bounds__(256, 2) gemm1_kernel(const float* __restrict__ A,
                                                       const __half2* __restrict__ BT,
                                                       __half2* __restrict__ Ch, int M) {
    constexpr int N    = 128;
    constexpr int STRB = 272;       // B row stride bytes (128 fp16 + 8 pad)
    constexpr int STRA = 272;       // A chunk row stride bytes (64 fp32 + 4 pad)
    constexpr int NT2  = N / 16;    // 8 n-pair blocks

    extern __shared__ char smem[];
    const uint32_t sb   = smem_u32(smem);
    const uint32_t b_b  = sb;
    const uint32_t a_b0 = b_b + (uint32_t)(N * STRB);
    const uint32_t a_b1 = a_b0 + (uint32_t)(128 * STRA);

    const int tid  = threadIdx.x;
    const int w    = tid >> 5;
    const int lane = tid & 31;
    const int g    = lane >> 2;
    const int t    = lane & 3;
    const int r0   = w * 16;
    const int rowi = lane & 7;
    const int sel  = lane >> 3;

    // ---- prologue: B via cp.async (16B pieces)
#pragma unroll
    for (int i = 0; i < N * 16 / 256; i++) {
        int idx = tid + i * 256;
        int r = idx >> 4, c = idx & 15;
        cp_async16(b_b + (uint32_t)(r * STRB + c * 16), BT + (size_t)r * 64 + c * 4, 16);
    }

#define STAGE_A1(bufu32, m0_, chunk_)                                                       \
    _Pragma("unroll")                                                                       \
    for (int i = 0; i < 8; i++) {                                                           \
        int idx = tid + i * 256;                                                            \
        int r = idx >> 4, c = idx & 15;                                                     \
        int gm = (m0_) + r;                                                                 \
        const float* srcp = A + (size_t)(gm < M ? gm : M - 1) * 128 + (chunk_) * 64 + c * 4;\
        cp_async16((bufu32) + (uint32_t)(r * STRA + c * 16), srcp, (gm < M) ? 16 : 0);      \
    }

    int tile = blockIdx.x;
    STAGE_A1(a_b0, tile * 128, 0);
    cp_commit();

    // A quad (fp32 data via b16 ldsm): rows r0+(sel&1)*8+rowi, 16B-half (sel>>1)
    const uint32_t a_off =
        (uint32_t)((r0 + (sel & 1) * 8 + rowi) * STRA + (sel >> 1) * 16);
    // B quad: n-rows rowi + 8*(sel>>1), 16B word-half (sel&1)
    const uint32_t b_off =
        b_b + (uint32_t)((rowi + (sel >> 1) * 8) * STRB + (sel & 1) * 16);

    float acc[2 * NT2][4];
#pragma unroll
    for (int nt = 0; nt < 2 * NT2; nt++)
#pragma unroll
        for (int j = 0; j < 4; j++) acc[nt][j] = 0.0f;

    int cur = 0;
    for (; tile < NTILES; tile += GEMM_GRID) {
#pragma unroll
        for (int chunk = 0; chunk < 2; chunk++) {
            const int   nTile  = (chunk == 0) ? tile : tile + GEMM_GRID;
            const int   nChunk = chunk ^ 1;
            const bool  have   = (nTile < NTILES);
            const uint32_t abuf_next = cur ? a_b0 : a_b1;
            if (have) { STAGE_A1(abuf_next, nTile * 128, nChunk); cp_commit(); }
            if (have) cp_wait<1>(); else cp_wait<0>();
            __syncthreads();

            const uint32_t abuf = cur ? a_b1 : a_b0;
#pragma unroll 1
            for (int ks = 0; ks < 4; ks++) {
                // fp32 A words at k = {t, t+4} and {t+8, t+12}; pack to fp16
                uint32_t ar[8], ah[4];
                ldsm_x4(ar[0], ar[1], ar[2], ar[3], abuf + a_off + (uint32_t)(ks * 64));
                ldsm_x4(ar[4], ar[5], ar[6], ar[7], abuf + a_off + (uint32_t)(ks * 64 + 32));
                ah[0] = pack_h2(ar[0], ar[2]);
                ah[1] = pack_h2(ar[1], ar[3]);
                ah[2] = pack_h2(ar[4], ar[6]);
                ah[3] = pack_h2(ar[5], ar[7]);

                const uint32_t koff = (uint32_t)((chunk * 4 + ks) * 32);
#pragma unroll
                for (int nt2 = 0; nt2 < NT2; nt2++) {
                    uint32_t b0, b1, b2, b3;
                    ldsm_x4(b0, b1, b2, b3, b_off + (uint32_t)(nt2 * 16 * STRB) + koff);
                    mma_f16(acc[nt2 * 2],     ah, b0, b1);
                    mma_f16(acc[nt2 * 2 + 1], ah, b2, b3);
                }
            }
            __syncthreads();
            cur ^= 1;
        }
        // ---- epilogue: fp16 store
        const int gr0 = tile * 128 + r0 + g;
#pragma unroll
        for (int nt = 0; nt < 2 * NT2; nt++) {
            int cc = nt * 8 + 2 * t;
            if (gr0 < M)
                Ch[(size_t)gr0 * 64 + cc / 2] = __floats2half2_rn(acc[nt][0], acc[nt][1]);
            if (gr0 + 8 < M)
                Ch[(size_t)(gr0 + 8) * 64 + cc / 2] = __floats2half2_rn(acc[nt][2], acc[nt][3]);
#pragma unroll
            for (int j = 0; j < 4; j++) acc[nt][j] = 0.0f;
        }
    }
#undef STAGE_A1
}

// ---------------- GEMM2 (pure fp16, native fp16 A): h2 = agg1h @ W2 ------------------
// A fp16 [M][128] staged per tile in two K=64 chunks; B natural fp16 [64][128] resident.
__global__ void __launch_bounds__(256, 2) gemm2_kernel(const __half2* __restrict__ A,
                                                       const __half2* __restrict__ BT,
                                                       __half2* __restrict__ Ch, int M) {
    constexpr int N    = 64;
    constexpr int STRB = 272;       // B row stride bytes (128 fp16 + 8 pad)
    constexpr int STRA = 144;       // A chunk row stride bytes (64 fp16 + 8 pad)
    constexpr int NT2  = N / 16;    // 4

    extern __shared__ char smem[];
    const uint32_t sb   = smem_u32(smem);
    const uint32_t b_b  = sb;
    const uint32_t a_b0 = b_b + (uint32_t)(N * STRB);
    const uint32_t a_b1 = a_b0 + (uint32_t)(128 * STRA);

    const int tid  = threadIdx.x;
    const int w    = tid >> 5;
    const int lane = tid & 31;
    const int g    = lane >> 2;
    const int t    = lane & 3;
    const int r0   = w * 16;
    const int rowi = lane & 7;
    const int sel  = lane >> 3;

    // ---- prologue: B via cp.async
#pragma unroll
    for (int i = 0; i < N * 16 / 256; i++) {
        int idx = tid + i * 256;
        int r = idx >> 4, c = idx & 15;
        cp_async16(b_b + (uint32_t)(r * STRB + c * 16), BT + (size_t)r * 64 + c * 4, 16);
    }

#define STAGE_A2(bufu32, m0_, chunk_)                                                       \
    _Pragma("unroll")                                                                       \
    for (int i = 0; i < 4; i++) {                                                           \
        int idx = tid + i * 256;                                                            \
        int r = idx >> 3, c = idx & 7;                                                      \
        int gm = (m0_) + r;                                                                 \
        const __half2* srcp = A + (size_t)(gm < M ? gm : M - 1) * 64 + (chunk_) * 32 + c * 4;\
        cp_async16((bufu32) + (uint32_t)(r * STRA + c * 16), srcp, (gm < M) ? 16 : 0);      \
    }

    int tile = blockIdx.x;
    STAGE_A2(a_b0, tile * 128, 0);
    cp_commit();

    const uint32_t a_off =
        (uint32_t)((r0 + (sel & 1) * 8 + rowi) * STRA + (sel >> 1) * 16);
    const uint32_t b_off =
        b_b + (uint32_t)((rowi + (sel >> 1) * 8) * STRB + (sel & 1) * 16);

    float acc[2 * NT2][4];
#pragma unroll
    for (int nt = 0; nt < 2 * NT2; nt++)
#pragma unroll
        for (int j = 0; j < 4; j++) acc[nt][j] = 0.0f;

    int cur = 0;
    for (; tile < NTILES; tile += GEMM_GRID) {
#pragma unroll
        for (int chunk = 0; chunk < 2; chunk++) {
            const int   nTile  = (chunk == 0) ? tile : tile + GEMM_GRID;
            const int   nChunk = chunk ^ 1;
            const bool  have   = (nTile < NTILES);
            const uint32_t abuf_next = cur ? a_b0 : a_b1;
            if (have) { STAGE_A2(abuf_next, nTile * 128, nChunk); cp_commit(); }
            if (have) cp_wait<1>(); else cp_wait<0>();
            __syncthreads();

            const uint32_t abuf = cur ? a_b1 : a_b0;
#pragma unroll 1
            for (int ks = 0; ks < 4; ks++) {
                uint32_t a[4];
                ldsm_x4(a[0], a[1], a[2], a[3], abuf + a_off + (uint32_t)(ks * 32));
                const uint32_t koff = (uint32_t)((chunk * 4 + ks) * 32);
#pragma unroll
                for (int nt2 = 0; nt2 < NT2; nt2++) {
                    uint32_t b0, b1, b2, b3;
                    ldsm_x4(b0, b1, b2, b3, b_off + (uint32_t)(nt2 * 16 * STRB) + koff);
                    mma_f16(acc[nt2 * 2],     a, b0, b1);
                    mma_f16(acc[nt2 * 2 + 1], a, b2, b3);
                }
            }
            __syncthreads();
            cur ^= 1;
        }
        const int gr0 = tile * 128 + r0 + g;
#pragma unroll
        for (int nt = 0; nt < 2 * NT2; nt++) {
            int cc = nt * 8 + 2 * t;
            if (gr0 < M)
                Ch[(size_t)gr0 * 32 + cc / 2] = __floats2half2_rn(acc[nt][0], acc[nt][1]);
            if (gr0 + 8 < M)
                Ch[(size_t)(gr0 + 8) * 32 + cc / 2] = __floats2half2_rn(acc[nt][2], acc[nt][3]);
#pragma unroll
            for (int j = 0; j < 4; j++) acc[nt][j] = 0.0f;
        }
    }
#undef STAGE_A2
}

// ---------------- CSR gather (fp16 in/out for layer 1) --------------------------------
__global__ void gather128_kernel(const int* __restrict__ rowptr,
                                 const int* __restrict__ csrc,
                                 const float* __restrict__ dis,
                                 const __half2* __restrict__ h,
                                 const float* __restrict__ bias,
                                 __half2* __restrict__ outh) {
    const int lane = threadIdx.x & 31;
    const int node = blockIdx.x * (blockDim.x >> 5) + (threadIdx.x >> 5);
    if (node >= N_NODES) return;

    const int start = rowptr[node];
    const int end   = rowptr[node + 1];
    float4 acc = make_float4(0.f, 0.f, 0.f, 0.f);

    for (int j = start; j < end; j++) {
        int s = csrc[j];
        float ws = dis[s];
        uint2 raw = ((const uint2*)(h + (size_t)s * 64))[lane];
        float2 p0 = __half22float2(*(const __half2*)&raw.x);
        float2 p1 = __half22float2(*(const __half2*)&raw.y);
        acc.x += ws * p0.x;
        acc.y += ws * p0.y;
        acc.z += ws * p1.x;
        acc.w += ws * p1.y;
    }

    float dn = dis[node];
    float4 bv = ((const float4*)bias)[lane];
    float rx = fmaxf(dn * acc.x + bv.x, 0.f);
    float ry = fmaxf(dn * acc.y + bv.y, 0.f);
    float rz = fmaxf(dn * acc.z + bv.z, 0.f);
    float rw = fmaxf(dn * acc.w + bv.w, 0.f);
    __half2 o0 = __floats2half2_rn(rx, ry);
    __half2 o1 = __floats2half2_rn(rz, rw);
    uint2 o;
    o.x = *(uint32_t*)&o0;
    o.y = *(uint32_t*)&o1;
    ((uint2*)(outh + (size_t)node * 64))[lane] = o;
}

__global__ void gather64_kernel(const int* __restrict__ rowptr,
                                const int* __restrict__ csrc,
                                const float* __restrict__ dis,
                                const __half2* __restrict__ h,
                                const float* __restrict__ bias,
                                float* __restrict__ out) {
    const int lane = threadIdx.x & 31;
    const int node = blockIdx.x * (blockDim.x >> 5) + (threadIdx.x >> 5);
    if (node >= N_NODES) return;

    const int start = rowptr[node];
    const int end   = rowptr[node + 1];
    float2 acc = make_float2(0.f, 0.f);

    for (int j = start; j < end; j++) {
        int s = csrc[j];
        float ws = dis[s];
        float2 p = __half22float2(h[(size_t)s * 32 + lane]);
        acc.x += ws * p.x;
        acc.y += ws * p.y;
    }

    float dn = dis[node];
    float2 bv = ((const float2*)bias)[lane];
    float2 r;
    r.x = dn * acc.x + bv.x;
    r.y = dn * acc.y + bv.y;
    ((float2*)(out + (size_t)node * 64))[lane] = r;
}

// ---------------- launch ----------------------------------------------------------
extern "C" void kernel_launch(void* const* d_in, const int* in_sizes, int n_in,
                              void* d_out, int out_size) {
    const float* x   = (const float*)d_in[0];
    const int*   ei  = (const int*)d_in[1];   // [2, E] int32
    const float* W1  = (const float*)d_in[2];
    const float* b1  = (const float*)d_in[3];
    const float* W2  = (const float*)d_in[4];
    const float* b2  = (const float*)d_in[5];
    float*       out = (float*)d_out;

    const int* src = ei;
    const int* dst = ei + N_EDGES;

    int*      deg;      cudaGetSymbolAddress((void**)&deg,      g_deg);
    int*      rowptr;   cudaGetSymbolAddress((void**)&rowptr,   g_rowptr);
    int*      blocksum; cudaGetSymbolAddress((void**)&blocksum, g_blocksum);
    int*      epos;     cudaGetSymbolAddress((void**)&epos,     g_epos);
    int*      csrc;     cudaGetSymbolAddress((void**)&csrc,     g_csrc);
    float*    dis;      cudaGetSymbolAddress((void**)&dis,      g_dis);
    __half2*  h1h;      cudaGetSymbolAddress((void**)&h1h,      g_h1h);
    __half2*  agg1h;    cudaGetSymbolAddress((void**)&agg1h,    g_agg1h);
    __half2*  h2h;      cudaGetSymbolAddress((void**)&h2h,      g_h2h);
    __half2*  w1t;      cudaGetSymbolAddress((void**)&w1t,      g_w1t);
    __half2*  w2t;      cudaGetSymbolAddress((void**)&w2t,      g_w2t);

    // smem: GEMM1 = B(128*272) + 2*A(128*272) = 104448; GEMM2 = 64*272 + 2*128*144 = 54272
    constexpr int SMEM_G1 = 128 * 272 + 2 * 128 * 272;   // 104448
    constexpr int SMEM_G2 = 64 * 272 + 2 * 128 * 144;    //  54272
    cudaFuncSetAttribute(gemm1_kernel, cudaFuncAttributeMaxDynamicSharedMemorySize, SMEM_G1);
    cudaFuncSetAttribute(gemm2_kernel, cudaFuncAttributeMaxDynamicSharedMemorySize, SMEM_G2);

    // ncu profiles the 4th kernel launch -> keep gemm1 there.
    zero_kernel<<<(N_NODES + 255) / 256, 256>>>(deg);                               // 1
    splitW1_kernel<<<(128 * 64 + 255) / 256, 256>>>(W1, w1t);                       // 2
    deg_kernel<<<(N_EDGES + 255) / 256, 256>>>(dst, deg, epos);                     // 3
    gemm1_kernel<<<GEMM_GRID, 256, SMEM_G1>>>(x, w1t, h1h, N_NODES);                // 4
    transW2_kernel<<<(64 * 64 + 255) / 256, 256>>>(W2, w2t);                        // 5
    scan_pass1<<<SCAN_BLOCKS, SCAN_TPB>>>(deg, blocksum);                           // 6
    scan_pass2<<<1, 256>>>(blocksum, rowptr);                                       // 7
    scan_pass3<<<SCAN_BLOCKS, SCAN_TPB>>>(deg, blocksum, rowptr, dis);              // 8
    fill_kernel<<<(N_EDGES + 255) / 256, 256>>>(src, dst, rowptr, epos, csrc);      // 9
    gather128_kernel<<<(N_NODES + 7) / 8, 256>>>(rowptr, csrc, dis, h1h, b1, agg1h); // 10
    gemm2_kernel<<<GEMM_GRID, 256, SMEM_G2>>>(agg1h, w2t, h2h, N_NODES);            // 11
    gather64_kernel<<<(N_NODES + 7) / 8, 256>>>(rowptr, csrc, dis, h2h, b2, out);   // 12
}

// round 16
// speedup vs baseline: 1.6948x; 1.0640x over previous
#include <cuda_runtime.h>
#include <cuda_fp16.h>
#include <cstdint>

#define N_NODES 100000
#define N_EDGES 1600000
#define IN_DIM 128
#define HID_DIM 128
#define OUT_DIM 64

#define SCAN_TPB 512
#define SCAN_BLOCKS ((N_NODES + SCAN_TPB - 1) / SCAN_TPB)   // 196
#define GEMM_GRID 304
#define NTILES ((N_NODES + 127) / 128)                      // 782

// ---------------- device scratch ------------------------------------------------
__device__ int      g_deg[N_NODES];
__device__ int      g_rowptr[N_NODES + 1];
__device__ int      g_blocksum[SCAN_BLOCKS];
__device__ int      g_epos[N_EDGES];
__device__ int      g_csrc[N_EDGES];
__device__ __half2  g_h1h[(size_t)N_NODES * HID_DIM / 2];   // dis[s] * (x @ W1), fp16
__device__ __half2  g_agg1h[(size_t)N_NODES * HID_DIM / 2]; // relu(A_hat h1 + b1), fp16
__device__ __half2  g_h2h[(size_t)N_NODES * OUT_DIM / 2];   // dis[s] * (agg1 @ W2), fp16
// W1^T fp16, interleaved-pair layout (matches fp32-ldsm A slots): [n][64 half2 words]
__device__ __half2  g_w1t[HID_DIM * 64];
// W2^T fp16, natural layout: [n][128 fp16] (contiguous k)
__device__ __half2  g_w2t[OUT_DIM * 64];

// ---------------- helpers ----------------------------------------------------------
__device__ __forceinline__ uint32_t smem_u32(const void* p) {
    uint32_t a;
    asm("{ .reg .u64 t; cvta.to.shared.u64 t, %1; cvt.u32.u64 %0, t; }" : "=r"(a) : "l"(p));
    return a;
}
__device__ __forceinline__ void mma_f16(float* d, const uint32_t* a,
                                        uint32_t b0, uint32_t b1) {
    asm volatile(
        "mma.sync.aligned.m16n8k16.row.col.f32.f16.f16.f32 "
        "{%0,%1,%2,%3}, {%4,%5,%6,%7}, {%8,%9}, {%0,%1,%2,%3};"
        : "+f"(d[0]), "+f"(d[1]), "+f"(d[2]), "+f"(d[3])
        : "r"(a[0]), "r"(a[1]), "r"(a[2]), "r"(a[3]), "r"(b0), "r"(b1));
}
__device__ __forceinline__ void ldsm_x4(uint32_t& r0, uint32_t& r1, uint32_t& r2, uint32_t& r3,
                                        uint32_t addr) {
    asm volatile("ldmatrix.sync.aligned.m8n8.x4.shared.b16 {%0,%1,%2,%3}, [%4];"
                 : "=r"(r0), "=r"(r1), "=r"(r2), "=r"(r3) : "r"(addr));
}
__device__ __forceinline__ void cp_async16(uint32_t dst, const void* src, int src_bytes) {
    asm volatile("cp.async.cg.shared.global [%0], [%1], 16, %2;"
                 :: "r"(dst), "l"(src), "r"(src_bytes) : "memory");
}
__device__ __forceinline__ void cp_commit() {
    asm volatile("cp.async.commit_group;" ::: "memory");
}
template<int NMAX>
__device__ __forceinline__ void cp_wait() {
    asm volatile("cp.async.wait_group %0;" :: "n"(NMAX) : "memory");
}
__device__ __forceinline__ uint32_t pack_h2(uint32_t w0, uint32_t w1) {
    __half2 h = __floats2half2_rn(__uint_as_float(w0), __uint_as_float(w1));
    return *(uint32_t*)&h;
}
__device__ __forceinline__ float deg_rsqrt(int v) {
    return (v > 0) ? rsqrtf((float)v) : 0.0f;
}

// ---------------- zero + degree (+edge position) -------------------------------------
__global__ void zero_kernel(int* __restrict__ deg) {
    int i = blockIdx.x * blockDim.x + threadIdx.x;
    if (i < N_NODES) deg[i] = 0;
}
__global__ void deg_kernel(const int* __restrict__ dst, int* __restrict__ deg,
                           int* __restrict__ epos) {
    int i = blockIdx.x * blockDim.x + threadIdx.x;
    if (i < N_EDGES) epos[i] = atomicAdd(&deg[dst[i]], 1);
}

// ---------------- 3-pass exclusive scan -> rowptr ------------------------------------
__global__ void scan_pass1(const int* __restrict__ deg, int* __restrict__ blocksum) {
    __shared__ int warpsum[SCAN_TPB / 32];
    int idx = blockIdx.x * SCAN_TPB + threadIdx.x;
    int v = (idx < N_NODES) ? deg[idx] : 0;
    for (int o = 16; o > 0; o >>= 1) v += __shfl_down_sync(0xffffffff, v, o);
    if ((threadIdx.x & 31) == 0) warpsum[threadIdx.x >> 5] = v;
    __syncthreads();
    if (threadIdx.x < SCAN_TPB / 32) {
        int s = warpsum[threadIdx.x];
        for (int o = 8; o > 0; o >>= 1) s += __shfl_down_sync(0xffff, s, o);
        if (threadIdx.x == 0) blocksum[blockIdx.x] = s;
    }
}
__global__ void scan_pass2(int* __restrict__ blocksum, int* __restrict__ rowptr) {
    __shared__ int ws[8];
    int lane = threadIdx.x & 31;
    int wid  = threadIdx.x >> 5;
    int v = (threadIdx.x < SCAN_BLOCKS) ? blocksum[threadIdx.x] : 0;
    int sc = v;
    for (int o = 1; o < 32; o <<= 1) {
        int t = __shfl_up_sync(0xffffffff, sc, o);
        if (lane >= o) sc += t;
    }
    if (lane == 31) ws[wid] = sc;
    __syncthreads();
    if (wid == 0 && lane < 8) {
        int s = ws[lane], ss = s;
        for (int o = 1; o < 8; o <<= 1) {
            int t = __shfl_up_sync(0xff, ss, o);
            if (lane >= o) ss += t;
        }
        ws[lane] = ss - s;
    }
    __syncthreads();
    if (threadIdx.x < SCAN_BLOCKS) blocksum[threadIdx.x] = ws[wid] + sc - v;
    if (threadIdx.x == 0) rowptr[N_NODES] = N_EDGES;
}
__global__ void scan_pass3(const int* __restrict__ deg, const int* __restrict__ blocksum,
                           int* __restrict__ rowptr) {
    __shared__ int warpsum[SCAN_TPB / 32];
    int idx = blockIdx.x * SCAN_TPB + threadIdx.x;
    int lane = threadIdx.x & 31;
    int wid  = threadIdx.x >> 5;
    int v = (idx < N_NODES) ? deg[idx] : 0;
    int sc = v;
    for (int o = 1; o < 32; o <<= 1) {
        int t = __shfl_up_sync(0xffffffff, sc, o);
        if (lane >= o) sc += t;
    }
    if (lane == 31) warpsum[wid] = sc;
    __syncthreads();
    if (wid == 0 && lane < SCAN_TPB / 32) {
        int s = warpsum[lane];
        int ss = s;
        for (int o = 1; o < SCAN_TPB / 32; o <<= 1) {
            int t = __shfl_up_sync(0xffff, ss, o);
            if (lane >= o) ss += t;
        }
        warpsum[lane] = ss - s;
    }
    __syncthreads();
    if (idx < N_NODES)
        rowptr[idx] = blocksum[blockIdx.x] + warpsum[wid] + (sc - v);
}

// ---------------- CSR fill (atomic-free) ----------------------------------------------
__global__ void fill_kernel(const int* __restrict__ src, const int* __restrict__ dst,
                            const int* __restrict__ rowptr, const int* __restrict__ epos,
                            int* __restrict__ csrc) {
    int e = blockIdx.x * blockDim.x + threadIdx.x;
    if (e < N_EDGES) {
        csrc[rowptr[dst[e]] + epos[e]] = src[e];
    }
}

// ---------------- weight prep: W1 interleaved-pair + W2 natural, one launch ----------
__global__ void prepW_kernel(const float* __restrict__ W1, const float* __restrict__ W2,
                             __half2* __restrict__ WT1, __half2* __restrict__ WT2) {
    int idx = blockIdx.x * blockDim.x + threadIdx.x;
    if (idx < 128 * 64) {
        // W1 [128,128] -> [n][64 half2]: block b, word w, t=w&3:
        //   k0 = 16b + ((w>>2)<<3) + t, pair {k0, k0+4}
        int n = idx >> 6, word = idx & 63;
        int b = word >> 3, w = word & 7;
        int t = w & 3;
        int k0 = b * 16 + ((w >> 2) << 3) + t;
        WT1[n * 64 + word] = __floats2half2_rn(W1[k0 * 128 + n], W1[(k0 + 4) * 128 + n]);
    } else if (idx < 128 * 64 + 64 * 64) {
        // W2 [128,64] -> [n][64 half2] natural: word w = {W2[2w][n], W2[2w+1][n]}
        int j = idx - 128 * 64;
        int n = j >> 6, word = j & 63;
        WT2[n * 64 + word] = __floats2half2_rn(W2[(2 * word) * 64 + n],
                                               W2[(2 * word + 1) * 64 + n]);
    }
}

// ---------------- GEMM1 (pure fp16): h1h = dis[row] * (fp16(x) @ W1) -----------------
// Persistent, grid=GEMM_GRID. B (fp16, full K, interleaved pairs) smem-resident;
// A (fp32) streamed per 128-row tile in two K=64 chunks, double-buffered cp.async.
// Epilogue scales each output row by rsqrt(deg[row]).
__global__ void __launch_bounds__(256, 2) gemm1_kernel(const float* __restrict__ A,
                                                       const __half2* __restrict__ BT,
                                                       const int* __restrict__ deg,
                                                       __half2* __restrict__ Ch, int M) {
    constexpr int N    = 128;
    constexpr int STRB = 272;       // B row stride bytes (128 fp16 + 8 pad)
    constexpr int STRA = 272;       // A chunk row stride bytes (64 fp32 + 4 pad)
    constexpr int NT2  = N / 16;    // 8

    extern __shared__ char smem[];
    const uint32_t sb   = smem_u32(smem);
    const uint32_t b_b  = sb;
    const uint32_t a_b0 = b_b + (uint32_t)(N * STRB);
    const uint32_t a_b1 = a_b0 + (uint32_t)(128 * STRA);

    const int tid  = threadIdx.x;
    const int w    = tid >> 5;
    const int lane = tid & 31;
    const int g    = lane >> 2;
    const int t    = lane & 3;
    const int r0   = w * 16;
    const int rowi = lane & 7;
    const int sel  = lane >> 3;

#pragma unroll
    for (int i = 0; i < N * 16 / 256; i++) {
        int idx = tid + i * 256;
        int r = idx >> 4, c = idx & 15;
        cp_async16(b_b + (uint32_t)(r * STRB + c * 16), BT + (size_t)r * 64 + c * 4, 16);
    }

#define STAGE_A1(bufu32, m0_, chunk_)                                                       \
    _Pragma("unroll")                                                                       \
    for (int i = 0; i < 8; i++) {                                                           \
        int idx = tid + i * 256;                                                            \
        int r = idx >> 4, c = idx & 15;                                                     \
        int gm = (m0_) + r;                                                                 \
        const float* srcp = A + (size_t)(gm < M ? gm : M - 1) * 128 + (chunk_) * 64 + c * 4;\
        cp_async16((bufu32) + (uint32_t)(r * STRA + c * 16), srcp, (gm < M) ? 16 : 0);      \
    }

    int tile = blockIdx.x;
    STAGE_A1(a_b0, tile * 128, 0);
    cp_commit();

    const uint32_t a_off =
        (uint32_t)((r0 + (sel & 1) * 8 + rowi) * STRA + (sel >> 1) * 16);
    const uint32_t b_off =
        b_b + (uint32_t)((rowi + (sel >> 1) * 8) * STRB + (sel & 1) * 16);

    float acc[2 * NT2][4];
#pragma unroll
    for (int nt = 0; nt < 2 * NT2; nt++)
#pragma unroll
        for (int j = 0; j < 4; j++) acc[nt][j] = 0.0f;

    int cur = 0;
    for (; tile < NTILES; tile += GEMM_GRID) {
#pragma unroll
        for (int chunk = 0; chunk < 2; chunk++) {
            const int   nTile  = (chunk == 0) ? tile : tile + GEMM_GRID;
            const int   nChunk = chunk ^ 1;
            const bool  have   = (nTile < NTILES);
            const uint32_t abuf_next = cur ? a_b0 : a_b1;
            if (have) { STAGE_A1(abuf_next, nTile * 128, nChunk); cp_commit(); }
            if (have) cp_wait<1>(); else cp_wait<0>();
            __syncthreads();

            const uint32_t abuf = cur ? a_b1 : a_b0;
#pragma unroll 1
            for (int ks = 0; ks < 4; ks++) {
                uint32_t ar[8], ah[4];
                ldsm_x4(ar[0], ar[1], ar[2], ar[3], abuf + a_off + (uint32_t)(ks * 64));
                ldsm_x4(ar[4], ar[5], ar[6], ar[7], abuf + a_off + (uint32_t)(ks * 64 + 32));
                ah[0] = pack_h2(ar[0], ar[2]);
                ah[1] = pack_h2(ar[1], ar[3]);
                ah[2] = pack_h2(ar[4], ar[6]);
                ah[3] = pack_h2(ar[5], ar[7]);

                const uint32_t koff = (uint32_t)((chunk * 4 + ks) * 32);
#pragma unroll
                for (int nt2 = 0; nt2 < NT2; nt2++) {
                    uint32_t b0, b1, b2, b3;
                    ldsm_x4(b0, b1, b2, b3, b_off + (uint32_t)(nt2 * 16 * STRB) + koff);
                    mma_f16(acc[nt2 * 2],     ah, b0, b1);
                    mma_f16(acc[nt2 * 2 + 1], ah, b2, b3);
                }
            }
            __syncthreads();
            cur ^= 1;
        }
        // ---- epilogue: scale rows by rsqrt(deg), fp16 store
        const int gr0 = tile * 128 + r0 + g;
        float d0 = (gr0 < M)     ? deg_rsqrt(deg[gr0])     : 0.0f;
        float d1 = (gr0 + 8 < M) ? deg_rsqrt(deg[gr0 + 8]) : 0.0f;
#pragma unroll
        for (int nt = 0; nt < 2 * NT2; nt++) {
            int cc = nt * 8 + 2 * t;
            if (gr0 < M)
                Ch[(size_t)gr0 * 64 + cc / 2] =
                    __floats2half2_rn(d0 * acc[nt][0], d0 * acc[nt][1]);
            if (gr0 + 8 < M)
                Ch[(size_t)(gr0 + 8) * 64 + cc / 2] =
                    __floats2half2_rn(d1 * acc[nt][2], d1 * acc[nt][3]);
#pragma unroll
            for (int j = 0; j < 4; j++) acc[nt][j] = 0.0f;
        }
    }
#undef STAGE_A1
}

// ---------------- GEMM2 (pure fp16): h2h = dis[row] * (agg1h @ W2) -------------------
__global__ void __launch_bounds__(256, 2) gemm2_kernel(const __half2* __restrict__ A,
                                                       const __half2* __restrict__ BT,
                                                       const int* __restrict__ deg,
                                                       __half2* __restrict__ Ch, int M) {
    constexpr int N    = 64;
    constexpr int STRB = 272;       // B row stride bytes
    constexpr int STRA = 144;       // A chunk row stride bytes (64 fp16 + 8 pad)
    constexpr int NT2  = N / 16;    // 4

    extern __shared__ char smem[];
    const uint32_t sb   = smem_u32(smem);
    const uint32_t b_b  = sb;
    const uint32_t a_b0 = b_b + (uint32_t)(N * STRB);
    const uint32_t a_b1 = a_b0 + (uint32_t)(128 * STRA);

    const int tid  = threadIdx.x;
    const int w    = tid >> 5;
    const int lane = tid & 31;
    const int g    = lane >> 2;
    const int t    = lane & 3;
    const int r0   = w * 16;
    const int rowi = lane & 7;
    const int sel  = lane >> 3;

#pragma unroll
    for (int i = 0; i < N * 16 / 256; i++) {
        int idx = tid + i * 256;
        int r = idx >> 4, c = idx & 15;
        cp_async16(b_b + (uint32_t)(r * STRB + c * 16), BT + (size_t)r * 64 + c * 4, 16);
    }

#define STAGE_A2(bufu32, m0_, chunk_)                                                       \
    _Pragma("unroll")                                                                       \
    for (int i = 0; i < 4; i++) {                                                           \
        int idx = tid + i * 256;                                                            \
        int r = idx >> 3, c = idx & 7;                                                      \
        int gm = (m0_) + r;                                                                 \
        const __half2* srcp = A + (size_t)(gm < M ? gm : M - 1) * 64 + (chunk_) * 32 + c * 4;\
        cp_async16((bufu32) + (uint32_t)(r * STRA + c * 16), srcp, (gm < M) ? 16 : 0);      \
    }

    int tile = blockIdx.x;
    STAGE_A2(a_b0, tile * 128, 0);
    cp_commit();

    const uint32_t a_off =
        (uint32_t)((r0 + (sel & 1) * 8 + rowi) * STRA + (sel >> 1) * 16);
    const uint32_t b_off =
        b_b + (uint32_t)((rowi + (sel >> 1) * 8) * STRB + (sel & 1) * 16);

    float acc[2 * NT2][4];
#pragma unroll
    for (int nt = 0; nt < 2 * NT2; nt++)
#pragma unroll
        for (int j = 0; j < 4; j++) acc[nt][j] = 0.0f;

    int cur = 0;
    for (; tile < NTILES; tile += GEMM_GRID) {
#pragma unroll
        for (int chunk = 0; chunk < 2; chunk++) {
            const int   nTile  = (chunk == 0) ? tile : tile + GEMM_GRID;
            const int   nChunk = chunk ^ 1;
            const bool  have   = (nTile < NTILES);
            const uint32_t abuf_next = cur ? a_b0 : a_b1;
            if (have) { STAGE_A2(abuf_next, nTile * 128, nChunk); cp_commit(); }
            if (have) cp_wait<1>(); else cp_wait<0>();
            __syncthreads();

            const uint32_t abuf = cur ? a_b1 : a_b0;
#pragma unroll 1
            for (int ks = 0; ks < 4; ks++) {
                uint32_t a[4];
                ldsm_x4(a[0], a[1], a[2], a[3], abuf + a_off + (uint32_t)(ks * 32));
                const uint32_t koff = (uint32_t)((chunk * 4 + ks) * 32);
#pragma unroll
                for (int nt2 = 0; nt2 < NT2; nt2++) {
                    uint32_t b0, b1, b2, b3;
                    ldsm_x4(b0, b1, b2, b3, b_off + (uint32_t)(nt2 * 16 * STRB) + koff);
                    mma_f16(acc[nt2 * 2],     a, b0, b1);
                    mma_f16(acc[nt2 * 2 + 1], a, b2, b3);
                }
            }
            __syncthreads();
            cur ^= 1;
        }
        const int gr0 = tile * 128 + r0 + g;
        float d0 = (gr0 < M)     ? deg_rsqrt(deg[gr0])     : 0.0f;
        float d1 = (gr0 + 8 < M) ? deg_rsqrt(deg[gr0 + 8]) : 0.0f;
#pragma unroll
        for (int nt = 0; nt < 2 * NT2; nt++) {
            int cc = nt * 8 + 2 * t;
            if (gr0 < M)
                Ch[(size_t)gr0 * 32 + cc / 2] =
                    __floats2half2_rn(d0 * acc[nt][0], d0 * acc[nt][1]);
            if (gr0 + 8 < M)
                Ch[(size_t)(gr0 + 8) * 32 + cc / 2] =
                    __floats2half2_rn(d1 * acc[nt][2], d1 * acc[nt][3]);
#pragma unroll
            for (int j = 0; j < 4; j++) acc[nt][j] = 0.0f;
        }
    }
#undef STAGE_A2
}

// ---------------- CSR gather: pure row-sum (rows pre-scaled by dis[s]) ----------------
__global__ void gather128_kernel(const int* __restrict__ rowptr,
                                 const int* __restrict__ csrc,
                                 const int* __restrict__ deg,
                                 const __half2* __restrict__ h,
                                 const float* __restrict__ bias,
                                 __half2* __restrict__ outh) {
    const int lane = threadIdx.x & 31;
    const int node = blockIdx.x * (blockDim.x >> 5) + (threadIdx.x >> 5);
    if (node >= N_NODES) return;

    const int start = rowptr[node];
    const int end   = rowptr[node + 1];
    float4 acc = make_float4(0.f, 0.f, 0.f, 0.f);

    int j = start;
    for (; j + 2 <= end; j += 2) {
        int s0 = csrc[j], s1 = csrc[j + 1];
        uint2 r0 = ((const uint2*)(h + (size_t)s0 * 64))[lane];
        uint2 r1 = ((const uint2*)(h + (size_t)s1 * 64))[lane];
        float2 a0 = __half22float2(*(const __half2*)&r0.x);
        float2 b0 = __half22float2(*(const __half2*)&r0.y);
        float2 a1 = __half22float2(*(const __half2*)&r1.x);
        float2 b1 = __half22float2(*(const __half2*)&r1.y);
        acc.x += a0.x + a1.x;
        acc.y += a0.y + a1.y;
        acc.z += b0.x + b1.x;
        acc.w += b0.y + b1.y;
    }
    if (j < end) {
        int s0 = csrc[j];
        uint2 r0 = ((const uint2*)(h + (size_t)s0 * 64))[lane];
        float2 a0 = __half22float2(*(const __half2*)&r0.x);
        float2 b0 = __half22float2(*(const __half2*)&r0.y);
        acc.x += a0.x;
        acc.y += a0.y;
        acc.z += b0.x;
        acc.w += b0.y;
    }

    float dn = deg_rsqrt(deg[node]);
    float4 bv = ((const float4*)bias)[lane];
    float rx = fmaxf(dn * acc.x + bv.x, 0.f);
    float ry = fmaxf(dn * acc.y + bv.y, 0.f);
    float rz = fmaxf(dn * acc.z + bv.z, 0.f);
    float rw = fmaxf(dn * acc.w + bv.w, 0.f);
    __half2 o0 = __floats2half2_rn(rx, ry);
    __half2 o1 = __floats2half2_rn(rz, rw);
    uint2 o;
    o.x = *(uint32_t*)&o0;
    o.y = *(uint32_t*)&o1;
    ((uint2*)(outh + (size_t)node * 64))[lane] = o;
}

__global__ void gather64_kernel(const int* __restrict__ rowptr,
                                const int* __restrict__ csrc,
                                const int* __restrict__ deg,
                                const __half2* __restrict__ h,
                                const float* __restrict__ bias,
                                float* __restrict__ out) {
    const int lane = threadIdx.x & 31;
    const int node = blockIdx.x * (blockDim.x >> 5) + (threadIdx.x >> 5);
    if (node >= N_NODES) return;

    const int start = rowptr[node];
    const int end   = rowptr[node + 1];
    float2 acc = make_float2(0.f, 0.f);

    int j = start;
    for (; j + 2 <= end; j += 2) {
        int s0 = csrc[j], s1 = csrc[j + 1];
        float2 p0 = __half22float2(h[(size_t)s0 * 32 + lane]);
        float2 p1 = __half22float2(h[(size_t)s1 * 32 + lane]);
        acc.x += p0.x + p1.x;
        acc.y += p0.y + p1.y;
    }
    if (j < end) {
        int s0 = csrc[j];
        float2 p0 = __half22float2(h[(size_t)s0 * 32 + lane]);
        acc.x += p0.x;
        acc.y += p0.y;
    }

    float dn = deg_rsqrt(deg[node]);
    float2 bv = ((const float2*)bias)[lane];
    float2 r;
    r.x = dn * acc.x + bv.x;
    r.y = dn * acc.y + bv.y;
    ((float2*)(out + (size_t)node * 64))[lane] = r;
}

// ---------------- launch ----------------------------------------------------------
extern "C" void kernel_launch(void* const* d_in, const int* in_sizes, int n_in,
                              void* d_out, int out_size) {
    const float* x   = (const float*)d_in[0];
    const int*   ei  = (const int*)d_in[1];   // [2, E] int32
    const float* W1  = (const float*)d_in[2];
    const float* b1  = (const float*)d_in[3];
    const float* W2  = (const float*)d_in[4];
    const float* b2  = (const float*)d_in[5];
    float*       out = (float*)d_out;

    const int* src = ei;
    const int* dst = ei + N_EDGES;

    int*      deg;      cudaGetSymbolAddress((void**)&deg,      g_deg);
    int*      rowptr;   cudaGetSymbolAddress((void**)&rowptr,   g_rowptr);
    int*      blocksum; cudaGetSymbolAddress((void**)&blocksum, g_blocksum);
    int*      epos;     cudaGetSymbolAddress((void**)&epos,     g_epos);
    int*      csrc;     cudaGetSymbolAddress((void**)&csrc,     g_csrc);
    __half2*  h1h;      cudaGetSymbolAddress((void**)&h1h,      g_h1h);
    __half2*  agg1h;    cudaGetSymbolAddress((void**)&agg1h,    g_agg1h);
    __half2*  h2h;      cudaGetSymbolAddress((void**)&h2h,      g_h2h);
    __half2*  w1t;      cudaGetSymbolAddress((void**)&w1t,      g_w1t);
    __half2*  w2t;      cudaGetSymbolAddress((void**)&w2t,      g_w2t);

    constexpr int SMEM_G1 = 128 * 272 + 2 * 128 * 272;   // 104448
    constexpr int SMEM_G2 = 64 * 272 + 2 * 128 * 144;    //  54272
    cudaFuncSetAttribute(gemm1_kernel, cudaFuncAttributeMaxDynamicSharedMemorySize, SMEM_G1);
    cudaFuncSetAttribute(gemm2_kernel, cudaFuncAttributeMaxDynamicSharedMemorySize, SMEM_G2);

    // ncu profiles the 4th kernel launch -> keep gemm1 there.
    zero_kernel<<<(N_NODES + 255) / 256, 256>>>(deg);                               // 1
    prepW_kernel<<<(128 * 64 + 64 * 64 + 255) / 256, 256>>>(W1, W2, w1t, w2t);      // 2
    deg_kernel<<<(N_EDGES + 255) / 256, 256>>>(dst, deg, epos);                     // 3
    gemm1_kernel<<<GEMM_GRID, 256, SMEM_G1>>>(x, w1t, deg, h1h, N_NODES);           // 4
    scan_pass1<<<SCAN_BLOCKS, SCAN_TPB>>>(deg, blocksum);                           // 5
    scan_pass2<<<1, 256>>>(blocksum, rowptr);                                       // 6
    scan_pass3<<<SCAN_BLOCKS, SCAN_TPB>>>(deg, blocksum, rowptr);                   // 7
    fill_kernel<<<(N_EDGES + 255) / 256, 256>>>(src, dst, rowptr, epos, csrc);      // 8
    gather128_kernel<<<(N_NODES + 7) / 8, 256>>>(rowptr, csrc, deg, h1h, b1, agg1h); // 9
    gemm2_kernel<<<GEMM_GRID, 256, SMEM_G2>>>(agg1h, w2t, deg, h2h, N_NODES);       // 10
    gather64_kernel<<<(N_NODES + 7) / 8, 256>>>(rowptr, csrc, deg, h2h, b2, out);   // 11
}

// round 17
// speedup vs baseline: 1.6976x; 1.0017x over previous
#include <cuda_runtime.h>
#include <cuda_fp16.h>
#include <cstdint>

#define N_NODES 100000
#define N_EDGES 1600000
#define IN_DIM 128
#define HID_DIM 128
#define OUT_DIM 64

#define SCAN_TPB 512
#define SCAN_BLOCKS ((N_NODES + SCAN_TPB - 1) / SCAN_TPB)   // 196
#define GEMM_GRID 304
#define NTILES ((N_NODES + 127) / 128)                      // 782

// ---------------- device scratch ------------------------------------------------
__device__ int      g_deg[N_NODES];
__device__ int      g_rowptr[N_NODES + 1];
__device__ int      g_blocksum[SCAN_BLOCKS];
__device__ int      g_epos[N_EDGES];
__device__ int      g_csrc[N_EDGES];
__device__ __half2  g_h1h[(size_t)N_NODES * HID_DIM / 2];   // dis[s] * (x @ W1), fp16
__device__ __half2  g_agg1h[(size_t)N_NODES * HID_DIM / 2]; // relu(A_hat h1 + b1), fp16
__device__ __half2  g_h2h[(size_t)N_NODES * OUT_DIM / 2];   // dis[s] * (agg1 @ W2), fp16
__device__ __half2  g_w1t[HID_DIM * 64];   // W1^T fp16 interleaved-pair
__device__ __half2  g_w2t[OUT_DIM * 64];   // W2^T fp16 natural

// ---------------- helpers ----------------------------------------------------------
__device__ __forceinline__ uint32_t smem_u32(const void* p) {
    uint32_t a;
    asm("{ .reg .u64 t; cvta.to.shared.u64 t, %1; cvt.u32.u64 %0, t; }" : "=r"(a) : "l"(p));
    return a;
}
__device__ __forceinline__ void mma_f16(float* d, const uint32_t* a,
                                        uint32_t b0, uint32_t b1) {
    asm volatile(
        "mma.sync.aligned.m16n8k16.row.col.f32.f16.f16.f32 "
        "{%0,%1,%2,%3}, {%4,%5,%6,%7}, {%8,%9}, {%0,%1,%2,%3};"
        : "+f"(d[0]), "+f"(d[1]), "+f"(d[2]), "+f"(d[3])
        : "r"(a[0]), "r"(a[1]), "r"(a[2]), "r"(a[3]), "r"(b0), "r"(b1));
}
__device__ __forceinline__ void ldsm_x4(uint32_t& r0, uint32_t& r1, uint32_t& r2, uint32_t& r3,
                                        uint32_t addr) {
    asm volatile("ldmatrix.sync.aligned.m8n8.x4.shared.b16 {%0,%1,%2,%3}, [%4];"
                 : "=r"(r0), "=r"(r1), "=r"(r2), "=r"(r3) : "r"(addr));
}
__device__ __forceinline__ void cp_async16(uint32_t dst, const void* src, int src_bytes) {
    asm volatile("cp.async.cg.shared.global [%0], [%1], 16, %2;"
                 :: "r"(dst), "l"(src), "r"(src_bytes) : "memory");
}
__device__ __forceinline__ void cp_commit() {
    asm volatile("cp.async.commit_group;" ::: "memory");
}
template<int NMAX>
__device__ __forceinline__ void cp_wait() {
    asm volatile("cp.async.wait_group %0;" :: "n"(NMAX) : "memory");
}
__device__ __forceinline__ uint32_t pack_h2(uint32_t w0, uint32_t w1) {
    __half2 h = __floats2half2_rn(__uint_as_float(w0), __uint_as_float(w1));
    return *(uint32_t*)&h;
}
__device__ __forceinline__ float deg_rsqrt(int v) {
    return (v > 0) ? rsqrtf((float)v) : 0.0f;
}

// ---------------- prep: zero deg + both weight transposes (one launch) ---------------
__global__ void prep_kernel(const float* __restrict__ W1, const float* __restrict__ W2,
                            __half2* __restrict__ WT1, __half2* __restrict__ WT2,
                            int* __restrict__ deg) {
    int idx = blockIdx.x * blockDim.x + threadIdx.x;
    if (idx < N_NODES) deg[idx] = 0;
    if (idx < 128 * 64) {
        // W1 [128,128] -> [n][64 half2]: pair {k0, k0+4}, k0 = 16b + ((w>>2)<<3) + t
        int n = idx >> 6, word = idx & 63;
        int b = word >> 3, w = word & 7;
        int t = w & 3;
        int k0 = b * 16 + ((w >> 2) << 3) + t;
        WT1[n * 64 + word] = __floats2half2_rn(W1[k0 * 128 + n], W1[(k0 + 4) * 128 + n]);
    } else if (idx < 128 * 64 + 64 * 64) {
        // W2 [128,64] -> [n][64 half2] natural: word w = {W2[2w][n], W2[2w+1][n]}
        int j = idx - 128 * 64;
        int n = j >> 6, word = j & 63;
        WT2[n * 64 + word] = __floats2half2_rn(W2[(2 * word) * 64 + n],
                                               W2[(2 * word + 1) * 64 + n]);
    }
}

// ---------------- degree + edge position (x4 vectorized) ------------------------------
__global__ void deg_kernel(const int4* __restrict__ dst4, int* __restrict__ deg,
                           int4* __restrict__ epos4) {
    int i = blockIdx.x * blockDim.x + threadIdx.x;
    if (i < N_EDGES / 4) {
        int4 d = dst4[i];
        int4 p;
        p.x = atomicAdd(&deg[d.x], 1);
        p.y = atomicAdd(&deg[d.y], 1);
        p.z = atomicAdd(&deg[d.z], 1);
        p.w = atomicAdd(&deg[d.w], 1);
        epos4[i] = p;
    }
}

// ---------------- 3-pass exclusive scan -> rowptr ------------------------------------
__global__ void scan_pass1(const int* __restrict__ deg, int* __restrict__ blocksum) {
    __shared__ int warpsum[SCAN_TPB / 32];
    int idx = blockIdx.x * SCAN_TPB + threadIdx.x;
    int v = (idx < N_NODES) ? deg[idx] : 0;
    for (int o = 16; o > 0; o >>= 1) v += __shfl_down_sync(0xffffffff, v, o);
    if ((threadIdx.x & 31) == 0) warpsum[threadIdx.x >> 5] = v;
    __syncthreads();
    if (threadIdx.x < SCAN_TPB / 32) {
        int s = warpsum[threadIdx.x];
        for (int o = 8; o > 0; o >>= 1) s += __shfl_down_sync(0xffff, s, o);
        if (threadIdx.x == 0) blocksum[blockIdx.x] = s;
    }
}
__global__ void scan_pass2(int* __restrict__ blocksum, int* __restrict__ rowptr) {
    __shared__ int ws[8];
    int lane = threadIdx.x & 31;
    int wid  = threadIdx.x >> 5;
    int v = (threadIdx.x < SCAN_BLOCKS) ? blocksum[threadIdx.x] : 0;
    int sc = v;
    for (int o = 1; o < 32; o <<= 1) {
        int t = __shfl_up_sync(0xffffffff, sc, o);
        if (lane >= o) sc += t;
    }
    if (lane == 31) ws[wid] = sc;
    __syncthreads();
    if (wid == 0 && lane < 8) {
        int s = ws[lane], ss = s;
        for (int o = 1; o < 8; o <<= 1) {
            int t = __shfl_up_sync(0xff, ss, o);
            if (lane >= o) ss += t;
        }
        ws[lane] = ss - s;
    }
    __syncthreads();
    if (threadIdx.x < SCAN_BLOCKS) blocksum[threadIdx.x] = ws[wid] + sc - v;
    if (threadIdx.x == 0) rowptr[N_NODES] = N_EDGES;
}
__global__ void scan_pass3(const int* __restrict__ deg, const int* __restrict__ blocksum,
                           int* __restrict__ rowptr) {
    __shared__ int warpsum[SCAN_TPB / 32];
    int idx = blockIdx.x * SCAN_TPB + threadIdx.x;
    int lane = threadIdx.x & 31;
    int wid  = threadIdx.x >> 5;
    int v = (idx < N_NODES) ? deg[idx] : 0;
    int sc = v;
    for (int o = 1; o < 32; o <<= 1) {
        int t = __shfl_up_sync(0xffffffff, sc, o);
        if (lane >= o) sc += t;
    }
    if (lane == 31) warpsum[wid] = sc;
    __syncthreads();
    if (wid == 0 && lane < SCAN_TPB / 32) {
        int s = warpsum[lane];
        int ss = s;
        for (int o = 1; o < SCAN_TPB / 32; o <<= 1) {
            int t = __shfl_up_sync(0xffff, ss, o);
            if (lane >= o) ss += t;
        }
        warpsum[lane] = ss - s;
    }
    __syncthreads();
    if (idx < N_NODES)
        rowptr[idx] = blocksum[blockIdx.x] + warpsum[wid] + (sc - v);
}

// ---------------- CSR fill (atomic-free) ----------------------------------------------
__global__ void fill_kernel(const int* __restrict__ src, const int* __restrict__ dst,
                            const int* __restrict__ rowptr, const int* __restrict__ epos,
                            int* __restrict__ csrc) {
    int e = blockIdx.x * blockDim.x + threadIdx.x;
    if (e < N_EDGES) {
        csrc[rowptr[dst[e]] + epos[e]] = src[e];
    }
}

// ---------------- GEMM1 (pure fp16): h1h = dis[row] * (fp16(x) @ W1) -----------------
// Persistent, grid=GEMM_GRID. B (fp16, full K) smem-resident. A (fp32) streamed per
// 128-row tile in FOUR K=32 chunks through 4 ping-pong buffers, 3 chunks prefetch depth.
__global__ void __launch_bounds__(256, 2) gemm1_kernel(const float* __restrict__ A,
                                                       const __half2* __restrict__ BT,
                                                       const int* __restrict__ deg,
                                                       __half2* __restrict__ Ch, int M) {
    constexpr int N    = 128;
    constexpr int STRB = 272;       // B row stride bytes (128 fp16 + 8 pad)
    constexpr int STRA = 144;       // A chunk row stride bytes (32 fp32 + 4 pad)
    constexpr int ABUF = 128 * STRA;  // 18432 bytes per A buffer
    constexpr int NT2  = N / 16;    // 8

    extern __shared__ char smem[];
    const uint32_t sb   = smem_u32(smem);
    const uint32_t b_b  = sb;
    const uint32_t a_b0 = b_b + (uint32_t)(N * STRB);

    const int tid  = threadIdx.x;
    const int w    = tid >> 5;
    const int lane = tid & 31;
    const int g    = lane >> 2;
    const int t    = lane & 3;
    const int r0   = w * 16;
    const int rowi = lane & 7;
    const int sel  = lane >> 3;

    // ---- B prologue (own commit group)
#pragma unroll
    for (int i = 0; i < N * 16 / 256; i++) {
        int idx = tid + i * 256;
        int r = idx >> 4, c = idx & 15;
        cp_async16(b_b + (uint32_t)(r * STRB + c * 16), BT + (size_t)r * 64 + c * 4, 16);
    }
    cp_commit();

    // A chunk stage: 128 rows x 32 fp32; 1024 16B-pieces / 256 threads = 4 each
#define STAGE_A1(bufu32, m0_, chunk_)                                                       \
    _Pragma("unroll")                                                                       \
    for (int i = 0; i < 4; i++) {                                                           \
        int idx = tid + i * 256;                                                            \
        int r = idx >> 3, c = idx & 7;                                                      \
        int gm = (m0_) + r;                                                                 \
        const float* srcp = A + (size_t)(gm < M ? gm : M - 1) * 128 + (chunk_) * 32 + c * 4;\
        cp_async16((bufu32) + (uint32_t)(r * STRA + c * 16), srcp, (gm < M) ? 16 : 0);      \
    }
#define STAGE_Q(q_)                                                                         \
    do {                                                                                    \
        int _q = (q_);                                                                      \
        int _tq = blockIdx.x + (_q >> 2) * GEMM_GRID;                                       \
        if (_tq < NTILES) {                                                                 \
            uint32_t _buf = a_b0 + (uint32_t)((_q & 3) * ABUF);                             \
            STAGE_A1(_buf, _tq * 128, (_q & 3));                                            \
        }                                                                                   \
        cp_commit();                                                                        \
    } while (0)

    STAGE_Q(0);
    STAGE_Q(1);
    STAGE_Q(2);

    const uint32_t a_off =
        (uint32_t)((r0 + (sel & 1) * 8 + rowi) * STRA + (sel >> 1) * 16);
    const uint32_t b_off =
        b_b + (uint32_t)((rowi + (sel >> 1) * 8) * STRB + (sel & 1) * 16);

    float acc[2 * NT2][4];
#pragma unroll
    for (int nt = 0; nt < 2 * NT2; nt++)
#pragma unroll
        for (int j = 0; j < 4; j++) acc[nt][j] = 0.0f;

    const int ntiles_cta = (NTILES - blockIdx.x + GEMM_GRID - 1) / GEMM_GRID;
    const int Q = ntiles_cta * 4;

    for (int q = 0; q < Q; q++) {
        STAGE_Q(q + 3);
        cp_wait<3>();
        __syncthreads();

        const uint32_t abuf = a_b0 + (uint32_t)((q & 3) * ABUF);
        const int chk = q & 3;
#pragma unroll
        for (int ks2 = 0; ks2 < 2; ks2++) {
            uint32_t ar[8], ah[4];
            ldsm_x4(ar[0], ar[1], ar[2], ar[3], abuf + a_off + (uint32_t)(ks2 * 64));
            ldsm_x4(ar[4], ar[5], ar[6], ar[7], abuf + a_off + (uint32_t)(ks2 * 64 + 32));
            ah[0] = pack_h2(ar[0], ar[2]);
            ah[1] = pack_h2(ar[1], ar[3]);
            ah[2] = pack_h2(ar[4], ar[6]);
            ah[3] = pack_h2(ar[5], ar[7]);

            const uint32_t koff = (uint32_t)((chk * 2 + ks2) * 32);
#pragma unroll
            for (int nt2 = 0; nt2 < NT2; nt2++) {
                uint32_t b0, b1, b2, b3;
                ldsm_x4(b0, b1, b2, b3, b_off + (uint32_t)(nt2 * 16 * STRB) + koff);
                mma_f16(acc[nt2 * 2],     ah, b0, b1);
                mma_f16(acc[nt2 * 2 + 1], ah, b2, b3);
            }
        }
        __syncthreads();

        if (chk == 3) {
            const int tile = blockIdx.x + (q >> 2) * GEMM_GRID;
            const int gr0 = tile * 128 + r0 + g;
            float d0 = (gr0 < M)     ? deg_rsqrt(deg[gr0])     : 0.0f;
            float d1 = (gr0 + 8 < M) ? deg_rsqrt(deg[gr0 + 8]) : 0.0f;
#pragma unroll
            for (int nt = 0; nt < 2 * NT2; nt++) {
                int cc = nt * 8 + 2 * t;
                if (gr0 < M)
                    Ch[(size_t)gr0 * 64 + cc / 2] =
                        __floats2half2_rn(d0 * acc[nt][0], d0 * acc[nt][1]);
                if (gr0 + 8 < M)
                    Ch[(size_t)(gr0 + 8) * 64 + cc / 2] =
                        __floats2half2_rn(d1 * acc[nt][2], d1 * acc[nt][3]);
#pragma unroll
                for (int j = 0; j < 4; j++) acc[nt][j] = 0.0f;
            }
        }
    }
#undef STAGE_Q
#undef STAGE_A1
}

// ---------------- GEMM2 (pure fp16): h2h = dis[row] * (agg1h @ W2) -------------------
__global__ void __launch_bounds__(256, 2) gemm2_kernel(const __half2* __restrict__ A,
                                                       const __half2* __restrict__ BT,
                                                       const int* __restrict__ deg,
                                                       __half2* __restrict__ Ch, int M) {
    constexpr int N    = 64;
    constexpr int STRB = 272;
    constexpr int STRA = 144;       // A chunk row stride bytes (64 fp16 + 8 pad)
    constexpr int NT2  = N / 16;    // 4

    extern __shared__ char smem[];
    const uint32_t sb   = smem_u32(smem);
    const uint32_t b_b  = sb;
    const uint32_t a_b0 = b_b + (uint32_t)(N * STRB);
    const uint32_t a_b1 = a_b0 + (uint32_t)(128 * STRA);

    const int tid  = threadIdx.x;
    const int w    = tid >> 5;
    const int lane = tid & 31;
    const int g    = lane >> 2;
    const int t    = lane & 3;
    const int r0   = w * 16;
    const int rowi = lane & 7;
    const int sel  = lane >> 3;

#pragma unroll
    for (int i = 0; i < N * 16 / 256; i++) {
        int idx = tid + i * 256;
        int r = idx >> 4, c = idx & 15;
        cp_async16(b_b + (uint32_t)(r * STRB + c * 16), BT + (size_t)r * 64 + c * 4, 16);
    }

#define STAGE_A2(bufu32, m0_, chunk_)                                                       \
    _Pragma("unroll")                                                                       \
    for (int i = 0; i < 4; i++) {                                                           \
        int idx = tid + i * 256;                                                            \
        int r = idx >> 3, c = idx & 7;                                                      \
        int gm = (m0_) + r;                                                                 \
        const __half2* srcp = A + (size_t)(gm < M ? gm : M - 1) * 64 + (chunk_) * 32 + c * 4;\
        cp_async16((bufu32) + (uint32_t)(r * STRA + c * 16), srcp, (gm < M) ? 16 : 0);      \
    }

    int tile = blockIdx.x;
    STAGE_A2(a_b0, tile * 128, 0);
    cp_commit();

    const uint32_t a_off =
        (uint32_t)((r0 + (sel & 1) * 8 + rowi) * STRA + (sel >> 1) * 16);
    const uint32_t b_off =
        b_b + (uint32_t)((rowi + (sel >> 1) * 8) * STRB + (sel & 1) * 16);

    float acc[2 * NT2][4];
#pragma unroll
    for (int nt = 0; nt < 2 * NT2; nt++)
#pragma unroll
        for (int j = 0; j < 4; j++) acc[nt][j] = 0.0f;

    int cur = 0;
    for (; tile < NTILES; tile += GEMM_GRID) {
#pragma unroll
        for (int chunk = 0; chunk < 2; chunk++) {
            const int   nTile  = (chunk == 0) ? tile : tile + GEMM_GRID;
            const int   nChunk = chunk ^ 1;
            const bool  have   = (nTile < NTILES);
            const uint32_t abuf_next = cur ? a_b0 : a_b1;
            if (have) { STAGE_A2(abuf_next, nTile * 128, nChunk); cp_commit(); }
            if (have) cp_wait<1>(); else cp_wait<0>();
            __syncthreads();

            const uint32_t abuf = cur ? a_b1 : a_b0;
#pragma unroll 1
            for (int ks = 0; ks < 4; ks++) {
                uint32_t a[4];
                ldsm_x4(a[0], a[1], a[2], a[3], abuf + a_off + (uint32_t)(ks * 32));
                const uint32_t koff = (uint32_t)((chunk * 4 + ks) * 32);
#pragma unroll
                for (int nt2 = 0; nt2 < NT2; nt2++) {
                    uint32_t b0, b1, b2, b3;
                    ldsm_x4(b0, b1, b2, b3, b_off + (uint32_t)(nt2 * 16 * STRB) + koff);
                    mma_f16(acc[nt2 * 2],     a, b0, b1);
                    mma_f16(acc[nt2 * 2 + 1], a, b2, b3);
                }
            }
            __syncthreads();
            cur ^= 1;
        }
        const int gr0 = tile * 128 + r0 + g;
        float d0 = (gr0 < M)     ? deg_rsqrt(deg[gr0])     : 0.0f;
        float d1 = (gr0 + 8 < M) ? deg_rsqrt(deg[gr0 + 8]) : 0.0f;
#pragma unroll
        for (int nt = 0; nt < 2 * NT2; nt++) {
            int cc = nt * 8 + 2 * t;
            if (gr0 < M)
                Ch[(size_t)gr0 * 32 + cc / 2] =
                    __floats2half2_rn(d0 * acc[nt][0], d0 * acc[nt][1]);
            if (gr0 + 8 < M)
                Ch[(size_t)(gr0 + 8) * 32 + cc / 2] =
                    __floats2half2_rn(d1 * acc[nt][2], d1 * acc[nt][3]);
#pragma unroll
            for (int j = 0; j < 4; j++) acc[nt][j] = 0.0f;
        }
    }
#undef STAGE_A2
}

// ---------------- CSR gather: pure row-sum (rows pre-scaled by dis[s]) ----------------
__global__ void gather128_kernel(const int* __restrict__ rowptr,
                                 const int* __restrict__ csrc,
                                 const int* __restrict__ deg,
                                 const __half2* __restrict__ h,
                                 const float* __restrict__ bias,
                                 __half2* __restrict__ outh) {
    const int lane = threadIdx.x & 31;
    const int node = blockIdx.x * (blockDim.x >> 5) + (threadIdx.x >> 5);
    if (node >= N_NODES) return;

    const int start = rowptr[node];
    const int end   = rowptr[node + 1];
    float4 acc = make_float4(0.f, 0.f, 0.f, 0.f);

    int j = start;
    for (; j + 2 <= end; j += 2) {
        int s0 = csrc[j], s1 = csrc[j + 1];
        uint2 r0 = ((const uint2*)(h + (size_t)s0 * 64))[lane];
        uint2 r1 = ((const uint2*)(h + (size_t)s1 * 64))[lane];
        float2 a0 = __half22float2(*(const __half2*)&r0.x);
        float2 b0 = __half22float2(*(const __half2*)&r0.y);
        float2 a1 = __half22float2(*(const __half2*)&r1.x);
        float2 b1 = __half22float2(*(const __half2*)&r1.y);
        acc.x += a0.x + a1.x;
        acc.y += a0.y + a1.y;
        acc.z += b0.x + b1.x;
        acc.w += b0.y + b1.y;
    }
    if (j < end) {
        int s0 = csrc[j];
        uint2 r0 = ((const uint2*)(h + (size_t)s0 * 64))[lane];
        float2 a0 = __half22float2(*(const __half2*)&r0.x);
        float2 b0 = __half22float2(*(const __half2*)&r0.y);
        acc.x += a0.x;
        acc.y += a0.y;
        acc.z += b0.x;
        acc.w += b0.y;
    }

    float dn = deg_rsqrt(deg[node]);
    float4 bv = ((const float4*)bias)[lane];
    float rx = fmaxf(dn * acc.x + bv.x, 0.f);
    float ry = fmaxf(dn * acc.y + bv.y, 0.f);
    float rz = fmaxf(dn * acc.z + bv.z, 0.f);
    float rw = fmaxf(dn * acc.w + bv.w, 0.f);
    __half2 o0 = __floats2half2_rn(rx, ry);
    __half2 o1 = __floats2half2_rn(rz, rw);
    uint2 o;
    o.x = *(uint32_t*)&o0;
    o.y = *(uint32_t*)&o1;
    ((uint2*)(outh + (size_t)node * 64))[lane] = o;
}

__global__ void gather64_kernel(const int* __restrict__ rowptr,
                                const int* __restrict__ csrc,
                                const int* __restrict__ deg,
                                const __half2* __restrict__ h,
                                const float* __restrict__ bias,
                                float* __restrict__ out) {
    const int lane = threadIdx.x & 31;
    const int node = blockIdx.x * (blockDim.x >> 5) + (threadIdx.x >> 5);
    if (node >= N_NODES) return;

    const int start = rowptr[node];
    const int end   = rowptr[node + 1];
    float2 acc = make_float2(0.f, 0.f);

    int j = start;
    for (; j + 2 <= end; j += 2) {
        int s0 = csrc[j], s1 = csrc[j + 1];
        float2 p0 = __half22float2(h[(size_t)s0 * 32 + lane]);
        float2 p1 = __half22float2(h[(size_t)s1 * 32 + lane]);
        acc.x += p0.x + p1.x;
        acc.y += p0.y + p1.y;
    }
    if (j < end) {
        int s0 = csrc[j];
        float2 p0 = __half22float2(h[(size_t)s0 * 32 + lane]);
        acc.x += p0.x;
        acc.y += p0.y;
    }

    float dn = deg_rsqrt(deg[node]);
    float2 bv = ((const float2*)bias)[lane];
    float2 r;
    r.x = dn * acc.x + bv.x;
    r.y = dn * acc.y + bv.y;
    ((float2*)(out + (size_t)node * 64))[lane] = r;
}

// ---------------- launch ----------------------------------------------------------
extern "C" void kernel_launch(void* const* d_in, const int* in_sizes, int n_in,
                              void* d_out, int out_size) {
    const float* x   = (const float*)d_in[0];
    const int*   ei  = (const int*)d_in[1];   // [2, E] int32
    const float* W1  = (const float*)d_in[2];
    const float* b1  = (const float*)d_in[3];
    const float* W2  = (const float*)d_in[4];
    const float* b2  = (const float*)d_in[5];
    float*       out = (float*)d_out;

    const int* src = ei;
    const int* dst = ei + N_EDGES;

    int*      deg;      cudaGetSymbolAddress((void**)&deg,      g_deg);
    int*      rowptr;   cudaGetSymbolAddress((void**)&rowptr,   g_rowptr);
    int*      blocksum; cudaGetSymbolAddress((void**)&blocksum, g_blocksum);
    int*      epos;     cudaGetSymbolAddress((void**)&epos,     g_epos);
    int*      csrc;     cudaGetSymbolAddress((void**)&csrc,     g_csrc);
    __half2*  h1h;      cudaGetSymbolAddress((void**)&h1h,      g_h1h);
    __half2*  agg1h;    cudaGetSymbolAddress((void**)&agg1h,    g_agg1h);
    __half2*  h2h;      cudaGetSymbolAddress((void**)&h2h,      g_h2h);
    __half2*  w1t;      cudaGetSymbolAddress((void**)&w1t,      g_w1t);
    __half2*  w2t;      cudaGetSymbolAddress((void**)&w2t,      g_w2t);

    constexpr int SMEM_G1 = 128 * 272 + 4 * 128 * 144;   // 34816 + 73728 = 108544
    constexpr int SMEM_G2 = 64 * 272 + 2 * 128 * 144;    //  54272
    cudaFuncSetAttribute(gemm1_kernel, cudaFuncAttributeMaxDynamicSharedMemorySize, SMEM_G1);
    cudaFuncSetAttribute(gemm2_kernel, cudaFuncAttributeMaxDynamicSharedMemorySize, SMEM_G2);

    // ncu profiles the 4th kernel launch -> gemm1 there.
    prep_kernel<<<(N_NODES + 255) / 256, 256>>>(W1, W2, w1t, w2t, deg);             // 1
    deg_kernel<<<(N_EDGES / 4 + 255) / 256, 256>>>((const int4*)dst, deg, (int4*)epos); // 2
    scan_pass1<<<SCAN_BLOCKS, SCAN_TPB>>>(deg, blocksum);                           // 3
    gemm1_kernel<<<GEMM_GRID, 256, SMEM_G1>>>(x, w1t, deg, h1h, N_NODES);           // 4
    scan_pass2<<<1, 256>>>(blocksum, rowptr);                                       // 5
    scan_pass3<<<SCAN_BLOCKS, SCAN_TPB>>>(deg, blocksum, rowptr);                   // 6
    fill_kernel<<<(N_EDGES + 255) / 256, 256>>>(src, dst, rowptr, epos, csrc);      // 7
    gather128_kernel<<<(N_NODES + 7) / 8, 256>>>(rowptr, csrc, deg, h1h, b1, agg1h); // 8
    gemm2_kernel<<<GEMM_GRID, 256, SMEM_G2>>>(agg1h, w2t, deg, h2h, N_NODES);       // 9
    gather64_kernel<<<(N_NODES + 7) / 8, 256>>>(rowptr, csrc, deg, h2h, b2, out);   // 10
}